// round 1
// baseline (speedup 1.0000x reference)
#include <cuda_runtime.h>
#include <math.h>
#include <stdint.h>

#define NN 32
#define VV 25
#define TT 64
#define CC 256
#define SS 3
#define STT 2
#define CII 64
#define KK7 7
#define RTOT (NN*VV*TT)   /* 51200 */

// ------------------------- scratch (device globals) -------------------------
__device__ float g_bufA[(size_t)RTOT * 1024];   // y_s (768 wide), z (1024 wide)
__device__ float g_bufB[(size_t)RTOT * 512];    // qk (384 wide), qkt (512 wide)
__device__ float g_h   [(size_t)RTOT * 256];    // GEMM outputs pre-LN / conv out
__device__ float g_y1  [(size_t)RTOT * 256];    // y1 / z1
__device__ float g_y2  [(size_t)RTOT * 256];    // y2 transposed (N,T,V,C)
__device__ float g_z2  [(size_t)RTOT * 256];    // z2 (N,T,V,C)
__device__ float g_atts[NN*VV*VV*SS];
__device__ float g_attf[NN*TT*TT*STT];
__device__ float g_attb[NN*TT*TT*STT];
__device__ float g_wt  [KK7*256*256];           // conv weight transposed (1792,256)

__device__ __forceinline__ float gelu_f(float x) {
    return 0.5f * x * (1.0f + erff(x * 0.7071067811865475f));
}

// ------------------------- generic SGEMM (64x64x16) -------------------------
// C[M,N] = A[M,K] @ B[K,N] + bias[N].  M%64==0, N%64==0, K%16==0.
__global__ void sgemm_bias(const float* __restrict__ A, const float* __restrict__ B,
                           const float* __restrict__ bias, float* __restrict__ C,
                           int M, int N, int K) {
    __shared__ float As[16][64];
    __shared__ float Bs[16][64];
    const int tid = threadIdx.x;
    const int tx = tid & 15, ty = tid >> 4;
    const int bm = blockIdx.y << 6, bn = blockIdx.x << 6;
    const int arow = tid >> 2, acol = (tid & 3) << 2;
    const int brow = tid >> 4, bcol = (tid & 15) << 2;
    float acc[4][4] = {};
    for (int k0 = 0; k0 < K; k0 += 16) {
        float4 av = *(const float4*)(A + (size_t)(bm + arow) * K + k0 + acol);
        As[acol + 0][arow] = av.x; As[acol + 1][arow] = av.y;
        As[acol + 2][arow] = av.z; As[acol + 3][arow] = av.w;
        *(float4*)(&Bs[brow][bcol]) =
            *(const float4*)(B + (size_t)(k0 + brow) * N + bn + bcol);
        __syncthreads();
#pragma unroll
        for (int kk = 0; kk < 16; kk++) {
            float a[4], b[4];
            *(float4*)a = *(const float4*)(&As[kk][ty << 2]);
            *(float4*)b = *(const float4*)(&Bs[kk][tx << 2]);
#pragma unroll
            for (int i = 0; i < 4; i++)
#pragma unroll
                for (int j = 0; j < 4; j++) acc[i][j] = fmaf(a[i], b[j], acc[i][j]);
        }
        __syncthreads();
    }
    float4 bb = *(const float4*)(bias + bn + (tx << 2));
#pragma unroll
    for (int i = 0; i < 4; i++) {
        float4 o;
        o.x = acc[i][0] + bb.x; o.y = acc[i][1] + bb.y;
        o.z = acc[i][2] + bb.z; o.w = acc[i][3] + bb.w;
        *(float4*)(C + (size_t)(bm + (ty << 2) + i) * N + bn + (tx << 2)) = o;
    }
}

// ------------- conv as implicit-im2col GEMM: M=51200, N=256, K=1792 ---------
__global__ void conv_gemm(const float* __restrict__ Z, const float* __restrict__ B,
                          const float* __restrict__ bias, float* __restrict__ C) {
    const int N = 256, K = KK7 * 256;
    __shared__ float As[16][64];
    __shared__ float Bs[16][64];
    const int tid = threadIdx.x;
    const int tx = tid & 15, ty = tid >> 4;
    const int bm = blockIdx.y << 6, bn = blockIdx.x << 6;
    const int arow = tid >> 2, acol = (tid & 3) << 2;
    const int brow = tid >> 4, bcol = (tid & 15) << 2;
    const int row = bm + arow;
    const int t = (row / VV) % TT;
    float acc[4][4] = {};
    for (int k0 = 0; k0 < K; k0 += 16) {
        int kg = k0 + acol;
        int kw = kg >> 8;          // conv tap 0..6
        int ii = kg & 255;         // input channel
        int dt = kw - 3;
        int tt = t + dt;
        float4 av = make_float4(0.f, 0.f, 0.f, 0.f);
        if (tt >= 0 && tt < TT)
            av = *(const float4*)(Z + ((size_t)row + (size_t)dt * VV) * 256 + ii);
        As[acol + 0][arow] = av.x; As[acol + 1][arow] = av.y;
        As[acol + 2][arow] = av.z; As[acol + 3][arow] = av.w;
        *(float4*)(&Bs[brow][bcol]) =
            *(const float4*)(B + (size_t)(k0 + brow) * N + bn + bcol);
        __syncthreads();
#pragma unroll
        for (int kk = 0; kk < 16; kk++) {
            float a[4], b[4];
            *(float4*)a = *(const float4*)(&As[kk][ty << 2]);
            *(float4*)b = *(const float4*)(&Bs[kk][tx << 2]);
#pragma unroll
            for (int i = 0; i < 4; i++)
#pragma unroll
                for (int j = 0; j < 4; j++) acc[i][j] = fmaf(a[i], b[j], acc[i][j]);
        }
        __syncthreads();
    }
    float4 bb = *(const float4*)(bias + bn + (tx << 2));
#pragma unroll
    for (int i = 0; i < 4; i++) {
        float4 o;
        o.x = acc[i][0] + bb.x; o.y = acc[i][1] + bb.y;
        o.z = acc[i][2] + bb.z; o.w = acc[i][3] + bb.w;
        *(float4*)(C + (size_t)(bm + (ty << 2) + i) * N + bn + (tx << 2)) = o;
    }
}

// ------------------------- spatial attention (25x25) ------------------------
// att[n,u,v,s] = tanh( sum_{t,ci} q[n,u,t,ci,s]*k[n,v,t,ci,s] / 4096 ) * alpha[s] + att0[u,v,s]
__global__ void att_s_kernel(const float* __restrict__ qk, const float* __restrict__ alphas,
                             const float* __restrict__ att0, float* __restrict__ att) {
    int b = blockIdx.x;
    int v = b % VV, u = (b / VV) % VV, n = b / (VV * VV);
    int tid = threadIdx.x;           // 192 threads: (ci, s)
    int s = tid % 3, ci = tid / 3;
    const float* qrow = qk + (size_t)(n * VV + u) * TT * 384;
    const float* krow = qk + (size_t)(n * VV + v) * TT * 384;
    float acc = 0.f;
    for (int t = 0; t < TT; t++)
        acc += qrow[t * 384 + ci * 6 + s] * krow[t * 384 + ci * 6 + 3 + s];
    __shared__ float sd[192];
    sd[tid] = acc;
    __syncthreads();
    for (int st = 32; st > 0; st >>= 1) {
        if (ci < st) sd[tid] += sd[(ci + st) * 3 + s];
        __syncthreads();
    }
    if (ci == 0)
        att[((size_t)(n * VV + u) * VV + v) * 3 + s] =
            tanhf(sd[s] * (1.f / 4096.f)) * alphas[s] + att0[((size_t)u * VV + v) * 3 + s];
}

// y_s[n,v,t, c*3+s] = sum_u x[n,u,t,c] * att[n,u,v,s]
__global__ void y_s_kernel(const float* __restrict__ x, const float* __restrict__ att,
                           float* __restrict__ y) {
    int b = blockIdx.x;              // (n*V+v)*T + t
    int t = b % TT, v = (b / TT) % VV, n = b / (TT * VV);
    int c = threadIdx.x;             // 256
    __shared__ float a_s[VV * 3];
    if (c < VV * 3)
        a_s[c] = att[((size_t)(n * VV + c / 3) * VV + v) * 3 + (c % 3)];
    __syncthreads();
    float a0 = 0.f, a1 = 0.f, a2 = 0.f;
#pragma unroll
    for (int u = 0; u < VV; u++) {
        float xv = x[((size_t)(n * VV + u) * TT + t) * 256 + c];
        a0 = fmaf(xv, a_s[u * 3 + 0], a0);
        a1 = fmaf(xv, a_s[u * 3 + 1], a1);
        a2 = fmaf(xv, a_s[u * 3 + 2], a2);
    }
    float* yp = y + (size_t)b * 768 + c * 3;
    yp[0] = a0; yp[1] = a1; yp[2] = a2;
}

// --------------------- LN over group + residual + gelu ----------------------
// h,res contiguous per group of G elems. mode 0: out contiguous.
// mode 1: group = (n,v), local i = t*256+c, out[((n*T+t)*V+v)*256+c].
__global__ void ln_kernel(const float* __restrict__ h, const float* __restrict__ res,
                          const float* __restrict__ g, const float* __restrict__ b,
                          float* __restrict__ out, int G, int mode) {
    int grp = blockIdx.x;
    const float* hp = h + (size_t)grp * G;
    const float* rp = res + (size_t)grp * G;
    float s = 0.f, sq = 0.f;
    for (int i = threadIdx.x; i < G; i += blockDim.x) {
        float v = hp[i]; s += v; sq = fmaf(v, v, sq);
    }
    for (int o = 16; o; o >>= 1) {
        s += __shfl_down_sync(0xffffffffu, s, o);
        sq += __shfl_down_sync(0xffffffffu, sq, o);
    }
    __shared__ float ss[8], sqs[8];
    __shared__ float mean_s, inv_s;
    int w = threadIdx.x >> 5;
    if ((threadIdx.x & 31) == 0) { ss[w] = s; sqs[w] = sq; }
    __syncthreads();
    if (threadIdx.x == 0) {
        float S = 0.f, Q = 0.f;
        for (int i = 0; i < 8; i++) { S += ss[i]; Q += sqs[i]; }
        float mean = S / G;
        float var = Q / G - mean * mean;
        mean_s = mean; inv_s = rsqrtf(var + 1e-5f);
    }
    __syncthreads();
    float mean = mean_s, inv = inv_s;
    if (mode == 0) {
        float* op = out + (size_t)grp * G;
        for (int i = threadIdx.x; i < G; i += blockDim.x)
            op[i] = gelu_f(rp[i] + fmaf((hp[i] - mean) * inv, g[i], b[i]));
    } else {
        int n = grp / VV, v = grp % VV;
        for (int i = threadIdx.x; i < G; i += blockDim.x) {
            int t = i >> 8, c = i & 255;
            out[((size_t)(n * TT + t) * VV + v) * 256 + c] =
                gelu_f(rp[i] + fmaf((hp[i] - mean) * inv, g[i], b[i]));
        }
    }
}

// ------------------------ temporal attention (64x64) ------------------------
__global__ void att_t_kernel(const float* __restrict__ qkt, const float* __restrict__ alf,
                             const float* __restrict__ alb, float* __restrict__ attf,
                             float* __restrict__ attb) {
    int n = blockIdx.x / TT, t = blockIdx.x % TT;
    __shared__ float qs[4][1600];    // qf0,qf1,qb0,qb1
    __shared__ float red[8][4];
    for (int e = threadIdx.x; e < 1600; e += 256) {
        int v = e >> 6, ci = e & 63;
        const float* p = qkt + ((size_t)(n * TT + t) * VV + v) * 512 + ci * 8;
        qs[0][e] = p[0]; qs[1][e] = p[1]; qs[2][e] = p[2]; qs[3][e] = p[3];
    }
    __syncthreads();
    for (int q = 0; q < TT; q++) {
        float a0 = 0.f, a1 = 0.f, a2 = 0.f, a3 = 0.f;
        for (int e = threadIdx.x; e < 1600; e += 256) {
            int v = e >> 6, ci = e & 63;
            const float* p = qkt + ((size_t)(n * TT + q) * VV + v) * 512 + ci * 8 + 4;
            a0 = fmaf(qs[0][e], p[0], a0);
            a1 = fmaf(qs[1][e], p[1], a1);
            a2 = fmaf(qs[2][e], p[2], a2);
            a3 = fmaf(qs[3][e], p[3], a3);
        }
        for (int o = 16; o; o >>= 1) {
            a0 += __shfl_down_sync(0xffffffffu, a0, o);
            a1 += __shfl_down_sync(0xffffffffu, a1, o);
            a2 += __shfl_down_sync(0xffffffffu, a2, o);
            a3 += __shfl_down_sync(0xffffffffu, a3, o);
        }
        int w = threadIdx.x >> 5;
        if ((threadIdx.x & 31) == 0) {
            red[w][0] = a0; red[w][1] = a1; red[w][2] = a2; red[w][3] = a3;
        }
        __syncthreads();
        if (threadIdx.x < 4) {
            float sum = 0.f;
            for (int ww = 0; ww < 8; ww++) sum += red[ww][threadIdx.x];
            float val = tanhf(sum * (1.f / 1600.f));
            int s = threadIdx.x & 1;
            size_t idx = ((size_t)(n * TT + t) * TT + q) * 2 + s;
            if (threadIdx.x < 2)
                attf[idx] = val * alf[s] * ((q <= t) ? 1.f : 0.f);
            else
                attb[idx] = val * alb[s] * ((q >= t) ? 1.f : 0.f);
        }
        __syncthreads();
    }
}

// z[n,q,v, c*2+s] (f) and z[..., 512 + c*2+s] (b)
__global__ void z_kernel(const float* __restrict__ y2t, const float* __restrict__ attf,
                         const float* __restrict__ attb, float* __restrict__ z) {
    int b = blockIdx.x;              // (n*T+q)*V + v
    int v = b % VV, q = (b / VV) % TT, n = b / (VV * TT);
    int c = threadIdx.x;
    __shared__ float af[TT][2], ab[TT][2];
    if (c < 128) {
        int t = c >> 1, s = c & 1;
        af[t][s] = attf[((size_t)(n * TT + t) * TT + q) * 2 + s];
    } else {
        int r = c - 128; int t = r >> 1, s = r & 1;
        ab[t][s] = attb[((size_t)(n * TT + t) * TT + q) * 2 + s];
    }
    __syncthreads();
    float f0 = 0.f, f1 = 0.f, b0 = 0.f, b1 = 0.f;
#pragma unroll 4
    for (int t = 0; t < TT; t++) {
        float yv = y2t[((size_t)(n * TT + t) * VV + v) * 256 + c];
        f0 = fmaf(yv, af[t][0], f0); f1 = fmaf(yv, af[t][1], f1);
        b0 = fmaf(yv, ab[t][0], b0); b1 = fmaf(yv, ab[t][1], b1);
    }
    float* zp = z + (size_t)b * 1024;
    zp[c * 2 + 0] = f0; zp[c * 2 + 1] = f1;
    zp[512 + c * 2 + 0] = b0; zp[512 + c * 2 + 1] = b1;
}

// conv weight transpose: wt[(kk*256+i)*256 + o] = w[o*1792 + i*7 + kk]
__global__ void convw_t_kernel(const float* __restrict__ w, float* __restrict__ wt) {
    int idx = blockIdx.x * 256 + threadIdx.x;
    if (idx < 256 * 256 * 7) {
        int kk = idx % 7, i = (idx / 7) % 256, o = idx / (7 * 256);
        wt[((size_t)kk * 256 + i) * 256 + o] = w[idx];
    }
}

// final: out[n,v,t,o] = gelu(z2[n,t,v,o] + BN(conv[n,t,v,o]))
__global__ void final_kernel(const float* __restrict__ z2, const float* __restrict__ cv,
                             const float* __restrict__ bn_g, const float* __restrict__ bn_b,
                             const float* __restrict__ bn_m, const float* __restrict__ bn_v,
                             float* __restrict__ out) {
    size_t i = (size_t)blockIdx.x * 256 + threadIdx.x;
    int o = (int)(i & 255);
    size_t r = i >> 8;
    int v = (int)(r % VV);
    size_t r2 = r / VV;
    int t = (int)(r2 % TT);
    int n = (int)(r2 / TT);
    float c1 = fmaf((cv[i] - bn_m[o]) * rsqrtf(bn_v[o] + 1e-5f), bn_g[o], bn_b[o]);
    out[((size_t)(n * VV + v) * TT + t) * 256 + o] = gelu_f(z2[i] + c1);
}

// ------------------------------- launcher -----------------------------------
extern "C" void kernel_launch(void* const* d_in, const int* in_sizes, int n_in,
                              void* d_out, int out_size) {
    const float* x       = (const float*)d_in[0];
    const float* Wqk_s   = (const float*)d_in[1];
    const float* bqk_s   = (const float*)d_in[2];
    const float* alphas  = (const float*)d_in[3];
    const float* att0s   = (const float*)d_in[4];
    const float* Wo_s    = (const float*)d_in[5];
    const float* bo_s    = (const float*)d_in[6];
    const float* g_os    = (const float*)d_in[7];
    const float* b_os    = (const float*)d_in[8];
    const float* Wff_s   = (const float*)d_in[9];
    const float* bff_s   = (const float*)d_in[10];
    const float* g_ffs   = (const float*)d_in[11];
    const float* b_ffs   = (const float*)d_in[12];
    const float* Wqk_t   = (const float*)d_in[13];
    const float* bqk_t   = (const float*)d_in[14];
    const float* alphat_f= (const float*)d_in[15];
    const float* alphat_b= (const float*)d_in[16];
    const float* Wo_t    = (const float*)d_in[17];
    const float* bo_t    = (const float*)d_in[18];
    const float* g_ot    = (const float*)d_in[19];
    const float* b_ot    = (const float*)d_in[20];
    const float* Wff_t   = (const float*)d_in[21];
    const float* bff_t   = (const float*)d_in[22];
    const float* g_fft   = (const float*)d_in[23];
    const float* b_fft   = (const float*)d_in[24];
    const float* conv_w  = (const float*)d_in[25];
    const float* conv_b  = (const float*)d_in[26];
    const float* bn_g    = (const float*)d_in[27];
    const float* bn_b    = (const float*)d_in[28];
    const float* bn_m    = (const float*)d_in[29];
    const float* bn_v    = (const float*)d_in[30];
    float* out = (float*)d_out;

    void *pA, *pB, *pH, *pY1, *pY2, *pZ2, *pAS, *pAF, *pAB, *pWT;
    cudaGetSymbolAddress(&pA,  g_bufA);
    cudaGetSymbolAddress(&pB,  g_bufB);
    cudaGetSymbolAddress(&pH,  g_h);
    cudaGetSymbolAddress(&pY1, g_y1);
    cudaGetSymbolAddress(&pY2, g_y2);
    cudaGetSymbolAddress(&pZ2, g_z2);
    cudaGetSymbolAddress(&pAS, g_atts);
    cudaGetSymbolAddress(&pAF, g_attf);
    cudaGetSymbolAddress(&pAB, g_attb);
    cudaGetSymbolAddress(&pWT, g_wt);
    float* bufA = (float*)pA;  float* bufB = (float*)pB;
    float* h    = (float*)pH;  float* y1   = (float*)pY1;
    float* y2   = (float*)pY2; float* z2   = (float*)pZ2;
    float* atts = (float*)pAS; float* attf = (float*)pAF;
    float* attb = (float*)pAB; float* wt   = (float*)pWT;

    dim3 blk(256);
    const int MB = RTOT / 64;   // 800

    // Stage 1: spatial
    sgemm_bias<<<dim3(384/64, MB), blk>>>(x, Wqk_s, bqk_s, bufB, RTOT, 384, 256);
    att_s_kernel<<<NN*VV*VV, 192>>>(bufB, alphas, att0s, atts);
    y_s_kernel<<<RTOT, 256>>>(x, atts, bufA);
    sgemm_bias<<<dim3(4, MB), blk>>>(bufA, Wo_s, bo_s, h, RTOT, 256, 768);
    ln_kernel<<<NN*VV, 256>>>(h, x, g_os, b_os, y1, TT*CC, 0);
    sgemm_bias<<<dim3(4, MB), blk>>>(y1, Wff_s, bff_s, h, RTOT, 256, 256);
    ln_kernel<<<NN*VV, 256>>>(h, x, g_ffs, b_ffs, y2, TT*CC, 1);   // transposed write

    // Stage 2: temporal
    sgemm_bias<<<dim3(8, MB), blk>>>(y2, Wqk_t, bqk_t, bufB, RTOT, 512, 256);
    att_t_kernel<<<NN*TT, 256>>>(bufB, alphat_f, alphat_b, attf, attb);
    z_kernel<<<RTOT, 256>>>(y2, attf, attb, bufA);
    sgemm_bias<<<dim3(4, MB), blk>>>(bufA, Wo_t, bo_t, h, RTOT, 256, 1024);
    ln_kernel<<<NN*TT, 256>>>(h, y2, g_ot, b_ot, y1, VV*CC, 0);
    sgemm_bias<<<dim3(4, MB), blk>>>(y1, Wff_t, bff_t, h, RTOT, 256, 256);
    ln_kernel<<<NN*TT, 256>>>(h, y2, g_fft, b_fft, z2, VV*CC, 0);

    // Stage 3: conv + BN + gelu + transpose
    convw_t_kernel<<<(256*256*7 + 255)/256, 256>>>(conv_w, wt);
    conv_gemm<<<dim3(4, MB), blk>>>(z2, wt, conv_b, h);
    final_kernel<<<RTOT, 256>>>(z2, h, bn_g, bn_b, bn_m, bn_v, out);
}

// round 2
// speedup vs baseline: 1.0037x; 1.0037x over previous
#include <cuda_runtime.h>
#include <math.h>
#include <stdint.h>

#define NN 32
#define VV 25
#define TT 64
#define CC 256
#define SS 3
#define STT 2
#define CII 64
#define KK7 7
#define RTOT (NN*VV*TT)   /* 51200 */

// ------------------------- scratch (device globals) -------------------------
__device__ float g_bufA[(size_t)RTOT * 1024];   // y_s (768 wide), z (1024 wide)
__device__ float g_bufB[(size_t)RTOT * 512];    // qk (384 wide), qkt (512 wide)
__device__ float g_h   [(size_t)RTOT * 256];    // GEMM outputs pre-LN / conv out
__device__ float g_y1  [(size_t)RTOT * 256];    // y1 / z1
__device__ float g_y2  [(size_t)RTOT * 256];    // y2 transposed (N,T,V,C)
__device__ float g_z2  [(size_t)RTOT * 256];    // z2 (N,T,V,C)
__device__ float g_atts[NN*VV*VV*SS];
__device__ float g_attf[NN*TT*TT*STT];
__device__ float g_attb[NN*TT*TT*STT];
__device__ float g_wt  [KK7*256*256];           // conv weight transposed (1792,256)

__device__ __forceinline__ float gelu_f(float x) {
    return 0.5f * x * (1.0f + erff(x * 0.7071067811865475f));
}

// ------------------------- generic SGEMM (64x64x16) -------------------------
// C[M,N] = A[M,K] @ B[K,N] + bias[N].  M%64==0, N%64==0, K%16==0.
__global__ void sgemm_bias(const float* __restrict__ A, const float* __restrict__ B,
                           const float* __restrict__ bias, float* __restrict__ C,
                           int M, int N, int K) {
    __shared__ float As[16][64];
    __shared__ float Bs[16][64];
    const int tid = threadIdx.x;
    const int tx = tid & 15, ty = tid >> 4;
    const int bm = blockIdx.y << 6, bn = blockIdx.x << 6;
    const int arow = tid >> 2, acol = (tid & 3) << 2;
    const int brow = tid >> 4, bcol = (tid & 15) << 2;
    float acc[4][4] = {};
    for (int k0 = 0; k0 < K; k0 += 16) {
        float4 av = *(const float4*)(A + (size_t)(bm + arow) * K + k0 + acol);
        As[acol + 0][arow] = av.x; As[acol + 1][arow] = av.y;
        As[acol + 2][arow] = av.z; As[acol + 3][arow] = av.w;
        *(float4*)(&Bs[brow][bcol]) =
            *(const float4*)(B + (size_t)(k0 + brow) * N + bn + bcol);
        __syncthreads();
#pragma unroll
        for (int kk = 0; kk < 16; kk++) {
            float a[4], b[4];
            *(float4*)a = *(const float4*)(&As[kk][ty << 2]);
            *(float4*)b = *(const float4*)(&Bs[kk][tx << 2]);
#pragma unroll
            for (int i = 0; i < 4; i++)
#pragma unroll
                for (int j = 0; j < 4; j++) acc[i][j] = fmaf(a[i], b[j], acc[i][j]);
        }
        __syncthreads();
    }
    float4 bb = *(const float4*)(bias + bn + (tx << 2));
#pragma unroll
    for (int i = 0; i < 4; i++) {
        float4 o;
        o.x = acc[i][0] + bb.x; o.y = acc[i][1] + bb.y;
        o.z = acc[i][2] + bb.z; o.w = acc[i][3] + bb.w;
        *(float4*)(C + (size_t)(bm + (ty << 2) + i) * N + bn + (tx << 2)) = o;
    }
}

// ------------- conv as implicit-im2col GEMM: M=51200, N=256, K=1792 ---------
__global__ void conv_gemm(const float* __restrict__ Z, const float* __restrict__ B,
                          const float* __restrict__ bias, float* __restrict__ C) {
    const int N = 256, K = KK7 * 256;
    __shared__ float As[16][64];
    __shared__ float Bs[16][64];
    const int tid = threadIdx.x;
    const int tx = tid & 15, ty = tid >> 4;
    const int bm = blockIdx.y << 6, bn = blockIdx.x << 6;
    const int arow = tid >> 2, acol = (tid & 3) << 2;
    const int brow = tid >> 4, bcol = (tid & 15) << 2;
    const int row = bm + arow;
    const int t = (row / VV) % TT;
    float acc[4][4] = {};
    for (int k0 = 0; k0 < K; k0 += 16) {
        int kg = k0 + acol;
        int kw = kg >> 8;          // conv tap 0..6
        int ii = kg & 255;         // input channel
        int dt = kw - 3;
        int tt = t + dt;
        float4 av = make_float4(0.f, 0.f, 0.f, 0.f);
        if (tt >= 0 && tt < TT)
            av = *(const float4*)(Z + ((size_t)row + (size_t)dt * VV) * 256 + ii);
        As[acol + 0][arow] = av.x; As[acol + 1][arow] = av.y;
        As[acol + 2][arow] = av.z; As[acol + 3][arow] = av.w;
        *(float4*)(&Bs[brow][bcol]) =
            *(const float4*)(B + (size_t)(k0 + brow) * N + bn + bcol);
        __syncthreads();
#pragma unroll
        for (int kk = 0; kk < 16; kk++) {
            float a[4], b[4];
            *(float4*)a = *(const float4*)(&As[kk][ty << 2]);
            *(float4*)b = *(const float4*)(&Bs[kk][tx << 2]);
#pragma unroll
            for (int i = 0; i < 4; i++)
#pragma unroll
                for (int j = 0; j < 4; j++) acc[i][j] = fmaf(a[i], b[j], acc[i][j]);
        }
        __syncthreads();
    }
    float4 bb = *(const float4*)(bias + bn + (tx << 2));
#pragma unroll
    for (int i = 0; i < 4; i++) {
        float4 o;
        o.x = acc[i][0] + bb.x; o.y = acc[i][1] + bb.y;
        o.z = acc[i][2] + bb.z; o.w = acc[i][3] + bb.w;
        *(float4*)(C + (size_t)(bm + (ty << 2) + i) * N + bn + (tx << 2)) = o;
    }
}

// ------------------------- spatial attention (25x25) ------------------------
// att[n,u,v,s] = tanh( sum_{t,ci} q[n,u,t,ci,s]*k[n,v,t,ci,s] / 4096 ) * alpha[s] + att0[u,v,s]
__global__ void att_s_kernel(const float* __restrict__ qk, const float* __restrict__ alphas,
                             const float* __restrict__ att0, float* __restrict__ att) {
    int b = blockIdx.x;
    int v = b % VV, u = (b / VV) % VV, n = b / (VV * VV);
    int tid = threadIdx.x;           // 192 threads: (ci, s)
    int s = tid % 3, ci = tid / 3;
    const float* qrow = qk + (size_t)(n * VV + u) * TT * 384;
    const float* krow = qk + (size_t)(n * VV + v) * TT * 384;
    float acc = 0.f;
    for (int t = 0; t < TT; t++)
        acc += qrow[t * 384 + ci * 6 + s] * krow[t * 384 + ci * 6 + 3 + s];
    __shared__ float sd[192];
    sd[tid] = acc;
    __syncthreads();
    for (int st = 32; st > 0; st >>= 1) {
        if (ci < st) sd[tid] += sd[(ci + st) * 3 + s];
        __syncthreads();
    }
    if (ci == 0)
        att[((size_t)(n * VV + u) * VV + v) * 3 + s] =
            tanhf(sd[s] * (1.f / 4096.f)) * alphas[s] + att0[((size_t)u * VV + v) * 3 + s];
}

// y_s[n,v,t, c*3+s] = sum_u x[n,u,t,c] * att[n,u,v,s]
__global__ void y_s_kernel(const float* __restrict__ x, const float* __restrict__ att,
                           float* __restrict__ y) {
    int b = blockIdx.x;              // (n*V+v)*T + t
    int t = b % TT, v = (b / TT) % VV, n = b / (TT * VV);
    int c = threadIdx.x;             // 256
    __shared__ float a_s[VV * 3];
    if (c < VV * 3)
        a_s[c] = att[((size_t)(n * VV + c / 3) * VV + v) * 3 + (c % 3)];
    __syncthreads();
    float a0 = 0.f, a1 = 0.f, a2 = 0.f;
#pragma unroll
    for (int u = 0; u < VV; u++) {
        float xv = x[((size_t)(n * VV + u) * TT + t) * 256 + c];
        a0 = fmaf(xv, a_s[u * 3 + 0], a0);
        a1 = fmaf(xv, a_s[u * 3 + 1], a1);
        a2 = fmaf(xv, a_s[u * 3 + 2], a2);
    }
    float* yp = y + (size_t)b * 768 + c * 3;
    yp[0] = a0; yp[1] = a1; yp[2] = a2;
}

// --------------------- LN over group + residual + gelu ----------------------
// h,res contiguous per group of G elems. mode 0: out contiguous.
// mode 1: group = (n,v), local i = t*256+c, out[((n*T+t)*V+v)*256+c].
__global__ void ln_kernel(const float* __restrict__ h, const float* __restrict__ res,
                          const float* __restrict__ g, const float* __restrict__ b,
                          float* __restrict__ out, int G, int mode) {
    int grp = blockIdx.x;
    const float* hp = h + (size_t)grp * G;
    const float* rp = res + (size_t)grp * G;
    float s = 0.f, sq = 0.f;
    for (int i = threadIdx.x; i < G; i += blockDim.x) {
        float v = hp[i]; s += v; sq = fmaf(v, v, sq);
    }
    for (int o = 16; o; o >>= 1) {
        s += __shfl_down_sync(0xffffffffu, s, o);
        sq += __shfl_down_sync(0xffffffffu, sq, o);
    }
    __shared__ float ss[8], sqs[8];
    __shared__ float mean_s, inv_s;
    int w = threadIdx.x >> 5;
    if ((threadIdx.x & 31) == 0) { ss[w] = s; sqs[w] = sq; }
    __syncthreads();
    if (threadIdx.x == 0) {
        float S = 0.f, Q = 0.f;
        for (int i = 0; i < 8; i++) { S += ss[i]; Q += sqs[i]; }
        float mean = S / G;
        float var = Q / G - mean * mean;
        mean_s = mean; inv_s = rsqrtf(var + 1e-5f);
    }
    __syncthreads();
    float mean = mean_s, inv = inv_s;
    if (mode == 0) {
        float* op = out + (size_t)grp * G;
        for (int i = threadIdx.x; i < G; i += blockDim.x)
            op[i] = gelu_f(rp[i] + fmaf((hp[i] - mean) * inv, g[i], b[i]));
    } else {
        int n = grp / VV, v = grp % VV;
        for (int i = threadIdx.x; i < G; i += blockDim.x) {
            int t = i >> 8, c = i & 255;
            out[((size_t)(n * TT + t) * VV + v) * 256 + c] =
                gelu_f(rp[i] + fmaf((hp[i] - mean) * inv, g[i], b[i]));
        }
    }
}

// ------------------------ temporal attention (64x64) ------------------------
__global__ void att_t_kernel(const float* __restrict__ qkt, const float* __restrict__ alf,
                             const float* __restrict__ alb, float* __restrict__ attf,
                             float* __restrict__ attb) {
    int n = blockIdx.x / TT, t = blockIdx.x % TT;
    __shared__ float qs[4][1600];    // qf0,qf1,qb0,qb1
    __shared__ float red[8][4];
    for (int e = threadIdx.x; e < 1600; e += 256) {
        int v = e >> 6, ci = e & 63;
        const float* p = qkt + ((size_t)(n * TT + t) * VV + v) * 512 + ci * 8;
        qs[0][e] = p[0]; qs[1][e] = p[1]; qs[2][e] = p[2]; qs[3][e] = p[3];
    }
    __syncthreads();
    for (int q = 0; q < TT; q++) {
        float a0 = 0.f, a1 = 0.f, a2 = 0.f, a3 = 0.f;
        for (int e = threadIdx.x; e < 1600; e += 256) {
            int v = e >> 6, ci = e & 63;
            const float* p = qkt + ((size_t)(n * TT + q) * VV + v) * 512 + ci * 8 + 4;
            a0 = fmaf(qs[0][e], p[0], a0);
            a1 = fmaf(qs[1][e], p[1], a1);
            a2 = fmaf(qs[2][e], p[2], a2);
            a3 = fmaf(qs[3][e], p[3], a3);
        }
        for (int o = 16; o; o >>= 1) {
            a0 += __shfl_down_sync(0xffffffffu, a0, o);
            a1 += __shfl_down_sync(0xffffffffu, a1, o);
            a2 += __shfl_down_sync(0xffffffffu, a2, o);
            a3 += __shfl_down_sync(0xffffffffu, a3, o);
        }
        int w = threadIdx.x >> 5;
        if ((threadIdx.x & 31) == 0) {
            red[w][0] = a0; red[w][1] = a1; red[w][2] = a2; red[w][3] = a3;
        }
        __syncthreads();
        if (threadIdx.x < 4) {
            float sum = 0.f;
            for (int ww = 0; ww < 8; ww++) sum += red[ww][threadIdx.x];
            float val = tanhf(sum * (1.f / 1600.f));
            int s = threadIdx.x & 1;
            size_t idx = ((size_t)(n * TT + t) * TT + q) * 2 + s;
            if (threadIdx.x < 2)
                attf[idx] = val * alf[s] * ((q <= t) ? 1.f : 0.f);
            else
                attb[idx] = val * alb[s] * ((q >= t) ? 1.f : 0.f);
        }
        __syncthreads();
    }
}

// z[n,q,v, c*2+s] (f) and z[..., 512 + c*2+s] (b)
__global__ void z_kernel(const float* __restrict__ y2t, const float* __restrict__ attf,
                         const float* __restrict__ attb, float* __restrict__ z) {
    int b = blockIdx.x;              // (n*T+q)*V + v
    int v = b % VV, q = (b / VV) % TT, n = b / (VV * TT);
    int c = threadIdx.x;
    __shared__ float af[TT][2], ab[TT][2];
    if (c < 128) {
        int t = c >> 1, s = c & 1;
        af[t][s] = attf[((size_t)(n * TT + t) * TT + q) * 2 + s];
    } else {
        int r = c - 128; int t = r >> 1, s = r & 1;
        ab[t][s] = attb[((size_t)(n * TT + t) * TT + q) * 2 + s];
    }
    __syncthreads();
    float f0 = 0.f, f1 = 0.f, b0 = 0.f, b1 = 0.f;
#pragma unroll 4
    for (int t = 0; t < TT; t++) {
        float yv = y2t[((size_t)(n * TT + t) * VV + v) * 256 + c];
        f0 = fmaf(yv, af[t][0], f0); f1 = fmaf(yv, af[t][1], f1);
        b0 = fmaf(yv, ab[t][0], b0); b1 = fmaf(yv, ab[t][1], b1);
    }
    float* zp = z + (size_t)b * 1024;
    zp[c * 2 + 0] = f0; zp[c * 2 + 1] = f1;
    zp[512 + c * 2 + 0] = b0; zp[512 + c * 2 + 1] = b1;
}

// conv weight transpose: wt[(kk*256+i)*256 + o] = w[o*1792 + i*7 + kk]
__global__ void convw_t_kernel(const float* __restrict__ w, float* __restrict__ wt) {
    int idx = blockIdx.x * 256 + threadIdx.x;
    if (idx < 256 * 256 * 7) {
        int kk = idx % 7, i = (idx / 7) % 256, o = idx / (7 * 256);
        wt[((size_t)kk * 256 + i) * 256 + o] = w[idx];
    }
}

// final: out[n,v,t,o] = gelu(z2[n,t,v,o] + BN(conv[n,t,v,o]))
__global__ void final_kernel(const float* __restrict__ z2, const float* __restrict__ cv,
                             const float* __restrict__ bn_g, const float* __restrict__ bn_b,
                             const float* __restrict__ bn_m, const float* __restrict__ bn_v,
                             float* __restrict__ out) {
    size_t i = (size_t)blockIdx.x * 256 + threadIdx.x;
    int o = (int)(i & 255);
    size_t r = i >> 8;
    int v = (int)(r % VV);
    size_t r2 = r / VV;
    int t = (int)(r2 % TT);
    int n = (int)(r2 / TT);
    float c1 = fmaf((cv[i] - bn_m[o]) * rsqrtf(bn_v[o] + 1e-5f), bn_g[o], bn_b[o]);
    out[((size_t)(n * VV + v) * TT + t) * 256 + o] = gelu_f(z2[i] + c1);
}

// ------------------------------- launcher -----------------------------------
extern "C" void kernel_launch(void* const* d_in, const int* in_sizes, int n_in,
                              void* d_out, int out_size) {
    const float* x       = (const float*)d_in[0];
    const float* Wqk_s   = (const float*)d_in[1];
    const float* bqk_s   = (const float*)d_in[2];
    const float* alphas  = (const float*)d_in[3];
    const float* att0s   = (const float*)d_in[4];
    const float* Wo_s    = (const float*)d_in[5];
    const float* bo_s    = (const float*)d_in[6];
    const float* g_os    = (const float*)d_in[7];
    const float* b_os    = (const float*)d_in[8];
    const float* Wff_s   = (const float*)d_in[9];
    const float* bff_s   = (const float*)d_in[10];
    const float* g_ffs   = (const float*)d_in[11];
    const float* b_ffs   = (const float*)d_in[12];
    const float* Wqk_t   = (const float*)d_in[13];
    const float* bqk_t   = (const float*)d_in[14];
    const float* alphat_f= (const float*)d_in[15];
    const float* alphat_b= (const float*)d_in[16];
    const float* Wo_t    = (const float*)d_in[17];
    const float* bo_t    = (const float*)d_in[18];
    const float* g_ot    = (const float*)d_in[19];
    const float* b_ot    = (const float*)d_in[20];
    const float* Wff_t   = (const float*)d_in[21];
    const float* bff_t   = (const float*)d_in[22];
    const float* g_fft   = (const float*)d_in[23];
    const float* b_fft   = (const float*)d_in[24];
    const float* conv_w  = (const float*)d_in[25];
    const float* conv_b  = (const float*)d_in[26];
    const float* bn_g    = (const float*)d_in[27];
    const float* bn_b    = (const float*)d_in[28];
    const float* bn_m    = (const float*)d_in[29];
    const float* bn_v    = (const float*)d_in[30];
    float* out = (float*)d_out;

    void *pA, *pB, *pH, *pY1, *pY2, *pZ2, *pAS, *pAF, *pAB, *pWT;
    cudaGetSymbolAddress(&pA,  g_bufA);
    cudaGetSymbolAddress(&pB,  g_bufB);
    cudaGetSymbolAddress(&pH,  g_h);
    cudaGetSymbolAddress(&pY1, g_y1);
    cudaGetSymbolAddress(&pY2, g_y2);
    cudaGetSymbolAddress(&pZ2, g_z2);
    cudaGetSymbolAddress(&pAS, g_atts);
    cudaGetSymbolAddress(&pAF, g_attf);
    cudaGetSymbolAddress(&pAB, g_attb);
    cudaGetSymbolAddress(&pWT, g_wt);
    float* bufA = (float*)pA;  float* bufB = (float*)pB;
    float* h    = (float*)pH;  float* y1   = (float*)pY1;
    float* y2   = (float*)pY2; float* z2   = (float*)pZ2;
    float* atts = (float*)pAS; float* attf = (float*)pAF;
    float* attb = (float*)pAB; float* wt   = (float*)pWT;

    dim3 blk(256);
    const int MB = RTOT / 64;   // 800

    // Stage 1: spatial
    sgemm_bias<<<dim3(384/64, MB), blk>>>(x, Wqk_s, bqk_s, bufB, RTOT, 384, 256);
    att_s_kernel<<<NN*VV*VV, 192>>>(bufB, alphas, att0s, atts);
    y_s_kernel<<<RTOT, 256>>>(x, atts, bufA);
    sgemm_bias<<<dim3(4, MB), blk>>>(bufA, Wo_s, bo_s, h, RTOT, 256, 768);
    ln_kernel<<<NN*VV, 256>>>(h, x, g_os, b_os, y1, TT*CC, 0);
    sgemm_bias<<<dim3(4, MB), blk>>>(y1, Wff_s, bff_s, h, RTOT, 256, 256);
    ln_kernel<<<NN*VV, 256>>>(h, x, g_ffs, b_ffs, y2, TT*CC, 1);   // transposed write

    // Stage 2: temporal
    sgemm_bias<<<dim3(8, MB), blk>>>(y2, Wqk_t, bqk_t, bufB, RTOT, 512, 256);
    att_t_kernel<<<NN*TT, 256>>>(bufB, alphat_f, alphat_b, attf, attb);
    z_kernel<<<RTOT, 256>>>(y2, attf, attb, bufA);
    sgemm_bias<<<dim3(4, MB), blk>>>(bufA, Wo_t, bo_t, h, RTOT, 256, 1024);
    ln_kernel<<<NN*TT, 256>>>(h, y2, g_ot, b_ot, y1, VV*CC, 0);
    sgemm_bias<<<dim3(4, MB), blk>>>(y1, Wff_t, bff_t, h, RTOT, 256, 256);
    ln_kernel<<<NN*TT, 256>>>(h, y2, g_fft, b_fft, z2, VV*CC, 0);

    // Stage 3: conv + BN + gelu + transpose
    convw_t_kernel<<<(256*256*7 + 255)/256, 256>>>(conv_w, wt);
    conv_gemm<<<dim3(4, MB), blk>>>(z2, wt, conv_b, h);
    final_kernel<<<RTOT, 256>>>(z2, h, bn_g, bn_b, bn_m, bn_v, out);
}

// round 3
// speedup vs baseline: 1.5771x; 1.5713x over previous
#include <cuda_runtime.h>
#include <math.h>
#include <stdint.h>

#define NN 32
#define VV 25
#define TT 64
#define RTOT (NN*VV*TT)   /* 51200 */

__device__ float g_bufA[(size_t)RTOT * 1024];
__device__ float g_bufB[(size_t)RTOT * 512];
__device__ float g_h   [(size_t)RTOT * 256];
__device__ float g_y1  [(size_t)RTOT * 256];
__device__ float g_y2  [(size_t)RTOT * 256];
__device__ float g_z2  [(size_t)RTOT * 256];
__device__ float g_atts[NN*VV*VV*3];
__device__ float g_attf[NN*TT*TT*2];
__device__ float g_attb[NN*TT*TT*2];
__device__ float g_wt  [7*256*256];

__device__ __forceinline__ float gelu_f(float x) {
    return 0.5f * x * (1.0f + erff(x * 0.7071067811865475f));
}
__device__ __forceinline__ unsigned long long pack2(float lo, float hi) {
    unsigned long long r;
    asm("mov.b64 %0, {%1, %2};" : "=l"(r) : "f"(lo), "f"(hi));
    return r;
}
__device__ __forceinline__ void ffma2(unsigned long long &d, unsigned long long a, unsigned long long b) {
    asm("fma.rn.f32x2 %0, %1, %2, %0;" : "+l"(d) : "l"(a), "l"(b));
}
__device__ __forceinline__ float2 unpack2(unsigned long long v) {
    float2 f;
    asm("mov.b64 {%0, %1}, %2;" : "=f"(f.x), "=f"(f.y) : "l"(v));
    return f;
}

// ---------------- FFMA2 SGEMM: 128x128 tile, K-chunk 16 ---------------------
__global__ __launch_bounds__(256) void sgemm2(
        const float* __restrict__ A, const float* __restrict__ B,
        const float* __restrict__ bias, float* __restrict__ C,
        int M, int N, int K) {
    __shared__ float As[16][130];
    __shared__ float Bs[16][128];
    const int tid = threadIdx.x;
    const int tx = tid & 15, ty = tid >> 4;
    const int bm = blockIdx.y << 7, bn = blockIdx.x << 7;
    unsigned long long acc[4][8];
#pragma unroll
    for (int i = 0; i < 4; i++)
#pragma unroll
        for (int j = 0; j < 8; j++) acc[i][j] = 0ull;
    const int ar = tid >> 2, ac = (tid & 3) << 2;
    const int br = tid >> 5, bc = (tid & 31) << 2;
    for (int k0 = 0; k0 < K; k0 += 16) {
        float4 a0 = *(const float4*)(A + (size_t)(bm + ar) * K + k0 + ac);
        float4 a1 = *(const float4*)(A + (size_t)(bm + ar + 64) * K + k0 + ac);
        As[ac + 0][ar] = a0.x; As[ac + 1][ar] = a0.y; As[ac + 2][ar] = a0.z; As[ac + 3][ar] = a0.w;
        As[ac + 0][ar + 64] = a1.x; As[ac + 1][ar + 64] = a1.y; As[ac + 2][ar + 64] = a1.z; As[ac + 3][ar + 64] = a1.w;
        *(float4*)(&Bs[br][bc])     = *(const float4*)(B + (size_t)(k0 + br) * N + bn + bc);
        *(float4*)(&Bs[br + 8][bc]) = *(const float4*)(B + (size_t)(k0 + br + 8) * N + bn + bc);
        __syncthreads();
#pragma unroll
        for (int kk = 0; kk < 16; kk++) {
            const unsigned long long* ap = (const unsigned long long*)(&As[kk][ty << 3]);
            unsigned long long a0p = ap[0], a1p = ap[1], a2p = ap[2], a3p = ap[3];
            float4 b0 = *(const float4*)(&Bs[kk][tx << 2]);
            float4 b1 = *(const float4*)(&Bs[kk][(tx << 2) + 64]);
            unsigned long long bd[8];
            bd[0] = pack2(b0.x, b0.x); bd[1] = pack2(b0.y, b0.y);
            bd[2] = pack2(b0.z, b0.z); bd[3] = pack2(b0.w, b0.w);
            bd[4] = pack2(b1.x, b1.x); bd[5] = pack2(b1.y, b1.y);
            bd[6] = pack2(b1.z, b1.z); bd[7] = pack2(b1.w, b1.w);
#pragma unroll
            for (int j = 0; j < 8; j++) {
                ffma2(acc[0][j], a0p, bd[j]);
                ffma2(acc[1][j], a1p, bd[j]);
                ffma2(acc[2][j], a2p, bd[j]);
                ffma2(acc[3][j], a3p, bd[j]);
            }
        }
        __syncthreads();
    }
    float4 bb0 = *(const float4*)(bias + bn + (tx << 2));
    float4 bb1 = *(const float4*)(bias + bn + (tx << 2) + 64);
#pragma unroll
    for (int i = 0; i < 4; i++) {
        float2 c0 = unpack2(acc[i][0]), c1 = unpack2(acc[i][1]);
        float2 c2 = unpack2(acc[i][2]), c3 = unpack2(acc[i][3]);
        float2 d0 = unpack2(acc[i][4]), d1 = unpack2(acc[i][5]);
        float2 d2 = unpack2(acc[i][6]), d3 = unpack2(acc[i][7]);
        size_t r0 = (size_t)(bm + (ty << 3) + i * 2) * N + bn;
        size_t r1 = r0 + N;
        *(float4*)(C + r0 + (tx << 2))      = make_float4(c0.x + bb0.x, c1.x + bb0.y, c2.x + bb0.z, c3.x + bb0.w);
        *(float4*)(C + r1 + (tx << 2))      = make_float4(c0.y + bb0.x, c1.y + bb0.y, c2.y + bb0.z, c3.y + bb0.w);
        *(float4*)(C + r0 + (tx << 2) + 64) = make_float4(d0.x + bb1.x, d1.x + bb1.y, d2.x + bb1.z, d3.x + bb1.w);
        *(float4*)(C + r1 + (tx << 2) + 64) = make_float4(d0.y + bb1.x, d1.y + bb1.y, d2.y + bb1.z, d3.y + bb1.w);
    }
}

// -------------- conv as implicit-im2col FFMA2 GEMM (K=1792) -----------------
__global__ __launch_bounds__(256) void conv2(
        const float* __restrict__ Z, const float* __restrict__ B,
        const float* __restrict__ bias, float* __restrict__ C) {
    const int N = 256, K = 7 * 256;
    __shared__ float As[16][130];
    __shared__ float Bs[16][128];
    const int tid = threadIdx.x;
    const int tx = tid & 15, ty = tid >> 4;
    const int bm = blockIdx.y << 7, bn = blockIdx.x << 7;
    unsigned long long acc[4][8];
#pragma unroll
    for (int i = 0; i < 4; i++)
#pragma unroll
        for (int j = 0; j < 8; j++) acc[i][j] = 0ull;
    const int ar = tid >> 2, ac = (tid & 3) << 2;
    const int br = tid >> 5, bc = (tid & 31) << 2;
    const int row0 = bm + ar, row1 = row0 + 64;
    const int t0 = (row0 / VV) % TT, t1 = (row1 / VV) % TT;
    for (int k0 = 0; k0 < K; k0 += 16) {
        int kg = k0 + ac;
        int dt = (kg >> 8) - 3;
        int ii = kg & 255;
        float4 a0 = make_float4(0.f,0.f,0.f,0.f), a1 = a0;
        int tt0 = t0 + dt, tt1 = t1 + dt;
        if (tt0 >= 0 && tt0 < TT) a0 = *(const float4*)(Z + ((size_t)row0 + (size_t)dt * VV) * 256 + ii);
        if (tt1 >= 0 && tt1 < TT) a1 = *(const float4*)(Z + ((size_t)row1 + (size_t)dt * VV) * 256 + ii);
        As[ac + 0][ar] = a0.x; As[ac + 1][ar] = a0.y; As[ac + 2][ar] = a0.z; As[ac + 3][ar] = a0.w;
        As[ac + 0][ar + 64] = a1.x; As[ac + 1][ar + 64] = a1.y; As[ac + 2][ar + 64] = a1.z; As[ac + 3][ar + 64] = a1.w;
        *(float4*)(&Bs[br][bc])     = *(const float4*)(B + (size_t)(k0 + br) * N + bn + bc);
        *(float4*)(&Bs[br + 8][bc]) = *(const float4*)(B + (size_t)(k0 + br + 8) * N + bn + bc);
        __syncthreads();
#pragma unroll
        for (int kk = 0; kk < 16; kk++) {
            const unsigned long long* ap = (const unsigned long long*)(&As[kk][ty << 3]);
            unsigned long long a0p = ap[0], a1p = ap[1], a2p = ap[2], a3p = ap[3];
            float4 b0 = *(const float4*)(&Bs[kk][tx << 2]);
            float4 b1 = *(const float4*)(&Bs[kk][(tx << 2) + 64]);
            unsigned long long bd[8];
            bd[0] = pack2(b0.x, b0.x); bd[1] = pack2(b0.y, b0.y);
            bd[2] = pack2(b0.z, b0.z); bd[3] = pack2(b0.w, b0.w);
            bd[4] = pack2(b1.x, b1.x); bd[5] = pack2(b1.y, b1.y);
            bd[6] = pack2(b1.z, b1.z); bd[7] = pack2(b1.w, b1.w);
#pragma unroll
            for (int j = 0; j < 8; j++) {
                ffma2(acc[0][j], a0p, bd[j]);
                ffma2(acc[1][j], a1p, bd[j]);
                ffma2(acc[2][j], a2p, bd[j]);
                ffma2(acc[3][j], a3p, bd[j]);
            }
        }
        __syncthreads();
    }
    float4 bb0 = *(const float4*)(bias + bn + (tx << 2));
    float4 bb1 = *(const float4*)(bias + bn + (tx << 2) + 64);
#pragma unroll
    for (int i = 0; i < 4; i++) {
        float2 c0 = unpack2(acc[i][0]), c1 = unpack2(acc[i][1]);
        float2 c2 = unpack2(acc[i][2]), c3 = unpack2(acc[i][3]);
        float2 d0 = unpack2(acc[i][4]), d1 = unpack2(acc[i][5]);
        float2 d2 = unpack2(acc[i][6]), d3 = unpack2(acc[i][7]);
        size_t r0 = (size_t)(bm + (ty << 3) + i * 2) * N + bn;
        size_t r1 = r0 + N;
        *(float4*)(C + r0 + (tx << 2))      = make_float4(c0.x + bb0.x, c1.x + bb0.y, c2.x + bb0.z, c3.x + bb0.w);
        *(float4*)(C + r1 + (tx << 2))      = make_float4(c0.y + bb0.x, c1.y + bb0.y, c2.y + bb0.z, c3.y + bb0.w);
        *(float4*)(C + r0 + (tx << 2) + 64) = make_float4(d0.x + bb1.x, d1.x + bb1.y, d2.x + bb1.z, d3.x + bb1.w);
        *(float4*)(C + r1 + (tx << 2) + 64) = make_float4(d0.y + bb1.x, d1.y + bb1.y, d2.y + bb1.z, d3.y + bb1.w);
    }
}

// --------- de-interleave spatial qk -> qT,kT [(n*3+s)*25+u][4096] -----------
__global__ void deint_s(const float* __restrict__ qk, float* __restrict__ qT,
                        float* __restrict__ kT) {
    size_t idx = (size_t)blockIdx.x * 256 + threadIdx.x;   // 51200*384 elems
    int col = (int)(idx % 384);
    size_t row = idx / 384;
    int t = (int)(row % TT);
    size_t nu = row / TT;                                  // n*25+u
    int n = (int)(nu / VV), u = (int)(nu % VV);
    int ci = col / 6, r = col % 6;
    float v = qk[idx];
    int s = (r < 3) ? r : r - 3;
    size_t dst = (((size_t)(n * 3 + s) * VV + u) << 12) + t * 64 + ci;
    if (r < 3) qT[dst] = v; else kT[dst] = v;
}

// spatial attention: block per (n,s); 128 threads; u-tiled by 5
__global__ __launch_bounds__(128) void att_s_fast(
        const float* __restrict__ qT, const float* __restrict__ kT,
        const float* __restrict__ alphas, const float* __restrict__ att0,
        float* __restrict__ att) {
    int ns = blockIdx.x, n = ns / 3, s = ns % 3;
    __shared__ float qs[25][132], ks[25][132];
    const float* qb = qT + ((size_t)ns * VV << 12);
    const float* kb = kT + ((size_t)ns * VV << 12);
    int t = threadIdx.x;
    int u0 = (t / 25) * 5, v = t % 25;
    float acc[5] = {0.f, 0.f, 0.f, 0.f, 0.f};
    for (int kc = 0; kc < 4096; kc += 128) {
        for (int i = t; i < 25 * 128; i += 128) {
            int uu = i >> 7, e = i & 127;
            qs[uu][e] = qb[((size_t)uu << 12) + kc + e];
            ks[uu][e] = kb[((size_t)uu << 12) + kc + e];
        }
        __syncthreads();
        if (t < 125) {
#pragma unroll 4
            for (int e = 0; e < 128; e++) {
                float kv = ks[v][e];
                acc[0] = fmaf(qs[u0 + 0][e], kv, acc[0]);
                acc[1] = fmaf(qs[u0 + 1][e], kv, acc[1]);
                acc[2] = fmaf(qs[u0 + 2][e], kv, acc[2]);
                acc[3] = fmaf(qs[u0 + 3][e], kv, acc[3]);
                acc[4] = fmaf(qs[u0 + 4][e], kv, acc[4]);
            }
        }
        __syncthreads();
    }
    if (t < 125) {
        float al = alphas[s];
#pragma unroll
        for (int i = 0; i < 5; i++) {
            int u = u0 + i;
            att[((size_t)(n * VV + u) * VV + v) * 3 + s] =
                tanhf(acc[i] * (1.f / 4096.f)) * al + att0[((size_t)u * VV + v) * 3 + s];
        }
    }
}

// --------- de-interleave temporal qkt -> qd,kd [(n*4+m)][t][1600] -----------
__global__ void deint_t(const float* __restrict__ qkt, float* __restrict__ qd,
                        float* __restrict__ kd) {
    size_t idx = (size_t)blockIdx.x * 256 + threadIdx.x;   // 51200*512 elems
    int col = (int)(idx & 511);
    size_t row = idx >> 9;
    int v = (int)(row % VV);
    size_t nt = row / VV;
    int t = (int)(nt % TT), n = (int)(nt / TT);
    int ci = col >> 3, j = col & 7;
    float val = qkt[idx];
    int m = (j < 4) ? j : j - 4;
    size_t dst = ((size_t)(n * 4 + m) * TT + t) * 1600 + v * 64 + ci;
    if (j < 4) qd[dst] = val; else kd[dst] = val;
}

// temporal attention: block per (n,m); 64x64 out, K=1600
__global__ __launch_bounds__(256) void att_t_fast(
        const float* __restrict__ qd, const float* __restrict__ kd,
        const float* __restrict__ alf, const float* __restrict__ alb,
        float* __restrict__ attf, float* __restrict__ attb) {
    int nm = blockIdx.x, n = nm >> 2, m = nm & 3;
    int s = m & 1, dir = m >> 1;
    __shared__ float Qs[64][68], Ks[64][68];
    const float* qb = qd + (size_t)nm * TT * 1600;
    const float* kb = kd + (size_t)nm * TT * 1600;
    const int tid = threadIdx.x;
    const int tx = tid & 15, ty = tid >> 4;
    const int lr = tid >> 2, lc = (tid & 3) << 4;
    float acc[4][4] = {};
    for (int kc = 0; kc < 1600; kc += 64) {
#pragma unroll
        for (int j = 0; j < 4; j++) {
            float4 q4 = *(const float4*)(qb + (size_t)lr * 1600 + kc + lc + j * 4);
            float4 k4 = *(const float4*)(kb + (size_t)lr * 1600 + kc + lc + j * 4);
            Qs[lc + j*4 + 0][lr] = q4.x; Qs[lc + j*4 + 1][lr] = q4.y;
            Qs[lc + j*4 + 2][lr] = q4.z; Qs[lc + j*4 + 3][lr] = q4.w;
            Ks[lc + j*4 + 0][lr] = k4.x; Ks[lc + j*4 + 1][lr] = k4.y;
            Ks[lc + j*4 + 2][lr] = k4.z; Ks[lc + j*4 + 3][lr] = k4.w;
        }
        __syncthreads();
#pragma unroll 8
        for (int kk = 0; kk < 64; kk++) {
            float4 aq = *(const float4*)(&Qs[kk][ty << 2]);
            float4 bk = *(const float4*)(&Ks[kk][tx << 2]);
            float a[4] = {aq.x, aq.y, aq.z, aq.w};
            float b[4] = {bk.x, bk.y, bk.z, bk.w};
#pragma unroll
            for (int i = 0; i < 4; i++)
#pragma unroll
                for (int j = 0; j < 4; j++) acc[i][j] = fmaf(a[i], b[j], acc[i][j]);
        }
        __syncthreads();
    }
    float al = dir ? alb[s] : alf[s];
#pragma unroll
    for (int i = 0; i < 4; i++) {
#pragma unroll
        for (int j = 0; j < 4; j++) {
            int t_ = (ty << 2) + i, q_ = (tx << 2) + j;
            float val = tanhf(acc[i][j] * (1.f / 1600.f)) * al;
            size_t idx = ((size_t)(n * TT + t_) * TT + q_) * 2 + s;
            if (dir == 0) attf[idx] = (q_ <= t_) ? val : 0.f;
            else          attb[idx] = (q_ >= t_) ? val : 0.f;
        }
    }
}

// y_s[n,v,t, c*3+s] = sum_u x[n,u,t,c] * att[n,u,v,s]
__global__ void y_s_kernel(const float* __restrict__ x, const float* __restrict__ att,
                           float* __restrict__ y) {
    int b = blockIdx.x;
    int t = b % TT, v = (b / TT) % VV, n = b / (TT * VV);
    int c = threadIdx.x;
    __shared__ float a_s[VV * 3];
    if (c < VV * 3)
        a_s[c] = att[((size_t)(n * VV + c / 3) * VV + v) * 3 + (c % 3)];
    __syncthreads();
    float a0 = 0.f, a1 = 0.f, a2 = 0.f;
#pragma unroll
    for (int u = 0; u < VV; u++) {
        float xv = x[((size_t)(n * VV + u) * TT + t) * 256 + c];
        a0 = fmaf(xv, a_s[u * 3 + 0], a0);
        a1 = fmaf(xv, a_s[u * 3 + 1], a1);
        a2 = fmaf(xv, a_s[u * 3 + 2], a2);
    }
    float* yp = y + (size_t)b * 768 + c * 3;
    yp[0] = a0; yp[1] = a1; yp[2] = a2;
}

// LN over group + residual + gelu
__global__ void ln_kernel(const float* __restrict__ h, const float* __restrict__ res,
                          const float* __restrict__ g, const float* __restrict__ b,
                          float* __restrict__ out, int G, int mode) {
    int grp = blockIdx.x;
    const float* hp = h + (size_t)grp * G;
    const float* rp = res + (size_t)grp * G;
    float s = 0.f, sq = 0.f;
    for (int i = threadIdx.x; i < G; i += blockDim.x) {
        float v = hp[i]; s += v; sq = fmaf(v, v, sq);
    }
    for (int o = 16; o; o >>= 1) {
        s += __shfl_down_sync(0xffffffffu, s, o);
        sq += __shfl_down_sync(0xffffffffu, sq, o);
    }
    __shared__ float ss[8], sqs[8];
    __shared__ float mean_s, inv_s;
    int w = threadIdx.x >> 5;
    if ((threadIdx.x & 31) == 0) { ss[w] = s; sqs[w] = sq; }
    __syncthreads();
    if (threadIdx.x == 0) {
        float S = 0.f, Q = 0.f;
        for (int i = 0; i < 8; i++) { S += ss[i]; Q += sqs[i]; }
        float mean = S / G;
        float var = Q / G - mean * mean;
        mean_s = mean; inv_s = rsqrtf(var + 1e-5f);
    }
    __syncthreads();
    float mean = mean_s, inv = inv_s;
    if (mode == 0) {
        float* op = out + (size_t)grp * G;
        for (int i = threadIdx.x; i < G; i += blockDim.x)
            op[i] = gelu_f(rp[i] + fmaf((hp[i] - mean) * inv, g[i], b[i]));
    } else {
        int n = grp / VV, v = grp % VV;
        for (int i = threadIdx.x; i < G; i += blockDim.x) {
            int t = i >> 8, c = i & 255;
            out[((size_t)(n * TT + t) * VV + v) * 256 + c] =
                gelu_f(rp[i] + fmaf((hp[i] - mean) * inv, g[i], b[i]));
        }
    }
}

// z apply
__global__ void z_kernel(const float* __restrict__ y2t, const float* __restrict__ attf,
                         const float* __restrict__ attb, float* __restrict__ z) {
    int b = blockIdx.x;
    int v = b % VV, q = (b / VV) % TT, n = b / (VV * TT);
    int c = threadIdx.x;
    __shared__ float af[TT][2], ab[TT][2];
    if (c < 128) {
        int t = c >> 1, s = c & 1;
        af[t][s] = attf[((size_t)(n * TT + t) * TT + q) * 2 + s];
    } else {
        int r = c - 128; int t = r >> 1, s = r & 1;
        ab[t][s] = attb[((size_t)(n * TT + t) * TT + q) * 2 + s];
    }
    __syncthreads();
    float f0 = 0.f, f1 = 0.f, b0 = 0.f, b1 = 0.f;
#pragma unroll 4
    for (int t = 0; t < TT; t++) {
        float yv = y2t[((size_t)(n * TT + t) * VV + v) * 256 + c];
        f0 = fmaf(yv, af[t][0], f0); f1 = fmaf(yv, af[t][1], f1);
        b0 = fmaf(yv, ab[t][0], b0); b1 = fmaf(yv, ab[t][1], b1);
    }
    float* zp = z + (size_t)b * 1024;
    zp[c * 2 + 0] = f0; zp[c * 2 + 1] = f1;
    zp[512 + c * 2 + 0] = b0; zp[512 + c * 2 + 1] = b1;
}

__global__ void convw_t_kernel(const float* __restrict__ w, float* __restrict__ wt) {
    int idx = blockIdx.x * 256 + threadIdx.x;
    if (idx < 256 * 256 * 7) {
        int kk = idx % 7, i = (idx / 7) % 256, o = idx / (7 * 256);
        wt[((size_t)kk * 256 + i) * 256 + o] = w[idx];
    }
}

__global__ void final_kernel(const float* __restrict__ z2, const float* __restrict__ cv,
                             const float* __restrict__ bn_g, const float* __restrict__ bn_b,
                             const float* __restrict__ bn_m, const float* __restrict__ bn_v,
                             float* __restrict__ out) {
    size_t i = (size_t)blockIdx.x * 256 + threadIdx.x;
    int o = (int)(i & 255);
    size_t r = i >> 8;
    int v = (int)(r % VV);
    size_t r2 = r / VV;
    int t = (int)(r2 % TT);
    int n = (int)(r2 / TT);
    float c1 = fmaf((cv[i] - bn_m[o]) * rsqrtf(bn_v[o] + 1e-5f), bn_g[o], bn_b[o]);
    out[((size_t)(n * VV + v) * TT + t) * 256 + o] = gelu_f(z2[i] + c1);
}

// ------------------------------- launcher -----------------------------------
extern "C" void kernel_launch(void* const* d_in, const int* in_sizes, int n_in,
                              void* d_out, int out_size) {
    const float* x       = (const float*)d_in[0];
    const float* Wqk_s   = (const float*)d_in[1];
    const float* bqk_s   = (const float*)d_in[2];
    const float* alphas  = (const float*)d_in[3];
    const float* att0s   = (const float*)d_in[4];
    const float* Wo_s    = (const float*)d_in[5];
    const float* bo_s    = (const float*)d_in[6];
    const float* g_os    = (const float*)d_in[7];
    const float* b_os    = (const float*)d_in[8];
    const float* Wff_s   = (const float*)d_in[9];
    const float* bff_s   = (const float*)d_in[10];
    const float* g_ffs   = (const float*)d_in[11];
    const float* b_ffs   = (const float*)d_in[12];
    const float* Wqk_t   = (const float*)d_in[13];
    const float* bqk_t   = (const float*)d_in[14];
    const float* alphat_f= (const float*)d_in[15];
    const float* alphat_b= (const float*)d_in[16];
    const float* Wo_t    = (const float*)d_in[17];
    const float* bo_t    = (const float*)d_in[18];
    const float* g_ot    = (const float*)d_in[19];
    const float* b_ot    = (const float*)d_in[20];
    const float* Wff_t   = (const float*)d_in[21];
    const float* bff_t   = (const float*)d_in[22];
    const float* g_fft   = (const float*)d_in[23];
    const float* b_fft   = (const float*)d_in[24];
    const float* conv_w  = (const float*)d_in[25];
    const float* conv_b  = (const float*)d_in[26];
    const float* bn_g    = (const float*)d_in[27];
    const float* bn_b    = (const float*)d_in[28];
    const float* bn_m    = (const float*)d_in[29];
    const float* bn_v    = (const float*)d_in[30];
    float* out = (float*)d_out;

    void *pA, *pB, *pH, *pY1, *pY2, *pZ2, *pAS, *pAF, *pAB, *pWT;
    cudaGetSymbolAddress(&pA,  g_bufA);
    cudaGetSymbolAddress(&pB,  g_bufB);
    cudaGetSymbolAddress(&pH,  g_h);
    cudaGetSymbolAddress(&pY1, g_y1);
    cudaGetSymbolAddress(&pY2, g_y2);
    cudaGetSymbolAddress(&pZ2, g_z2);
    cudaGetSymbolAddress(&pAS, g_atts);
    cudaGetSymbolAddress(&pAF, g_attf);
    cudaGetSymbolAddress(&pAB, g_attb);
    cudaGetSymbolAddress(&pWT, g_wt);
    float* bufA = (float*)pA;  float* bufB = (float*)pB;
    float* h    = (float*)pH;  float* y1   = (float*)pY1;
    float* y2   = (float*)pY2; float* z2   = (float*)pZ2;
    float* atts = (float*)pAS; float* attf = (float*)pAF;
    float* attb = (float*)pAB; float* wt   = (float*)pWT;

    dim3 blk(256);
    const int MB = RTOT / 128;   // 400

    // Stage 1: spatial
    sgemm2<<<dim3(3, MB), blk>>>(x, Wqk_s, bqk_s, bufB, RTOT, 384, 256);
    deint_s<<<RTOT * 384 / 256, 256>>>(bufB, h, y1);
    att_s_fast<<<NN * 3, 128>>>(h, y1, alphas, att0s, atts);
    y_s_kernel<<<RTOT, 256>>>(x, atts, bufA);
    sgemm2<<<dim3(2, MB), blk>>>(bufA, Wo_s, bo_s, h, RTOT, 256, 768);
    ln_kernel<<<NN*VV, 256>>>(h, x, g_os, b_os, y1, TT*256, 0);
    sgemm2<<<dim3(2, MB), blk>>>(y1, Wff_s, bff_s, h, RTOT, 256, 256);
    ln_kernel<<<NN*VV, 256>>>(h, x, g_ffs, b_ffs, y2, TT*256, 1);

    // Stage 2: temporal
    sgemm2<<<dim3(4, MB), blk>>>(y2, Wqk_t, bqk_t, bufB, RTOT, 512, 256);
    deint_t<<<RTOT * 512 / 256, 256>>>(bufB, h, y1);
    att_t_fast<<<NN * 4, 256>>>(h, y1, alphat_f, alphat_b, attf, attb);
    z_kernel<<<RTOT, 256>>>(y2, attf, attb, bufA);
    sgemm2<<<dim3(2, MB), blk>>>(bufA, Wo_t, bo_t, h, RTOT, 256, 1024);
    ln_kernel<<<NN*TT, 256>>>(h, y2, g_ot, b_ot, y1, VV*256, 0);
    sgemm2<<<dim3(2, MB), blk>>>(y1, Wff_t, bff_t, h, RTOT, 256, 256);
    ln_kernel<<<NN*TT, 256>>>(h, y2, g_fft, b_fft, z2, VV*256, 0);

    // Stage 3
    convw_t_kernel<<<(256*256*7 + 255)/256, 256>>>(conv_w, wt);
    conv2<<<dim3(2, MB), blk>>>(z2, wt, conv_b, h);
    final_kernel<<<RTOT, 256>>>(z2, h, bn_g, bn_b, bn_m, bn_v, out);
}

// round 5
// speedup vs baseline: 2.3539x; 1.4925x over previous
#include <cuda_runtime.h>
#include <cuda_bf16.h>
#include <math.h>
#include <stdint.h>

#define NN 32
#define VV 25
#define TT 64
#define RTOT (NN*VV*TT)   /* 51200 */

// ------------------------- scratch (device globals) -------------------------
__device__ float g_bufA[(size_t)RTOT * 1024];
__device__ float g_bufB[(size_t)RTOT * 512];
__device__ float g_h   [(size_t)RTOT * 256];
__device__ float g_y1  [(size_t)RTOT * 256];
__device__ float g_y2  [(size_t)RTOT * 256];
__device__ float g_z2  [(size_t)RTOT * 256];
__device__ float g_atts[NN*VV*VV*3];
__device__ float g_attf[NN*TT*TT*2];   // transposed layout [n][q][t][s]
__device__ float g_attb[NN*TT*TT*2];
#define WTOT 1277952
__device__ __nv_bfloat16 g_wh[WTOT];
__device__ __nv_bfloat16 g_wl[WTOT];
#define OFF_QKS 0         /* K=256  N=384  */
#define OFF_WOS 98304     /* K=768  N=256  */
#define OFF_FFS 294912    /* K=256  N=256  */
#define OFF_QKT 360448    /* K=256  N=512  */
#define OFF_WOT 491520    /* K=1024 N=256  */
#define OFF_FFT 753664    /* K=256  N=256  */
#define OFF_CNV 819200    /* K=1792 N=256  */

__device__ __forceinline__ float gelu_f(float x) {
    return 0.5f * x * (1.0f + erff(x * 0.7071067811865475f));
}
__device__ __forceinline__ void split2(float a, float b, uint32_t &hi, uint32_t &lo) {
    __nv_bfloat16 ha = __float2bfloat16(a), hb = __float2bfloat16(b);
    float la = a - __bfloat162float(ha), lb = b - __bfloat162float(hb);
    __nv_bfloat16 l1 = __float2bfloat16(la), l2 = __float2bfloat16(lb);
    hi = (uint32_t)__bfloat16_as_ushort(ha) | ((uint32_t)__bfloat16_as_ushort(hb) << 16);
    lo = (uint32_t)__bfloat16_as_ushort(l1) | ((uint32_t)__bfloat16_as_ushort(l2) << 16);
}
__device__ __forceinline__ uint32_t smem_u32(const void* p) {
    uint32_t a;
    asm("{ .reg .u64 t; cvta.to.shared.u64 t, %1; cvt.u32.u64 %0, t; }" : "=r"(a) : "l"(p));
    return a;
}
__device__ __forceinline__ void ldm4(uint32_t &r0, uint32_t &r1, uint32_t &r2,
                                     uint32_t &r3, uint32_t a) {
    asm volatile("ldmatrix.sync.aligned.m8n8.x4.shared.b16 {%0,%1,%2,%3}, [%4];"
        : "=r"(r0), "=r"(r1), "=r"(r2), "=r"(r3) : "r"(a));
}
__device__ __forceinline__ void mma16816(float* c, const uint32_t* a, const uint32_t* b) {
    asm volatile(
        "mma.sync.aligned.m16n8k16.row.col.f32.bf16.bf16.f32 "
        "{%0,%1,%2,%3}, {%4,%5,%6,%7}, {%8,%9}, {%0,%1,%2,%3};"
        : "+f"(c[0]), "+f"(c[1]), "+f"(c[2]), "+f"(c[3])
        : "r"(a[0]), "r"(a[1]), "r"(a[2]), "r"(a[3]), "r"(b[0]), "r"(b[1]));
}

// ======================= HMMA GEMM: 128x128 tile, k-chunk 64 ==================
// C[M,N] = A[M,K](fp32) @ W[K,N] (pre-split bf16 stored [N][K]) + bias
// smem (dynamic 64KB): Ah(16K) Al(16K) Bh(16K) Bl(16K); rows of 64 bf16 = 128B,
// 16B-chunk XOR swizzle: chunk c of row r lives at c^(r&7).
#define GSM 65536
__global__ __launch_bounds__(256) void gemm_mma(
        const float* __restrict__ A, const __nv_bfloat16* __restrict__ Bh,
        const __nv_bfloat16* __restrict__ Bl, const float* __restrict__ bias,
        float* __restrict__ C, int M, int N, int K) {
    extern __shared__ char sm[];
    char* pAh = sm;            char* pAl = sm + 16384;
    char* pBh = sm + 32768;    char* pBl = sm + 49152;
    const uint32_t sAh = smem_u32(pAh), sAl = smem_u32(pAl);
    const uint32_t sBh = smem_u32(pBh), sBl = smem_u32(pBl);
    const int tid = threadIdx.x, lane = tid & 31, w = tid >> 5;
    const int wm = w & 3, wn = w >> 2;
    const int bm = blockIdx.y << 7, bn = blockIdx.x << 7;
    float acc[2][8][4];
#pragma unroll
    for (int i = 0; i < 2; i++)
#pragma unroll
        for (int j = 0; j < 8; j++)
#pragma unroll
            for (int q = 0; q < 4; q++) acc[i][j][q] = 0.f;

    for (int k0 = 0; k0 < K; k0 += 64) {
        const float* Ab = A + (size_t)bm * K + k0;
#pragma unroll
        for (int j = 0; j < 8; j++) {
            int f = j * 256 + tid;
            int row = f >> 4, c4 = f & 15;
            float4 v = *(const float4*)(Ab + (size_t)row * K + (c4 << 2));
            uint32_t h0, l0, h1, l1;
            split2(v.x, v.y, h0, l0);
            split2(v.z, v.w, h1, l1);
            uint32_t off = row * 128 + (((c4 >> 1) ^ (row & 7)) << 4) + ((c4 & 1) << 3);
            *(uint2*)(pAh + off) = make_uint2(h0, h1);
            *(uint2*)(pAl + off) = make_uint2(l0, l1);
        }
        const __nv_bfloat16* Bhb = Bh + (size_t)bn * K + k0;
        const __nv_bfloat16* Blb = Bl + (size_t)bn * K + k0;
#pragma unroll
        for (int j = 0; j < 4; j++) {
            int f = j * 256 + tid;
            int row = f >> 3, ch = f & 7;
            uint32_t off = row * 128 + ((ch ^ (row & 7)) << 4);
            *(uint4*)(pBh + off) = *(const uint4*)((const char*)(Bhb + (size_t)row * K) + (ch << 4));
            *(uint4*)(pBl + off) = *(const uint4*)((const char*)(Blb + (size_t)row * K) + (ch << 4));
        }
        __syncthreads();
#pragma unroll
        for (int kk = 0; kk < 4; kk++) {
            uint32_t ah[2][4], al[2][4], bh[8][2], bl[8][2];
            const int arow = wm * 32 + (lane & 15);
            const uint32_t aoff = (uint32_t)(((kk * 2 + (lane >> 4)) ^ (lane & 7)) << 4);
#pragma unroll
            for (int mi = 0; mi < 2; mi++) {
                ldm4(ah[mi][0], ah[mi][1], ah[mi][2], ah[mi][3],
                     sAh + (arow + mi * 16) * 128 + aoff);
                ldm4(al[mi][0], al[mi][1], al[mi][2], al[mi][3],
                     sAl + (arow + mi * 16) * 128 + aoff);
            }
            const uint32_t boff = (uint32_t)(((kk * 2 + ((lane >> 3) & 1)) ^ (lane & 7)) << 4);
#pragma unroll
            for (int p = 0; p < 4; p++) {
                int brow = wn * 64 + p * 16 + ((lane & 16) >> 1) + (lane & 7);
                ldm4(bh[2*p][0], bh[2*p][1], bh[2*p+1][0], bh[2*p+1][1],
                     sBh + brow * 128 + boff);
                ldm4(bl[2*p][0], bl[2*p][1], bl[2*p+1][0], bl[2*p+1][1],
                     sBl + brow * 128 + boff);
            }
#pragma unroll
            for (int mi = 0; mi < 2; mi++)
#pragma unroll
                for (int nf = 0; nf < 8; nf++) {
                    mma16816(acc[mi][nf], ah[mi], bh[nf]);
                    mma16816(acc[mi][nf], ah[mi], bl[nf]);
                    mma16816(acc[mi][nf], al[mi], bh[nf]);
                }
        }
        __syncthreads();
    }
    const int gid = lane >> 2, tig = lane & 3;
#pragma unroll
    for (int mi = 0; mi < 2; mi++)
#pragma unroll
        for (int nf = 0; nf < 8; nf++) {
            int col = bn + wn * 64 + nf * 8 + tig * 2;
            float b0v = bias[col], b1v = bias[col + 1];
            int r0 = bm + wm * 32 + mi * 16 + gid;
            *(float2*)(C + (size_t)r0 * N + col) =
                make_float2(acc[mi][nf][0] + b0v, acc[mi][nf][1] + b1v);
            *(float2*)(C + (size_t)(r0 + 8) * N + col) =
                make_float2(acc[mi][nf][2] + b0v, acc[mi][nf][3] + b1v);
        }
}

// ============ conv (implicit im2col) HMMA GEMM: K=1792, N=256 ================
__global__ __launch_bounds__(256) void conv_mma(
        const float* __restrict__ Z, const __nv_bfloat16* __restrict__ Bh,
        const __nv_bfloat16* __restrict__ Bl, const float* __restrict__ bias,
        float* __restrict__ C) {
    const int N = 256, K = 1792;
    extern __shared__ char sm[];
    char* pAh = sm;            char* pAl = sm + 16384;
    char* pBh = sm + 32768;    char* pBl = sm + 49152;
    const uint32_t sAh = smem_u32(pAh), sAl = smem_u32(pAl);
    const uint32_t sBh = smem_u32(pBh), sBl = smem_u32(pBl);
    const int tid = threadIdx.x, lane = tid & 31, w = tid >> 5;
    const int wm = w & 3, wn = w >> 2;
    const int bm = blockIdx.y << 7, bn = blockIdx.x << 7;
    float acc[2][8][4];
#pragma unroll
    for (int i = 0; i < 2; i++)
#pragma unroll
        for (int j = 0; j < 8; j++)
#pragma unroll
            for (int q = 0; q < 4; q++) acc[i][j][q] = 0.f;

    for (int k0 = 0; k0 < K; k0 += 64) {
        const int dt = (k0 >> 8) - 3;
        const int iio = k0 & 255;
#pragma unroll
        for (int j = 0; j < 8; j++) {
            int f = j * 256 + tid;
            int row = f >> 4, c4 = f & 15;
            int grow = bm + row;
            int t = (grow / VV) % TT;
            float4 v = make_float4(0.f, 0.f, 0.f, 0.f);
            int tt = t + dt;
            if (tt >= 0 && tt < TT)
                v = *(const float4*)(Z + ((size_t)grow + (size_t)dt * VV) * 256 + iio + (c4 << 2));
            uint32_t h0, l0, h1, l1;
            split2(v.x, v.y, h0, l0);
            split2(v.z, v.w, h1, l1);
            uint32_t off = row * 128 + (((c4 >> 1) ^ (row & 7)) << 4) + ((c4 & 1) << 3);
            *(uint2*)(pAh + off) = make_uint2(h0, h1);
            *(uint2*)(pAl + off) = make_uint2(l0, l1);
        }
        const __nv_bfloat16* Bhb = Bh + (size_t)bn * K + k0;
        const __nv_bfloat16* Blb = Bl + (size_t)bn * K + k0;
#pragma unroll
        for (int j = 0; j < 4; j++) {
            int f = j * 256 + tid;
            int row = f >> 3, ch = f & 7;
            uint32_t off = row * 128 + ((ch ^ (row & 7)) << 4);
            *(uint4*)(pBh + off) = *(const uint4*)((const char*)(Bhb + (size_t)row * K) + (ch << 4));
            *(uint4*)(pBl + off) = *(const uint4*)((const char*)(Blb + (size_t)row * K) + (ch << 4));
        }
        __syncthreads();
#pragma unroll
        for (int kk = 0; kk < 4; kk++) {
            uint32_t ah[2][4], al[2][4], bh[8][2], bl[8][2];
            const int arow = wm * 32 + (lane & 15);
            const uint32_t aoff = (uint32_t)(((kk * 2 + (lane >> 4)) ^ (lane & 7)) << 4);
#pragma unroll
            for (int mi = 0; mi < 2; mi++) {
                ldm4(ah[mi][0], ah[mi][1], ah[mi][2], ah[mi][3],
                     sAh + (arow + mi * 16) * 128 + aoff);
                ldm4(al[mi][0], al[mi][1], al[mi][2], al[mi][3],
                     sAl + (arow + mi * 16) * 128 + aoff);
            }
            const uint32_t boff = (uint32_t)(((kk * 2 + ((lane >> 3) & 1)) ^ (lane & 7)) << 4);
#pragma unroll
            for (int p = 0; p < 4; p++) {
                int brow = wn * 64 + p * 16 + ((lane & 16) >> 1) + (lane & 7);
                ldm4(bh[2*p][0], bh[2*p][1], bh[2*p+1][0], bh[2*p+1][1],
                     sBh + brow * 128 + boff);
                ldm4(bl[2*p][0], bl[2*p][1], bl[2*p+1][0], bl[2*p+1][1],
                     sBl + brow * 128 + boff);
            }
#pragma unroll
            for (int mi = 0; mi < 2; mi++)
#pragma unroll
                for (int nf = 0; nf < 8; nf++) {
                    mma16816(acc[mi][nf], ah[mi], bh[nf]);
                    mma16816(acc[mi][nf], ah[mi], bl[nf]);
                    mma16816(acc[mi][nf], al[mi], bh[nf]);
                }
        }
        __syncthreads();
    }
    const int gid = lane >> 2, tig = lane & 3;
#pragma unroll
    for (int mi = 0; mi < 2; mi++)
#pragma unroll
        for (int nf = 0; nf < 8; nf++) {
            int col = bn + wn * 64 + nf * 8 + tig * 2;
            float b0v = bias[col], b1v = bias[col + 1];
            int r0 = bm + wm * 32 + mi * 16 + gid;
            *(float2*)(C + (size_t)r0 * N + col) =
                make_float2(acc[mi][nf][0] + b0v, acc[mi][nf][1] + b1v);
            *(float2*)(C + (size_t)(r0 + 8) * N + col) =
                make_float2(acc[mi][nf][2] + b0v, acc[mi][nf][3] + b1v);
        }
}

// ------------------- weight transpose + bf16 split prep ---------------------
__global__ void wsplit(const float* __restrict__ W, __nv_bfloat16* __restrict__ H,
                       __nv_bfloat16* __restrict__ L, int K, int N) {
    int i = blockIdx.x * 256 + threadIdx.x;
    if (i >= K * N) return;
    int k = i / N, n = i % N;
    float v = W[i];
    __nv_bfloat16 h = __float2bfloat16(v);
    H[(size_t)n * K + k] = h;
    L[(size_t)n * K + k] = __float2bfloat16(v - __bfloat162float(h));
}
__global__ void wsplit_conv(const float* __restrict__ W, __nv_bfloat16* __restrict__ H,
                            __nv_bfloat16* __restrict__ L) {
    int i = blockIdx.x * 256 + threadIdx.x;
    if (i >= 256 * 1792) return;
    int o = i / 1792, r = i % 1792;
    int ii = r / 7, kw = r % 7;
    float v = W[i];
    __nv_bfloat16 h = __float2bfloat16(v);
    size_t dst = (size_t)o * 1792 + kw * 256 + ii;
    H[dst] = h;
    L[dst] = __float2bfloat16(v - __bfloat162float(h));
}

// --------- de-interleave spatial qk -> qT,kT [(n*3+s)*25+u][4096] -----------
__global__ void deint_s(const float* __restrict__ qk, float* __restrict__ qT,
                        float* __restrict__ kT) {
    size_t idx = (size_t)blockIdx.x * 256 + threadIdx.x;
    int col = (int)(idx % 384);
    size_t row = idx / 384;
    int t = (int)(row % TT);
    size_t nu = row / TT;
    int n = (int)(nu / VV), u = (int)(nu % VV);
    int ci = col / 6, r = col % 6;
    float v = qk[idx];
    int s = (r < 3) ? r : r - 3;
    size_t dst = (((size_t)(n * 3 + s) * VV + u) << 12) + t * 64 + ci;
    if (r < 3) qT[dst] = v; else kT[dst] = v;
}

// spatial attention
__global__ __launch_bounds__(128) void att_s_fast(
        const float* __restrict__ qT, const float* __restrict__ kT,
        const float* __restrict__ alphas, const float* __restrict__ att0,
        float* __restrict__ att) {
    int ns = blockIdx.x, n = ns / 3, s = ns % 3;
    __shared__ float qs[25][132], ks[25][132];
    const float* qb = qT + ((size_t)ns * VV << 12);
    const float* kb = kT + ((size_t)ns * VV << 12);
    int t = threadIdx.x;
    int u0 = (t / 25) * 5, v = t % 25;
    float acc[5] = {0.f, 0.f, 0.f, 0.f, 0.f};
    for (int kc = 0; kc < 4096; kc += 128) {
        for (int i = t; i < 25 * 128; i += 128) {
            int uu = i >> 7, e = i & 127;
            qs[uu][e] = qb[((size_t)uu << 12) + kc + e];
            ks[uu][e] = kb[((size_t)uu << 12) + kc + e];
        }
        __syncthreads();
        if (t < 125) {
#pragma unroll 4
            for (int e = 0; e < 128; e++) {
                float kv = ks[v][e];
                acc[0] = fmaf(qs[u0 + 0][e], kv, acc[0]);
                acc[1] = fmaf(qs[u0 + 1][e], kv, acc[1]);
                acc[2] = fmaf(qs[u0 + 2][e], kv, acc[2]);
                acc[3] = fmaf(qs[u0 + 3][e], kv, acc[3]);
                acc[4] = fmaf(qs[u0 + 4][e], kv, acc[4]);
            }
        }
        __syncthreads();
    }
    if (t < 125) {
        float al = alphas[s];
#pragma unroll
        for (int i = 0; i < 5; i++) {
            int u = u0 + i;
            att[((size_t)(n * VV + u) * VV + v) * 3 + s] =
                tanhf(acc[i] * (1.f / 4096.f)) * al + att0[((size_t)u * VV + v) * 3 + s];
        }
    }
}

// y_s: block per (n,t); x slice in smem read once
__global__ __launch_bounds__(256) void ys2(const float* __restrict__ x,
                                           const float* __restrict__ att,
                                           float* __restrict__ y) {
    __shared__ float xs[25][256];
    __shared__ float as_[25 * 25 * 3];
    int b = blockIdx.x;             // n*64 + t
    int n = b >> 6, t = b & 63;
    int tid = threadIdx.x;
    for (int i = tid; i < 25 * 256; i += 256) {
        int u = i >> 8, c = i & 255;
        xs[u][c] = x[((size_t)(n * VV + u) * TT + t) * 256 + c];
    }
    for (int i = tid; i < 1875; i += 256) as_[i] = att[(size_t)n * 1875 + i];
    __syncthreads();
    int c = tid;
#pragma unroll 1
    for (int v = 0; v < VV; v++) {
        float a0 = 0.f, a1 = 0.f, a2 = 0.f;
#pragma unroll
        for (int u = 0; u < VV; u++) {
            float xv = xs[u][c];
            a0 = fmaf(xv, as_[(u * VV + v) * 3 + 0], a0);
            a1 = fmaf(xv, as_[(u * VV + v) * 3 + 1], a1);
            a2 = fmaf(xv, as_[(u * VV + v) * 3 + 2], a2);
        }
        float* yp = y + ((size_t)(n * VV + v) * TT + t) * 768 + c * 3;
        yp[0] = a0; yp[1] = a1; yp[2] = a2;
    }
}

// LN over group + residual + gelu
__global__ void ln_kernel(const float* __restrict__ h, const float* __restrict__ res,
                          const float* __restrict__ g, const float* __restrict__ b,
                          float* __restrict__ out, int G, int mode) {
    int grp = blockIdx.x;
    const float* hp = h + (size_t)grp * G;
    const float* rp = res + (size_t)grp * G;
    float s = 0.f, sq = 0.f;
    for (int i = threadIdx.x; i < G; i += blockDim.x) {
        float v = hp[i]; s += v; sq = fmaf(v, v, sq);
    }
    for (int o = 16; o; o >>= 1) {
        s += __shfl_down_sync(0xffffffffu, s, o);
        sq += __shfl_down_sync(0xffffffffu, sq, o);
    }
    __shared__ float ss[8], sqs[8];
    __shared__ float mean_s, inv_s;
    int w = threadIdx.x >> 5;
    if ((threadIdx.x & 31) == 0) { ss[w] = s; sqs[w] = sq; }
    __syncthreads();
    if (threadIdx.x == 0) {
        float S = 0.f, Q = 0.f;
        for (int i = 0; i < 8; i++) { S += ss[i]; Q += sqs[i]; }
        float mean = S / G;
        float var = Q / G - mean * mean;
        mean_s = mean; inv_s = rsqrtf(var + 1e-5f);
    }
    __syncthreads();
    float mean = mean_s, inv = inv_s;
    if (mode == 0) {
        float* op = out + (size_t)grp * G;
        for (int i = threadIdx.x; i < G; i += blockDim.x)
            op[i] = gelu_f(rp[i] + fmaf((hp[i] - mean) * inv, g[i], b[i]));
    } else {
        int n = grp / VV, v = grp % VV;
        for (int i = threadIdx.x; i < G; i += blockDim.x) {
            int t = i >> 8, c = i & 255;
            out[((size_t)(n * TT + t) * VV + v) * 256 + c] =
                gelu_f(rp[i] + fmaf((hp[i] - mean) * inv, g[i], b[i]));
        }
    }
}

// --------- de-interleave temporal qkt -> qd,kd [(n*4+m)][t][1600] -----------
__global__ void deint_t(const float* __restrict__ qkt, float* __restrict__ qd,
                        float* __restrict__ kd) {
    size_t idx = (size_t)blockIdx.x * 256 + threadIdx.x;
    int col = (int)(idx & 511);
    size_t row = idx >> 9;
    int v = (int)(row % VV);
    size_t nt = row / VV;
    int t = (int)(nt % TT), n = (int)(nt / TT);
    int ci = col >> 3, j = col & 7;
    float val = qkt[idx];
    int m = (j < 4) ? j : j - 4;
    size_t dst = ((size_t)(n * 4 + m) * TT + t) * 1600 + v * 64 + ci;
    if (j < 4) qd[dst] = val; else kd[dst] = val;
}

// temporal attention -> TRANSPOSED layout att[n][q][t][s]
__global__ __launch_bounds__(256) void att_t_fast(
        const float* __restrict__ qd, const float* __restrict__ kd,
        const float* __restrict__ alf, const float* __restrict__ alb,
        float* __restrict__ attf, float* __restrict__ attb) {
    int nm = blockIdx.x, n = nm >> 2, m = nm & 3;
    int s = m & 1, dir = m >> 1;
    __shared__ float Qs[64][68], Ks[64][68];
    const float* qb = qd + (size_t)nm * TT * 1600;
    const float* kb = kd + (size_t)nm * TT * 1600;
    const int tid = threadIdx.x;
    const int tx = tid & 15, ty = tid >> 4;
    const int lr = tid >> 2, lc = (tid & 3) << 4;
    float acc[4][4] = {};
    for (int kc = 0; kc < 1600; kc += 64) {
#pragma unroll
        for (int j = 0; j < 4; j++) {
            float4 q4 = *(const float4*)(qb + (size_t)lr * 1600 + kc + lc + j * 4);
            float4 k4 = *(const float4*)(kb + (size_t)lr * 1600 + kc + lc + j * 4);
            Qs[lc + j*4 + 0][lr] = q4.x; Qs[lc + j*4 + 1][lr] = q4.y;
            Qs[lc + j*4 + 2][lr] = q4.z; Qs[lc + j*4 + 3][lr] = q4.w;
            Ks[lc + j*4 + 0][lr] = k4.x; Ks[lc + j*4 + 1][lr] = k4.y;
            Ks[lc + j*4 + 2][lr] = k4.z; Ks[lc + j*4 + 3][lr] = k4.w;
        }
        __syncthreads();
#pragma unroll 8
        for (int kk = 0; kk < 64; kk++) {
            float4 aq = *(const float4*)(&Qs[kk][ty << 2]);
            float4 bk = *(const float4*)(&Ks[kk][tx << 2]);
            float a[4] = {aq.x, aq.y, aq.z, aq.w};
            float b[4] = {bk.x, bk.y, bk.z, bk.w};
#pragma unroll
            for (int i = 0; i < 4; i++)
#pragma unroll
                for (int j = 0; j < 4; j++) acc[i][j] = fmaf(a[i], b[j], acc[i][j]);
        }
        __syncthreads();
    }
    float al = dir ? alb[s] : alf[s];
#pragma unroll
    for (int i = 0; i < 4; i++) {
#pragma unroll
        for (int j = 0; j < 4; j++) {
            int t_ = (ty << 2) + i, q_ = (tx << 2) + j;
            float val = tanhf(acc[i][j] * (1.f / 1600.f)) * al;
            size_t idx = ((size_t)(n * TT + q_) * TT + t_) * 2 + s;   // [n][q][t][s]
            if (dir == 0) attf[idx] = (q_ <= t_) ? val : 0.f;
            else          attb[idx] = (q_ >= t_) ? val : 0.f;
        }
    }
}

// z apply: block per (n,v); y2 slice in smem read once
__global__ __launch_bounds__(256) void z2k(const float* __restrict__ y2t,
                                           const float* __restrict__ attf,
                                           const float* __restrict__ attb,
                                           float* __restrict__ z) {
    extern __shared__ float zs[];          // 64*256 + 256
    float* ys = zs;
    float* as_ = zs + 64 * 256;
    int b = blockIdx.x;                    // n*25 + v
    int n = b / VV, v = b % VV;
    int tid = threadIdx.x;
    for (int i = tid; i < 64 * 256; i += 256) {
        int t = i >> 8, c = i & 255;
        ys[t * 256 + c] = y2t[((size_t)(n * TT + t) * VV + v) * 256 + c];
    }
    __syncthreads();
    int c = tid;
    for (int q = 0; q < TT; q++) {
        if (tid < 128) as_[tid] = attf[(size_t)n * 8192 + q * 128 + tid];
        else           as_[tid] = attb[(size_t)n * 8192 + q * 128 + (tid - 128)];
        __syncthreads();
        float f0 = 0.f, f1 = 0.f, b0 = 0.f, b1 = 0.f;
#pragma unroll 8
        for (int t = 0; t < TT; t++) {
            float yv = ys[t * 256 + c];
            f0 = fmaf(yv, as_[t * 2], f0);       f1 = fmaf(yv, as_[t * 2 + 1], f1);
            b0 = fmaf(yv, as_[128 + t * 2], b0); b1 = fmaf(yv, as_[128 + t * 2 + 1], b1);
        }
        float* zp = z + ((size_t)(n * TT + q) * VV + v) * 1024;
        zp[c * 2] = f0; zp[c * 2 + 1] = f1;
        zp[512 + c * 2] = b0; zp[512 + c * 2 + 1] = b1;
        __syncthreads();
    }
}

__global__ void final_kernel(const float* __restrict__ z2, const float* __restrict__ cv,
                             const float* __restrict__ bn_g, const float* __restrict__ bn_b,
                             const float* __restrict__ bn_m, const float* __restrict__ bn_v,
                             float* __restrict__ out) {
    size_t i = (size_t)blockIdx.x * 256 + threadIdx.x;
    int o = (int)(i & 255);
    size_t r = i >> 8;
    int v = (int)(r % VV);
    size_t r2 = r / VV;
    int t = (int)(r2 % TT);
    int n = (int)(r2 / TT);
    float c1 = fmaf((cv[i] - bn_m[o]) * rsqrtf(bn_v[o] + 1e-5f), bn_g[o], bn_b[o]);
    out[((size_t)(n * VV + v) * TT + t) * 256 + o] = gelu_f(z2[i] + c1);
}

// ------------------------------- launcher -----------------------------------
extern "C" void kernel_launch(void* const* d_in, const int* in_sizes, int n_in,
                              void* d_out, int out_size) {
    const float* x       = (const float*)d_in[0];
    const float* Wqk_s   = (const float*)d_in[1];
    const float* bqk_s   = (const float*)d_in[2];
    const float* alphas  = (const float*)d_in[3];
    const float* att0s   = (const float*)d_in[4];
    const float* Wo_s    = (const float*)d_in[5];
    const float* bo_s    = (const float*)d_in[6];
    const float* g_os    = (const float*)d_in[7];
    const float* b_os    = (const float*)d_in[8];
    const float* Wff_s   = (const float*)d_in[9];
    const float* bff_s   = (const float*)d_in[10];
    const float* g_ffs   = (const float*)d_in[11];
    const float* b_ffs   = (const float*)d_in[12];
    const float* Wqk_t   = (const float*)d_in[13];
    const float* bqk_t   = (const float*)d_in[14];
    const float* alphat_f= (const float*)d_in[15];
    const float* alphat_b= (const float*)d_in[16];
    const float* Wo_t    = (const float*)d_in[17];
    const float* bo_t    = (const float*)d_in[18];
    const float* g_ot    = (const float*)d_in[19];
    const float* b_ot    = (const float*)d_in[20];
    const float* Wff_t   = (const float*)d_in[21];
    const float* bff_t   = (const float*)d_in[22];
    const float* g_fft   = (const float*)d_in[23];
    const float* b_fft   = (const float*)d_in[24];
    const float* conv_w  = (const float*)d_in[25];
    const float* conv_b  = (const float*)d_in[26];
    const float* bn_g    = (const float*)d_in[27];
    const float* bn_b    = (const float*)d_in[28];
    const float* bn_m    = (const float*)d_in[29];
    const float* bn_v    = (const float*)d_in[30];
    float* out = (float*)d_out;

    void *pA, *pB, *pH, *pY1, *pY2, *pZ2, *pAS, *pAF, *pAB, *pWH, *pWL;
    cudaGetSymbolAddress(&pA,  g_bufA);
    cudaGetSymbolAddress(&pB,  g_bufB);
    cudaGetSymbolAddress(&pH,  g_h);
    cudaGetSymbolAddress(&pY1, g_y1);
    cudaGetSymbolAddress(&pY2, g_y2);
    cudaGetSymbolAddress(&pZ2, g_z2);
    cudaGetSymbolAddress(&pAS, g_atts);
    cudaGetSymbolAddress(&pAF, g_attf);
    cudaGetSymbolAddress(&pAB, g_attb);
    cudaGetSymbolAddress(&pWH, g_wh);
    cudaGetSymbolAddress(&pWL, g_wl);
    float* bufA = (float*)pA;  float* bufB = (float*)pB;
    float* h    = (float*)pH;  float* y1   = (float*)pY1;
    float* y2   = (float*)pY2; float* z2b  = (float*)pZ2;
    float* atts = (float*)pAS; float* attf = (float*)pAF;
    float* attb = (float*)pAB;
    __nv_bfloat16* wh = (__nv_bfloat16*)pWH;
    __nv_bfloat16* wl = (__nv_bfloat16*)pWL;

    cudaFuncSetAttribute(gemm_mma, cudaFuncAttributeMaxDynamicSharedMemorySize, GSM);
    cudaFuncSetAttribute(conv_mma, cudaFuncAttributeMaxDynamicSharedMemorySize, GSM);
    cudaFuncSetAttribute(z2k, cudaFuncAttributeMaxDynamicSharedMemorySize, (64*256 + 256) * 4);

    dim3 blk(256);
    const int MB = RTOT / 128;   // 400

    // weight prep (bf16 split, transposed to [N][K])
    wsplit<<<(256*384 + 255)/256, blk>>>(Wqk_s, wh + OFF_QKS, wl + OFF_QKS, 256, 384);
    wsplit<<<(768*256 + 255)/256, blk>>>(Wo_s,  wh + OFF_WOS, wl + OFF_WOS, 768, 256);
    wsplit<<<(256*256 + 255)/256, blk>>>(Wff_s, wh + OFF_FFS, wl + OFF_FFS, 256, 256);
    wsplit<<<(256*512 + 255)/256, blk>>>(Wqk_t, wh + OFF_QKT, wl + OFF_QKT, 256, 512);
    wsplit<<<(1024*256 + 255)/256, blk>>>(Wo_t, wh + OFF_WOT, wl + OFF_WOT, 1024, 256);
    wsplit<<<(256*256 + 255)/256, blk>>>(Wff_t, wh + OFF_FFT, wl + OFF_FFT, 256, 256);
    wsplit_conv<<<(256*1792 + 255)/256, blk>>>(conv_w, wh + OFF_CNV, wl + OFF_CNV);

    // Stage 1: spatial
    gemm_mma<<<dim3(3, MB), blk, GSM>>>(x, wh + OFF_QKS, wl + OFF_QKS, bqk_s, bufB, RTOT, 384, 256);
    deint_s<<<RTOT * 384 / 256, blk>>>(bufB, h, y1);
    att_s_fast<<<NN * 3, 128>>>(h, y1, alphas, att0s, atts);
    ys2<<<NN * TT, blk>>>(x, atts, bufA);
    gemm_mma<<<dim3(2, MB), blk, GSM>>>(bufA, wh + OFF_WOS, wl + OFF_WOS, bo_s, h, RTOT, 256, 768);
    ln_kernel<<<NN*VV, blk>>>(h, x, g_os, b_os, y1, TT*256, 0);
    gemm_mma<<<dim3(2, MB), blk, GSM>>>(y1, wh + OFF_FFS, wl + OFF_FFS, bff_s, h, RTOT, 256, 256);
    ln_kernel<<<NN*VV, blk>>>(h, x, g_ffs, b_ffs, y2, TT*256, 1);

    // Stage 2: temporal
    gemm_mma<<<dim3(4, MB), blk, GSM>>>(y2, wh + OFF_QKT, wl + OFF_QKT, bqk_t, bufB, RTOT, 512, 256);
    deint_t<<<RTOT * 512 / 256, blk>>>(bufB, h, y1);
    att_t_fast<<<NN * 4, blk>>>(h, y1, alphat_f, alphat_b, attf, attb);
    z2k<<<NN * VV, blk, (64*256 + 256) * 4>>>(y2, attf, attb, bufA);
    gemm_mma<<<dim3(2, MB), blk, GSM>>>(bufA, wh + OFF_WOT, wl + OFF_WOT, bo_t, h, RTOT, 256, 1024);
    ln_kernel<<<NN*TT, blk>>>(h, y2, g_ot, b_ot, y1, VV*256, 0);
    gemm_mma<<<dim3(2, MB), blk, GSM>>>(y1, wh + OFF_FFT, wl + OFF_FFT, bff_t, h, RTOT, 256, 256);
    ln_kernel<<<NN*TT, blk>>>(h, y2, g_fft, b_fft, z2b, VV*256, 0);

    // Stage 3: conv + BN + gelu + transpose
    conv_mma<<<dim3(2, MB), blk, GSM>>>(z2b, wh + OFF_CNV, wl + OFF_CNV, conv_b, h);
    final_kernel<<<RTOT, blk>>>(z2b, h, bn_g, bn_b, bn_m, bn_v, out);
}

// round 6
// speedup vs baseline: 2.5201x; 1.0706x over previous
#include <cuda_runtime.h>
#include <cuda_bf16.h>
#include <math.h>
#include <stdint.h>

#define NN 32
#define VV 25
#define TT 64
#define RTOT (NN*VV*TT)   /* 51200 */

// ------------------------- scratch (device globals) -------------------------
__device__ float g_bufB[(size_t)RTOT * 512];
__device__ float g_h   [(size_t)RTOT * 256];
__device__ float g_y1  [(size_t)RTOT * 256];
__device__ float g_y2  [(size_t)RTOT * 256];
__device__ float g_z2  [(size_t)RTOT * 256];
__device__ float g_atts[NN*VV*VV*3];
__device__ float g_attf[NN*TT*TT*2];   // transposed layout [n][q][t][s]
__device__ float g_attb[NN*TT*TT*2];
// bf16 split activation buffers (16B-aligned for cp.async)
__device__ __align__(128) __nv_bfloat16 g_ah [(size_t)RTOT * 1024];
__device__ __align__(128) __nv_bfloat16 g_al [(size_t)RTOT * 1024];
__device__ __align__(128) __nv_bfloat16 g_xh [(size_t)RTOT * 256];
__device__ __align__(128) __nv_bfloat16 g_xl [(size_t)RTOT * 256];
__device__ __align__(128) __nv_bfloat16 g_y1h[(size_t)RTOT * 256];
__device__ __align__(128) __nv_bfloat16 g_y1l[(size_t)RTOT * 256];
__device__ __align__(128) __nv_bfloat16 g_y2h[(size_t)RTOT * 256];
__device__ __align__(128) __nv_bfloat16 g_y2l[(size_t)RTOT * 256];
__device__ __align__(128) __nv_bfloat16 g_z2h[(size_t)RTOT * 256];
__device__ __align__(128) __nv_bfloat16 g_z2l[(size_t)RTOT * 256];
#define WTOT 1277952
__device__ __align__(128) __nv_bfloat16 g_wh[WTOT];
__device__ __align__(128) __nv_bfloat16 g_wl[WTOT];
#define OFF_QKS 0         /* K=256  N=384  */
#define OFF_WOS 98304     /* K=768  N=256  */
#define OFF_FFS 294912    /* K=256  N=256  */
#define OFF_QKT 360448    /* K=256  N=512  */
#define OFF_WOT 491520    /* K=1024 N=256  */
#define OFF_FFT 753664    /* K=256  N=256  */
#define OFF_CNV 819200    /* K=1792 N=256  */

__device__ __forceinline__ float gelu_f(float x) {
    return 0.5f * x * (1.0f + erff(x * 0.7071067811865475f));
}
__device__ __forceinline__ void split2(float a, float b, uint32_t &hi, uint32_t &lo) {
    __nv_bfloat16 ha = __float2bfloat16(a), hb = __float2bfloat16(b);
    float la = a - __bfloat162float(ha), lb = b - __bfloat162float(hb);
    __nv_bfloat16 l1 = __float2bfloat16(la), l2 = __float2bfloat16(lb);
    hi = (uint32_t)__bfloat16_as_ushort(ha) | ((uint32_t)__bfloat16_as_ushort(hb) << 16);
    lo = (uint32_t)__bfloat16_as_ushort(l1) | ((uint32_t)__bfloat16_as_ushort(l2) << 16);
}
__device__ __forceinline__ uint32_t smem_u32(const void* p) {
    uint32_t a;
    asm("{ .reg .u64 t; cvta.to.shared.u64 t, %1; cvt.u32.u64 %0, t; }" : "=r"(a) : "l"(p));
    return a;
}
__device__ __forceinline__ void ldm4(uint32_t &r0, uint32_t &r1, uint32_t &r2,
                                     uint32_t &r3, uint32_t a) {
    asm volatile("ldmatrix.sync.aligned.m8n8.x4.shared.b16 {%0,%1,%2,%3}, [%4];"
        : "=r"(r0), "=r"(r1), "=r"(r2), "=r"(r3) : "r"(a));
}
__device__ __forceinline__ void mma16816(float* c, const uint32_t* a, const uint32_t* b) {
    asm volatile(
        "mma.sync.aligned.m16n8k16.row.col.f32.bf16.bf16.f32 "
        "{%0,%1,%2,%3}, {%4,%5,%6,%7}, {%8,%9}, {%0,%1,%2,%3};"
        : "+f"(c[0]), "+f"(c[1]), "+f"(c[2]), "+f"(c[3])
        : "r"(a[0]), "r"(a[1]), "r"(a[2]), "r"(a[3]), "r"(b[0]), "r"(b[1]));
}
__device__ __forceinline__ void cpa16(uint32_t dst, const void* src) {
    asm volatile("cp.async.cg.shared.global [%0], [%1], 16;" :: "r"(dst), "l"(src));
}
__device__ __forceinline__ void cpa16z(uint32_t dst, const void* src, int sz) {
    asm volatile("cp.async.cg.shared.global [%0], [%1], 16, %2;" :: "r"(dst), "l"(src), "r"(sz));
}
#define CPA_COMMIT() asm volatile("cp.async.commit_group;" ::: "memory")
#define CPA_WAIT1() asm volatile("cp.async.wait_group 1;" ::: "memory")
#define CPA_WAIT0() asm volatile("cp.async.wait_group 0;" ::: "memory")

// ================= HMMA GEMM, cp.async 2-stage pipeline ======================
// C[M,N] = (Ah+Al)[M,K] @ (Bh+Bl)[K,N] + bias; A,B bf16 split; B stored [N][K].
// smem/stage 64KB: Ah(16K) Al(16K) Bh(16K) Bl(16K); rows of 64 bf16 = 128B,
// 16B-chunk XOR swizzle: chunk ch of row r at (ch ^ (r&7))*16.
#define GSM (2*65536)
__global__ __launch_bounds__(256) void gemm_mma2(
        const __nv_bfloat16* __restrict__ Ah, const __nv_bfloat16* __restrict__ Al,
        const __nv_bfloat16* __restrict__ Bh, const __nv_bfloat16* __restrict__ Bl,
        const float* __restrict__ bias, float* __restrict__ C, int M, int N, int K) {
    extern __shared__ char sm[];
    const uint32_t sbase = smem_u32(sm);
    const int tid = threadIdx.x, lane = tid & 31, w = tid >> 5;
    const int wm = w & 3, wn = w >> 2;
    const int bm = blockIdx.y << 7, bn = blockIdx.x << 7;
    float acc[2][8][4];
#pragma unroll
    for (int i = 0; i < 2; i++)
#pragma unroll
        for (int j = 0; j < 8; j++)
#pragma unroll
            for (int q = 0; q < 4; q++) acc[i][j][q] = 0.f;
    const int nch = K >> 6;

    auto load_stage = [&](int c, int s) {
        uint32_t st = sbase + s * 65536;
        const int k0 = c << 6;
#pragma unroll
        for (int j = 0; j < 4; j++) {
            int f = j * 256 + tid;
            int row = f >> 3, ch = f & 7;
            uint32_t off = row * 128 + ((ch ^ (row & 7)) << 4);
            cpa16(st + off,         Ah + (size_t)(bm + row) * K + k0 + ch * 8);
            cpa16(st + 16384 + off, Al + (size_t)(bm + row) * K + k0 + ch * 8);
            cpa16(st + 32768 + off, Bh + (size_t)(bn + row) * K + k0 + ch * 8);
            cpa16(st + 49152 + off, Bl + (size_t)(bn + row) * K + k0 + ch * 8);
        }
        CPA_COMMIT();
    };
    load_stage(0, 0);
    for (int c = 0; c < nch; c++) {
        const int s = c & 1;
        if (c + 1 < nch) { load_stage(c + 1, s ^ 1); CPA_WAIT1(); }
        else             { CPA_WAIT0(); }
        __syncthreads();
        const uint32_t sAh = sbase + s * 65536;
        const uint32_t sAl = sAh + 16384, sBh = sAh + 32768, sBl = sAh + 49152;
#pragma unroll
        for (int kk = 0; kk < 4; kk++) {
            uint32_t ah[2][4], al[2][4], bh[8][2], bl[8][2];
            const int arow = wm * 32 + (lane & 15);
            const uint32_t aoff = (uint32_t)(((kk * 2 + (lane >> 4)) ^ (lane & 7)) << 4);
#pragma unroll
            for (int mi = 0; mi < 2; mi++) {
                ldm4(ah[mi][0], ah[mi][1], ah[mi][2], ah[mi][3],
                     sAh + (arow + mi * 16) * 128 + aoff);
                ldm4(al[mi][0], al[mi][1], al[mi][2], al[mi][3],
                     sAl + (arow + mi * 16) * 128 + aoff);
            }
            const uint32_t boff = (uint32_t)(((kk * 2 + ((lane >> 3) & 1)) ^ (lane & 7)) << 4);
#pragma unroll
            for (int p = 0; p < 4; p++) {
                int brow = wn * 64 + p * 16 + ((lane & 16) >> 1) + (lane & 7);
                ldm4(bh[2*p][0], bh[2*p][1], bh[2*p+1][0], bh[2*p+1][1],
                     sBh + brow * 128 + boff);
                ldm4(bl[2*p][0], bl[2*p][1], bl[2*p+1][0], bl[2*p+1][1],
                     sBl + brow * 128 + boff);
            }
#pragma unroll
            for (int mi = 0; mi < 2; mi++)
#pragma unroll
                for (int nf = 0; nf < 8; nf++) {
                    mma16816(acc[mi][nf], ah[mi], bh[nf]);
                    mma16816(acc[mi][nf], ah[mi], bl[nf]);
                    mma16816(acc[mi][nf], al[mi], bh[nf]);
                }
        }
        __syncthreads();
    }
    const int gid = lane >> 2, tig = lane & 3;
#pragma unroll
    for (int mi = 0; mi < 2; mi++)
#pragma unroll
        for (int nf = 0; nf < 8; nf++) {
            int col = bn + wn * 64 + nf * 8 + tig * 2;
            float b0v = bias[col], b1v = bias[col + 1];
            int r0 = bm + wm * 32 + mi * 16 + gid;
            *(float2*)(C + (size_t)r0 * N + col) =
                make_float2(acc[mi][nf][0] + b0v, acc[mi][nf][1] + b1v);
            *(float2*)(C + (size_t)(r0 + 8) * N + col) =
                make_float2(acc[mi][nf][2] + b0v, acc[mi][nf][3] + b1v);
        }
}

// ========= conv (implicit im2col) pipelined HMMA: K=1792, N=256 ==============
__global__ __launch_bounds__(256) void conv_mma2(
        const __nv_bfloat16* __restrict__ Zh, const __nv_bfloat16* __restrict__ Zl,
        const __nv_bfloat16* __restrict__ Bh, const __nv_bfloat16* __restrict__ Bl,
        const float* __restrict__ bias, float* __restrict__ C) {
    const int N = 256, K = 1792;
    extern __shared__ char sm[];
    const uint32_t sbase = smem_u32(sm);
    const int tid = threadIdx.x, lane = tid & 31, w = tid >> 5;
    const int wm = w & 3, wn = w >> 2;
    const int bm = blockIdx.y << 7, bn = blockIdx.x << 7;
    float acc[2][8][4];
#pragma unroll
    for (int i = 0; i < 2; i++)
#pragma unroll
        for (int j = 0; j < 8; j++)
#pragma unroll
            for (int q = 0; q < 4; q++) acc[i][j][q] = 0.f;
    const int nch = K >> 6;   // 28

    auto load_stage = [&](int c, int s) {
        uint32_t st = sbase + s * 65536;
        const int k0 = c << 6;
        const int dt = (k0 >> 8) - 3;
        const int iio = k0 & 255;
#pragma unroll
        for (int j = 0; j < 4; j++) {
            int f = j * 256 + tid;
            int row = f >> 3, ch = f & 7;
            uint32_t off = row * 128 + ((ch ^ (row & 7)) << 4);
            int grow = bm + row;
            int t = (grow / VV) % TT;
            int tt = t + dt;
            int ok = (tt >= 0 && tt < TT);
            size_t srcoff = ok ? ((size_t)grow + (size_t)dt * VV) * 256 + iio + ch * 8 : 0;
            cpa16z(st + off,         Zh + srcoff, ok ? 16 : 0);
            cpa16z(st + 16384 + off, Zl + srcoff, ok ? 16 : 0);
            cpa16(st + 32768 + off,  Bh + (size_t)(bn + row) * K + k0 + ch * 8);
            cpa16(st + 49152 + off,  Bl + (size_t)(bn + row) * K + k0 + ch * 8);
        }
        CPA_COMMIT();
    };
    load_stage(0, 0);
    for (int c = 0; c < nch; c++) {
        const int s = c & 1;
        if (c + 1 < nch) { load_stage(c + 1, s ^ 1); CPA_WAIT1(); }
        else             { CPA_WAIT0(); }
        __syncthreads();
        const uint32_t sAh = sbase + s * 65536;
        const uint32_t sAl = sAh + 16384, sBh = sAh + 32768, sBl = sAh + 49152;
#pragma unroll
        for (int kk = 0; kk < 4; kk++) {
            uint32_t ah[2][4], al[2][4], bh[8][2], bl[8][2];
            const int arow = wm * 32 + (lane & 15);
            const uint32_t aoff = (uint32_t)(((kk * 2 + (lane >> 4)) ^ (lane & 7)) << 4);
#pragma unroll
            for (int mi = 0; mi < 2; mi++) {
                ldm4(ah[mi][0], ah[mi][1], ah[mi][2], ah[mi][3],
                     sAh + (arow + mi * 16) * 128 + aoff);
                ldm4(al[mi][0], al[mi][1], al[mi][2], al[mi][3],
                     sAl + (arow + mi * 16) * 128 + aoff);
            }
            const uint32_t boff = (uint32_t)(((kk * 2 + ((lane >> 3) & 1)) ^ (lane & 7)) << 4);
#pragma unroll
            for (int p = 0; p < 4; p++) {
                int brow = wn * 64 + p * 16 + ((lane & 16) >> 1) + (lane & 7);
                ldm4(bh[2*p][0], bh[2*p][1], bh[2*p+1][0], bh[2*p+1][1],
                     sBh + brow * 128 + boff);
                ldm4(bl[2*p][0], bl[2*p][1], bl[2*p+1][0], bl[2*p+1][1],
                     sBl + brow * 128 + boff);
            }
#pragma unroll
            for (int mi = 0; mi < 2; mi++)
#pragma unroll
                for (int nf = 0; nf < 8; nf++) {
                    mma16816(acc[mi][nf], ah[mi], bh[nf]);
                    mma16816(acc[mi][nf], ah[mi], bl[nf]);
                    mma16816(acc[mi][nf], al[mi], bh[nf]);
                }
        }
        __syncthreads();
    }
    const int gid = lane >> 2, tig = lane & 3;
#pragma unroll
    for (int mi = 0; mi < 2; mi++)
#pragma unroll
        for (int nf = 0; nf < 8; nf++) {
            int col = bn + wn * 64 + nf * 8 + tig * 2;
            float b0v = bias[col], b1v = bias[col + 1];
            int r0 = bm + wm * 32 + mi * 16 + gid;
            *(float2*)(C + (size_t)r0 * N + col) =
                make_float2(acc[mi][nf][0] + b0v, acc[mi][nf][1] + b1v);
            *(float2*)(C + (size_t)(r0 + 8) * N + col) =
                make_float2(acc[mi][nf][2] + b0v, acc[mi][nf][3] + b1v);
        }
}

// ------------------- weight transpose + bf16 split prep ---------------------
__global__ void wsplit(const float* __restrict__ W, __nv_bfloat16* __restrict__ H,
                       __nv_bfloat16* __restrict__ L, int K, int N) {
    int i = blockIdx.x * 256 + threadIdx.x;
    if (i >= K * N) return;
    int k = i / N, n = i % N;
    float v = W[i];
    __nv_bfloat16 h = __float2bfloat16(v);
    H[(size_t)n * K + k] = h;
    L[(size_t)n * K + k] = __float2bfloat16(v - __bfloat162float(h));
}
__global__ void wsplit_conv(const float* __restrict__ W, __nv_bfloat16* __restrict__ H,
                            __nv_bfloat16* __restrict__ L) {
    int i = blockIdx.x * 256 + threadIdx.x;
    if (i >= 256 * 1792) return;
    int o = i / 1792, r = i % 1792;
    int ii = r / 7, kw = r % 7;
    float v = W[i];
    __nv_bfloat16 h = __float2bfloat16(v);
    size_t dst = (size_t)o * 1792 + kw * 256 + ii;
    H[dst] = h;
    L[dst] = __float2bfloat16(v - __bfloat162float(h));
}

// activation split: fp32 -> bf16 hi/lo (vectorized)
__global__ void xsplit(const float* __restrict__ X, __nv_bfloat16* __restrict__ H,
                       __nv_bfloat16* __restrict__ L) {
    size_t i = ((size_t)blockIdx.x * 256 + threadIdx.x) * 4;
    float4 v = *(const float4*)(X + i);
    uint32_t h0, l0, h1, l1;
    split2(v.x, v.y, h0, l0);
    split2(v.z, v.w, h1, l1);
    *(uint2*)(H + i) = make_uint2(h0, h1);
    *(uint2*)(L + i) = make_uint2(l0, l1);
}

// --------- de-interleave spatial qk -> qT,kT [(n*3+s)*25+u][4096] -----------
__global__ void deint_s(const float* __restrict__ qk, float* __restrict__ qT,
                        float* __restrict__ kT) {
    size_t idx = (size_t)blockIdx.x * 256 + threadIdx.x;
    int col = (int)(idx % 384);
    size_t row = idx / 384;
    int t = (int)(row % TT);
    size_t nu = row / TT;
    int n = (int)(nu / VV), u = (int)(nu % VV);
    int ci = col / 6, r = col % 6;
    float v = qk[idx];
    int s = (r < 3) ? r : r - 3;
    size_t dst = (((size_t)(n * 3 + s) * VV + u) << 12) + t * 64 + ci;
    if (r < 3) qT[dst] = v; else kT[dst] = v;
}

// spatial attention
__global__ __launch_bounds__(128) void att_s_fast(
        const float* __restrict__ qT, const float* __restrict__ kT,
        const float* __restrict__ alphas, const float* __restrict__ att0,
        float* __restrict__ att) {
    int ns = blockIdx.x, n = ns / 3, s = ns % 3;
    __shared__ float qs[25][132], ks[25][132];
    const float* qb = qT + ((size_t)ns * VV << 12);
    const float* kb = kT + ((size_t)ns * VV << 12);
    int t = threadIdx.x;
    int u0 = (t / 25) * 5, v = t % 25;
    float acc[5] = {0.f, 0.f, 0.f, 0.f, 0.f};
    for (int kc = 0; kc < 4096; kc += 128) {
        for (int i = t; i < 25 * 128; i += 128) {
            int uu = i >> 7, e = i & 127;
            qs[uu][e] = qb[((size_t)uu << 12) + kc + e];
            ks[uu][e] = kb[((size_t)uu << 12) + kc + e];
        }
        __syncthreads();
        if (t < 125) {
#pragma unroll 4
            for (int e = 0; e < 128; e++) {
                float kv = ks[v][e];
                acc[0] = fmaf(qs[u0 + 0][e], kv, acc[0]);
                acc[1] = fmaf(qs[u0 + 1][e], kv, acc[1]);
                acc[2] = fmaf(qs[u0 + 2][e], kv, acc[2]);
                acc[3] = fmaf(qs[u0 + 3][e], kv, acc[3]);
                acc[4] = fmaf(qs[u0 + 4][e], kv, acc[4]);
            }
        }
        __syncthreads();
    }
    if (t < 125) {
        float al = alphas[s];
#pragma unroll
        for (int i = 0; i < 5; i++) {
            int u = u0 + i;
            att[((size_t)(n * VV + u) * VV + v) * 3 + s] =
                tanhf(acc[i] * (1.f / 4096.f)) * al + att0[((size_t)u * VV + v) * 3 + s];
        }
    }
}

// y_s: block per (n,t); x slice in smem; bf16 split output (768-wide)
__global__ __launch_bounds__(256) void ys2(const float* __restrict__ x,
                                           const float* __restrict__ att,
                                           __nv_bfloat16* __restrict__ yh,
                                           __nv_bfloat16* __restrict__ yl) {
    __shared__ float xs[25][256];
    __shared__ float as_[25 * 25 * 3];
    int b = blockIdx.x;             // n*64 + t
    int n = b >> 6, t = b & 63;
    int tid = threadIdx.x;
    for (int i = tid; i < 25 * 256; i += 256) {
        int u = i >> 8, c = i & 255;
        xs[u][c] = x[((size_t)(n * VV + u) * TT + t) * 256 + c];
    }
    for (int i = tid; i < 1875; i += 256) as_[i] = att[(size_t)n * 1875 + i];
    __syncthreads();
    int c = tid;
#pragma unroll 1
    for (int v = 0; v < VV; v++) {
        float a0 = 0.f, a1 = 0.f, a2 = 0.f;
#pragma unroll
        for (int u = 0; u < VV; u++) {
            float xv = xs[u][c];
            a0 = fmaf(xv, as_[(u * VV + v) * 3 + 0], a0);
            a1 = fmaf(xv, as_[(u * VV + v) * 3 + 1], a1);
            a2 = fmaf(xv, as_[(u * VV + v) * 3 + 2], a2);
        }
        size_t base = ((size_t)(n * VV + v) * TT + t) * 768 + c * 3;
        __nv_bfloat16 h0 = __float2bfloat16(a0);
        __nv_bfloat16 h1 = __float2bfloat16(a1);
        __nv_bfloat16 h2 = __float2bfloat16(a2);
        yh[base] = h0; yh[base + 1] = h1; yh[base + 2] = h2;
        yl[base]     = __float2bfloat16(a0 - __bfloat162float(h0));
        yl[base + 1] = __float2bfloat16(a1 - __bfloat162float(h1));
        yl[base + 2] = __float2bfloat16(a2 - __bfloat162float(h2));
    }
}

// LN over group + residual + gelu; writes bf16 hi/lo (+ optional fp32)
__global__ void ln2(const float* __restrict__ h, const float* __restrict__ res,
                    const float* __restrict__ g, const float* __restrict__ b,
                    float* __restrict__ outf, __nv_bfloat16* __restrict__ oh,
                    __nv_bfloat16* __restrict__ ol, int G, int mode, int wf) {
    int grp = blockIdx.x;
    const float* hp = h + (size_t)grp * G;
    const float* rp = res + (size_t)grp * G;
    float s = 0.f, sq = 0.f;
    for (int i = threadIdx.x; i < G; i += blockDim.x) {
        float v = hp[i]; s += v; sq = fmaf(v, v, sq);
    }
    for (int o = 16; o; o >>= 1) {
        s += __shfl_down_sync(0xffffffffu, s, o);
        sq += __shfl_down_sync(0xffffffffu, sq, o);
    }
    __shared__ float ss[8], sqs[8];
    __shared__ float mean_s, inv_s;
    int w = threadIdx.x >> 5;
    if ((threadIdx.x & 31) == 0) { ss[w] = s; sqs[w] = sq; }
    __syncthreads();
    if (threadIdx.x == 0) {
        float S = 0.f, Q = 0.f;
        for (int i = 0; i < 8; i++) { S += ss[i]; Q += sqs[i]; }
        float mean = S / G;
        float var = Q / G - mean * mean;
        mean_s = mean; inv_s = rsqrtf(var + 1e-5f);
    }
    __syncthreads();
    float mean = mean_s, inv = inv_s;
    int n = 0, v = 0;
    if (mode == 1) { n = grp / VV; v = grp % VV; }
    for (int i = threadIdx.x; i < G; i += blockDim.x) {
        float val = gelu_f(rp[i] + fmaf((hp[i] - mean) * inv, g[i], b[i]));
        size_t dst;
        if (mode == 0) dst = (size_t)grp * G + i;
        else {
            int t = i >> 8, c = i & 255;
            dst = ((size_t)(n * TT + t) * VV + v) * 256 + c;
        }
        if (wf) outf[dst] = val;
        __nv_bfloat16 hi = __float2bfloat16(val);
        oh[dst] = hi;
        ol[dst] = __float2bfloat16(val - __bfloat162float(hi));
    }
}

// --------- de-interleave temporal qkt -> qd,kd [(n*4+m)][t][1600] -----------
__global__ void deint_t(const float* __restrict__ qkt, float* __restrict__ qd,
                        float* __restrict__ kd) {
    size_t idx = (size_t)blockIdx.x * 256 + threadIdx.x;
    int col = (int)(idx & 511);
    size_t row = idx >> 9;
    int v = (int)(row % VV);
    size_t nt = row / VV;
    int t = (int)(nt % TT), n = (int)(nt / TT);
    int ci = col >> 3, j = col & 7;
    float val = qkt[idx];
    int m = (j < 4) ? j : j - 4;
    size_t dst = ((size_t)(n * 4 + m) * TT + t) * 1600 + v * 64 + ci;
    if (j < 4) qd[dst] = val; else kd[dst] = val;
}

// temporal attention -> TRANSPOSED layout att[n][q][t][s]
__global__ __launch_bounds__(256) void att_t_fast(
        const float* __restrict__ qd, const float* __restrict__ kd,
        const float* __restrict__ alf, const float* __restrict__ alb,
        float* __restrict__ attf, float* __restrict__ attb) {
    int nm = blockIdx.x, n = nm >> 2, m = nm & 3;
    int s = m & 1, dir = m >> 1;
    __shared__ float Qs[64][68], Ks[64][68];
    const float* qb = qd + (size_t)nm * TT * 1600;
    const float* kb = kd + (size_t)nm * TT * 1600;
    const int tid = threadIdx.x;
    const int tx = tid & 15, ty = tid >> 4;
    const int lr = tid >> 2, lc = (tid & 3) << 4;
    float acc[4][4] = {};
    for (int kc = 0; kc < 1600; kc += 64) {
#pragma unroll
        for (int j = 0; j < 4; j++) {
            float4 q4 = *(const float4*)(qb + (size_t)lr * 1600 + kc + lc + j * 4);
            float4 k4 = *(const float4*)(kb + (size_t)lr * 1600 + kc + lc + j * 4);
            Qs[lc + j*4 + 0][lr] = q4.x; Qs[lc + j*4 + 1][lr] = q4.y;
            Qs[lc + j*4 + 2][lr] = q4.z; Qs[lc + j*4 + 3][lr] = q4.w;
            Ks[lc + j*4 + 0][lr] = k4.x; Ks[lc + j*4 + 1][lr] = k4.y;
            Ks[lc + j*4 + 2][lr] = k4.z; Ks[lc + j*4 + 3][lr] = k4.w;
        }
        __syncthreads();
#pragma unroll 8
        for (int kk = 0; kk < 64; kk++) {
            float4 aq = *(const float4*)(&Qs[kk][ty << 2]);
            float4 bk = *(const float4*)(&Ks[kk][tx << 2]);
            float a[4] = {aq.x, aq.y, aq.z, aq.w};
            float b[4] = {bk.x, bk.y, bk.z, bk.w};
#pragma unroll
            for (int i = 0; i < 4; i++)
#pragma unroll
                for (int j = 0; j < 4; j++) acc[i][j] = fmaf(a[i], b[j], acc[i][j]);
        }
        __syncthreads();
    }
    float al = dir ? alb[s] : alf[s];
#pragma unroll
    for (int i = 0; i < 4; i++) {
#pragma unroll
        for (int j = 0; j < 4; j++) {
            int t_ = (ty << 2) + i, q_ = (tx << 2) + j;
            float val = tanhf(acc[i][j] * (1.f / 1600.f)) * al;
            size_t idx = ((size_t)(n * TT + q_) * TT + t_) * 2 + s;   // [n][q][t][s]
            if (dir == 0) attf[idx] = (q_ <= t_) ? val : 0.f;
            else          attb[idx] = (q_ >= t_) ? val : 0.f;
        }
    }
}

// z apply: block per (n,v); y2 slice in smem; bf16 split output (1024-wide)
__global__ __launch_bounds__(256) void z2k(const float* __restrict__ y2t,
                                           const float* __restrict__ attf,
                                           const float* __restrict__ attb,
                                           __nv_bfloat16* __restrict__ zh,
                                           __nv_bfloat16* __restrict__ zl) {
    extern __shared__ float zs[];          // 64*256 + 256
    float* ys = zs;
    float* as_ = zs + 64 * 256;
    int b = blockIdx.x;                    // n*25 + v
    int n = b / VV, v = b % VV;
    int tid = threadIdx.x;
    for (int i = tid; i < 64 * 256; i += 256) {
        int t = i >> 8, c = i & 255;
        ys[t * 256 + c] = y2t[((size_t)(n * TT + t) * VV + v) * 256 + c];
    }
    __syncthreads();
    int c = tid;
    for (int q = 0; q < TT; q++) {
        if (tid < 128) as_[tid] = attf[(size_t)n * 8192 + q * 128 + tid];
        else           as_[tid] = attb[(size_t)n * 8192 + q * 128 + (tid - 128)];
        __syncthreads();
        float f0 = 0.f, f1 = 0.f, b0 = 0.f, b1 = 0.f;
#pragma unroll 8
        for (int t = 0; t < TT; t++) {
            float yv = ys[t * 256 + c];
            f0 = fmaf(yv, as_[t * 2], f0);       f1 = fmaf(yv, as_[t * 2 + 1], f1);
            b0 = fmaf(yv, as_[128 + t * 2], b0); b1 = fmaf(yv, as_[128 + t * 2 + 1], b1);
        }
        size_t base = ((size_t)(n * TT + q) * VV + v) * 1024;
        uint32_t hf, lf, hb, lb;
        split2(f0, f1, hf, lf);
        split2(b0, b1, hb, lb);
        *(uint32_t*)(zh + base + c * 2) = hf;
        *(uint32_t*)(zl + base + c * 2) = lf;
        *(uint32_t*)(zh + base + 512 + c * 2) = hb;
        *(uint32_t*)(zl + base + 512 + c * 2) = lb;
        __syncthreads();
    }
}

__global__ void final_kernel(const float* __restrict__ z2, const float* __restrict__ cv,
                             const float* __restrict__ bn_g, const float* __restrict__ bn_b,
                             const float* __restrict__ bn_m, const float* __restrict__ bn_v,
                             float* __restrict__ out) {
    size_t i = (size_t)blockIdx.x * 256 + threadIdx.x;
    int o = (int)(i & 255);
    size_t r = i >> 8;
    int v = (int)(r % VV);
    size_t r2 = r / VV;
    int t = (int)(r2 % TT);
    int n = (int)(r2 / TT);
    float c1 = fmaf((cv[i] - bn_m[o]) * rsqrtf(bn_v[o] + 1e-5f), bn_g[o], bn_b[o]);
    out[((size_t)(n * VV + v) * TT + t) * 256 + o] = gelu_f(z2[i] + c1);
}

// ------------------------------- launcher -----------------------------------
extern "C" void kernel_launch(void* const* d_in, const int* in_sizes, int n_in,
                              void* d_out, int out_size) {
    const float* x       = (const float*)d_in[0];
    const float* Wqk_s   = (const float*)d_in[1];
    const float* bqk_s   = (const float*)d_in[2];
    const float* alphas  = (const float*)d_in[3];
    const float* att0s   = (const float*)d_in[4];
    const float* Wo_s    = (const float*)d_in[5];
    const float* bo_s    = (const float*)d_in[6];
    const float* g_os    = (const float*)d_in[7];
    const float* b_os    = (const float*)d_in[8];
    const float* Wff_s   = (const float*)d_in[9];
    const float* bff_s   = (const float*)d_in[10];
    const float* g_ffs   = (const float*)d_in[11];
    const float* b_ffs   = (const float*)d_in[12];
    const float* Wqk_t   = (const float*)d_in[13];
    const float* bqk_t   = (const float*)d_in[14];
    const float* alphat_f= (const float*)d_in[15];
    const float* alphat_b= (const float*)d_in[16];
    const float* Wo_t    = (const float*)d_in[17];
    const float* bo_t    = (const float*)d_in[18];
    const float* g_ot    = (const float*)d_in[19];
    const float* b_ot    = (const float*)d_in[20];
    const float* Wff_t   = (const float*)d_in[21];
    const float* bff_t   = (const float*)d_in[22];
    const float* g_fft   = (const float*)d_in[23];
    const float* b_fft   = (const float*)d_in[24];
    const float* conv_w  = (const float*)d_in[25];
    const float* conv_b  = (const float*)d_in[26];
    const float* bn_g    = (const float*)d_in[27];
    const float* bn_b    = (const float*)d_in[28];
    const float* bn_m    = (const float*)d_in[29];
    const float* bn_v    = (const float*)d_in[30];
    float* out = (float*)d_out;

    void *pB, *pH, *pY1, *pY2, *pZ2, *pAS, *pAF, *pAB, *pWH, *pWL;
    void *pAH, *pAL, *pXH, *pXL, *pY1H, *pY1L, *pY2H, *pY2L, *pZ2H, *pZ2L;
    cudaGetSymbolAddress(&pB,  g_bufB);
    cudaGetSymbolAddress(&pH,  g_h);
    cudaGetSymbolAddress(&pY1, g_y1);
    cudaGetSymbolAddress(&pY2, g_y2);
    cudaGetSymbolAddress(&pZ2, g_z2);
    cudaGetSymbolAddress(&pAS, g_atts);
    cudaGetSymbolAddress(&pAF, g_attf);
    cudaGetSymbolAddress(&pAB, g_attb);
    cudaGetSymbolAddress(&pWH, g_wh);
    cudaGetSymbolAddress(&pWL, g_wl);
    cudaGetSymbolAddress(&pAH, g_ah);
    cudaGetSymbolAddress(&pAL, g_al);
    cudaGetSymbolAddress(&pXH, g_xh);
    cudaGetSymbolAddress(&pXL, g_xl);
    cudaGetSymbolAddress(&pY1H, g_y1h);
    cudaGetSymbolAddress(&pY1L, g_y1l);
    cudaGetSymbolAddress(&pY2H, g_y2h);
    cudaGetSymbolAddress(&pY2L, g_y2l);
    cudaGetSymbolAddress(&pZ2H, g_z2h);
    cudaGetSymbolAddress(&pZ2L, g_z2l);
    float* bufB = (float*)pB;
    float* h    = (float*)pH;  float* y1   = (float*)pY1;
    float* y2   = (float*)pY2; float* z2b  = (float*)pZ2;
    float* atts = (float*)pAS; float* attf = (float*)pAF;
    float* attb = (float*)pAB;
    __nv_bfloat16* wh = (__nv_bfloat16*)pWH;
    __nv_bfloat16* wl = (__nv_bfloat16*)pWL;
    __nv_bfloat16* ah = (__nv_bfloat16*)pAH;
    __nv_bfloat16* al = (__nv_bfloat16*)pAL;
    __nv_bfloat16* xh = (__nv_bfloat16*)pXH;
    __nv_bfloat16* xl = (__nv_bfloat16*)pXL;
    __nv_bfloat16* y1h = (__nv_bfloat16*)pY1H;
    __nv_bfloat16* y1l = (__nv_bfloat16*)pY1L;
    __nv_bfloat16* y2h = (__nv_bfloat16*)pY2H;
    __nv_bfloat16* y2l = (__nv_bfloat16*)pY2L;
    __nv_bfloat16* z2h = (__nv_bfloat16*)pZ2H;
    __nv_bfloat16* z2l = (__nv_bfloat16*)pZ2L;

    cudaFuncSetAttribute(gemm_mma2, cudaFuncAttributeMaxDynamicSharedMemorySize, GSM);
    cudaFuncSetAttribute(conv_mma2, cudaFuncAttributeMaxDynamicSharedMemorySize, GSM);
    cudaFuncSetAttribute(z2k, cudaFuncAttributeMaxDynamicSharedMemorySize, (64*256 + 256) * 4);

    dim3 blk(256);
    const int MB = RTOT / 128;   // 400

    // weight prep
    wsplit<<<(256*384 + 255)/256, blk>>>(Wqk_s, wh + OFF_QKS, wl + OFF_QKS, 256, 384);
    wsplit<<<(768*256 + 255)/256, blk>>>(Wo_s,  wh + OFF_WOS, wl + OFF_WOS, 768, 256);
    wsplit<<<(256*256 + 255)/256, blk>>>(Wff_s, wh + OFF_FFS, wl + OFF_FFS, 256, 256);
    wsplit<<<(256*512 + 255)/256, blk>>>(Wqk_t, wh + OFF_QKT, wl + OFF_QKT, 256, 512);
    wsplit<<<(1024*256 + 255)/256, blk>>>(Wo_t, wh + OFF_WOT, wl + OFF_WOT, 1024, 256);
    wsplit<<<(256*256 + 255)/256, blk>>>(Wff_t, wh + OFF_FFT, wl + OFF_FFT, 256, 256);
    wsplit_conv<<<(256*1792 + 255)/256, blk>>>(conv_w, wh + OFF_CNV, wl + OFF_CNV);
    xsplit<<<RTOT * 256 / 1024, blk>>>(x, xh, xl);

    // Stage 1: spatial
    gemm_mma2<<<dim3(3, MB), blk, GSM>>>(xh, xl, wh + OFF_QKS, wl + OFF_QKS, bqk_s, bufB, RTOT, 384, 256);
    deint_s<<<RTOT * 384 / 256, blk>>>(bufB, h, y1);
    att_s_fast<<<NN * 3, 128>>>(h, y1, alphas, att0s, atts);
    ys2<<<NN * TT, blk>>>(x, atts, ah, al);
    gemm_mma2<<<dim3(2, MB), blk, GSM>>>(ah, al, wh + OFF_WOS, wl + OFF_WOS, bo_s, h, RTOT, 256, 768);
    ln2<<<NN*VV, blk>>>(h, x, g_os, b_os, y1, y1h, y1l, TT*256, 0, 0);
    gemm_mma2<<<dim3(2, MB), blk, GSM>>>(y1h, y1l, wh + OFF_FFS, wl + OFF_FFS, bff_s, h, RTOT, 256, 256);
    ln2<<<NN*VV, blk>>>(h, x, g_ffs, b_ffs, y2, y2h, y2l, TT*256, 1, 1);

    // Stage 2: temporal
    gemm_mma2<<<dim3(4, MB), blk, GSM>>>(y2h, y2l, wh + OFF_QKT, wl + OFF_QKT, bqk_t, bufB, RTOT, 512, 256);
    deint_t<<<RTOT * 512 / 256, blk>>>(bufB, h, y1);
    att_t_fast<<<NN * 4, blk>>>(h, y1, alphat_f, alphat_b, attf, attb);
    z2k<<<NN * VV, blk, (64*256 + 256) * 4>>>(y2, attf, attb, ah, al);
    gemm_mma2<<<dim3(2, MB), blk, GSM>>>(ah, al, wh + OFF_WOT, wl + OFF_WOT, bo_t, h, RTOT, 256, 1024);
    ln2<<<NN*TT, blk>>>(h, y2, g_ot, b_ot, y1, y1h, y1l, VV*256, 0, 0);
    gemm_mma2<<<dim3(2, MB), blk, GSM>>>(y1h, y1l, wh + OFF_FFT, wl + OFF_FFT, bff_t, h, RTOT, 256, 256);
    ln2<<<NN*TT, blk>>>(h, y2, g_fft, b_fft, z2b, z2h, z2l, VV*256, 0, 1);

    // Stage 3: conv + BN + gelu + transpose
    conv_mma2<<<dim3(2, MB), blk, GSM>>>(z2h, z2l, wh + OFF_CNV, wl + OFF_CNV, conv_b, h);
    final_kernel<<<RTOT, blk>>>(z2b, h, bn_g, bn_b, bn_m, bn_v, out);
}

// round 7
// speedup vs baseline: 2.5905x; 1.0279x over previous
#include <cuda_runtime.h>
#include <cuda_bf16.h>
#include <math.h>
#include <stdint.h>

#define NN 32
#define VV 25
#define TT 64
#define RTOT (NN*VV*TT)   /* 51200 */

// ------------------------- scratch (device globals) -------------------------
__device__ float g_bufB[(size_t)RTOT * 512];
__device__ float g_h   [(size_t)RTOT * 256];
__device__ float g_y1  [(size_t)RTOT * 256];
__device__ float g_y2  [(size_t)RTOT * 256];
__device__ float g_z2  [(size_t)RTOT * 256];
__device__ float g_atts[NN*VV*VV*3];
__device__ float g_attf[NN*TT*TT*2];   // transposed layout [n][q][t][s]
__device__ float g_attb[NN*TT*TT*2];
// bf16 split activation buffers (16B-aligned for cp.async)
__device__ __align__(128) __nv_bfloat16 g_ah [(size_t)RTOT * 1024];
__device__ __align__(128) __nv_bfloat16 g_al [(size_t)RTOT * 1024];
__device__ __align__(128) __nv_bfloat16 g_xh [(size_t)RTOT * 256];
__device__ __align__(128) __nv_bfloat16 g_xl [(size_t)RTOT * 256];
__device__ __align__(128) __nv_bfloat16 g_y1h[(size_t)RTOT * 256];
__device__ __align__(128) __nv_bfloat16 g_y1l[(size_t)RTOT * 256];
__device__ __align__(128) __nv_bfloat16 g_y2h[(size_t)RTOT * 256];
__device__ __align__(128) __nv_bfloat16 g_y2l[(size_t)RTOT * 256];
__device__ __align__(128) __nv_bfloat16 g_z2h[(size_t)RTOT * 256];
__device__ __align__(128) __nv_bfloat16 g_z2l[(size_t)RTOT * 256];
#define WTOT 1277952
__device__ __align__(128) __nv_bfloat16 g_wh[WTOT];
__device__ __align__(128) __nv_bfloat16 g_wl[WTOT];
#define OFF_QKS 0         /* K=256  N=384  */
#define OFF_WOS 98304     /* K=768  N=256  */
#define OFF_FFS 294912    /* K=256  N=256  */
#define OFF_QKT 360448    /* K=256  N=512  */
#define OFF_WOT 491520    /* K=1024 N=256  */
#define OFF_FFT 753664    /* K=256  N=256  */
#define OFF_CNV 819200    /* K=1792 N=256  */

__device__ __forceinline__ float gelu_f(float x) {
    return 0.5f * x * (1.0f + erff(x * 0.7071067811865475f));
}
__device__ __forceinline__ void split2(float a, float b, uint32_t &hi, uint32_t &lo) {
    __nv_bfloat16 ha = __float2bfloat16(a), hb = __float2bfloat16(b);
    float la = a - __bfloat162float(ha), lb = b - __bfloat162float(hb);
    __nv_bfloat16 l1 = __float2bfloat16(la), l2 = __float2bfloat16(lb);
    hi = (uint32_t)__bfloat16_as_ushort(ha) | ((uint32_t)__bfloat16_as_ushort(hb) << 16);
    lo = (uint32_t)__bfloat16_as_ushort(l1) | ((uint32_t)__bfloat16_as_ushort(l2) << 16);
}
__device__ __forceinline__ uint32_t smem_u32(const void* p) {
    uint32_t a;
    asm("{ .reg .u64 t; cvta.to.shared.u64 t, %1; cvt.u32.u64 %0, t; }" : "=r"(a) : "l"(p));
    return a;
}
__device__ __forceinline__ void ldm4(uint32_t &r0, uint32_t &r1, uint32_t &r2,
                                     uint32_t &r3, uint32_t a) {
    asm volatile("ldmatrix.sync.aligned.m8n8.x4.shared.b16 {%0,%1,%2,%3}, [%4];"
        : "=r"(r0), "=r"(r1), "=r"(r2), "=r"(r3) : "r"(a));
}
__device__ __forceinline__ void mma16816(float* c, const uint32_t* a, const uint32_t* b) {
    asm volatile(
        "mma.sync.aligned.m16n8k16.row.col.f32.bf16.bf16.f32 "
        "{%0,%1,%2,%3}, {%4,%5,%6,%7}, {%8,%9}, {%0,%1,%2,%3};"
        : "+f"(c[0]), "+f"(c[1]), "+f"(c[2]), "+f"(c[3])
        : "r"(a[0]), "r"(a[1]), "r"(a[2]), "r"(a[3]), "r"(b[0]), "r"(b[1]));
}
__device__ __forceinline__ void cpa16(uint32_t dst, const void* src) {
    asm volatile("cp.async.cg.shared.global [%0], [%1], 16;" :: "r"(dst), "l"(src));
}
__device__ __forceinline__ void cpa16z(uint32_t dst, const void* src, int sz) {
    asm volatile("cp.async.cg.shared.global [%0], [%1], 16, %2;" :: "r"(dst), "l"(src), "r"(sz));
}
#define CPA_COMMIT() asm volatile("cp.async.commit_group;" ::: "memory")
#define CPA_WAIT2() asm volatile("cp.async.wait_group 2;" ::: "memory")
#define CPA_WAIT1() asm volatile("cp.async.wait_group 1;" ::: "memory")
#define CPA_WAIT0() asm volatile("cp.async.wait_group 0;" ::: "memory")

// smem swizzle for 64B rows (32 bf16): 16B chunk ch of row r at (ch ^ ((r>>1)&3))*16
#define SWZ(row, ch) ((uint32_t)((row) * 64 + ((((ch) ^ (((row) >> 1) & 3))) << 4)))

// ========== HMMA GEMM: 128x128 tile, k-chunk 32, 3-stage, 2 CTA/SM ==========
// C[M,N] = (Ah+Al)[M,K] @ (Bh+Bl)[K,N] + bias; bf16 split; B stored [N][K].
// stage 32KB: Ah(8K) Al(8K) Bh(8K) Bl(8K); 3 stages = 96KB.
#define GSM (3*32768)
__global__ __launch_bounds__(256, 2) void gemm_mma3(
        const __nv_bfloat16* __restrict__ Ah, const __nv_bfloat16* __restrict__ Al,
        const __nv_bfloat16* __restrict__ Bh, const __nv_bfloat16* __restrict__ Bl,
        const float* __restrict__ bias, float* __restrict__ C, int M, int N, int K) {
    extern __shared__ char sm[];
    const uint32_t sbase = smem_u32(sm);
    const int tid = threadIdx.x, lane = tid & 31, w = tid >> 5;
    const int wm = w & 3, wn = w >> 2;
    const int bm = blockIdx.y << 7, bn = blockIdx.x << 7;
    float acc[2][8][4];
#pragma unroll
    for (int i = 0; i < 2; i++)
#pragma unroll
        for (int j = 0; j < 8; j++)
#pragma unroll
            for (int q = 0; q < 4; q++) acc[i][j][q] = 0.f;
    const int nch = K >> 5;

    auto load_stage = [&](int c) {
        uint32_t st = sbase + (c % 3) * 32768;
        const int k0 = c << 5;
#pragma unroll
        for (int j = 0; j < 2; j++) {
            int f = j * 256 + tid;
            int row = f >> 2, ch = f & 3;
            uint32_t off = SWZ(row, ch);
            cpa16(st + off,         Ah + (size_t)(bm + row) * K + k0 + ch * 8);
            cpa16(st + 8192 + off,  Al + (size_t)(bm + row) * K + k0 + ch * 8);
            cpa16(st + 16384 + off, Bh + (size_t)(bn + row) * K + k0 + ch * 8);
            cpa16(st + 24576 + off, Bl + (size_t)(bn + row) * K + k0 + ch * 8);
        }
        CPA_COMMIT();
    };
    load_stage(0);
    load_stage(1);
    for (int c = 0; c < nch; c++) {
        if (c + 2 < nch) { load_stage(c + 2); CPA_WAIT2(); }
        else if (c + 1 < nch) CPA_WAIT1();
        else CPA_WAIT0();
        __syncthreads();
        const uint32_t sAh = sbase + (c % 3) * 32768;
        const uint32_t sAl = sAh + 8192, sBh = sAh + 16384, sBl = sAh + 24576;
#pragma unroll
        for (int kk = 0; kk < 2; kk++) {
            uint32_t ah[2][4], al[2][4];
            const int arow = wm * 32 + (lane & 15);
            const int achunk = kk * 2 + (lane >> 4);
#pragma unroll
            for (int mi = 0; mi < 2; mi++) {
                int row = arow + mi * 16;
                ldm4(ah[mi][0], ah[mi][1], ah[mi][2], ah[mi][3], sAh + SWZ(row, achunk));
                ldm4(al[mi][0], al[mi][1], al[mi][2], al[mi][3], sAl + SWZ(row, achunk));
            }
            const int bchunk = kk * 2 + ((lane >> 3) & 1);
#pragma unroll
            for (int half = 0; half < 2; half++) {
                uint32_t bh[4][2], bl[4][2];
#pragma unroll
                for (int p = 0; p < 2; p++) {
                    int brow = wn * 64 + half * 32 + p * 16 + ((lane & 16) >> 1) + (lane & 7);
                    ldm4(bh[2*p][0], bh[2*p][1], bh[2*p+1][0], bh[2*p+1][1],
                         sBh + SWZ(brow, bchunk));
                    ldm4(bl[2*p][0], bl[2*p][1], bl[2*p+1][0], bl[2*p+1][1],
                         sBl + SWZ(brow, bchunk));
                }
#pragma unroll
                for (int mi = 0; mi < 2; mi++)
#pragma unroll
                    for (int nf = 0; nf < 4; nf++) {
                        mma16816(acc[mi][half * 4 + nf], ah[mi], bh[nf]);
                        mma16816(acc[mi][half * 4 + nf], ah[mi], bl[nf]);
                        mma16816(acc[mi][half * 4 + nf], al[mi], bh[nf]);
                    }
            }
        }
        __syncthreads();
    }
    const int gid = lane >> 2, tig = lane & 3;
#pragma unroll
    for (int mi = 0; mi < 2; mi++)
#pragma unroll
        for (int nf = 0; nf < 8; nf++) {
            int col = bn + wn * 64 + nf * 8 + tig * 2;
            float b0v = bias[col], b1v = bias[col + 1];
            int r0 = bm + wm * 32 + mi * 16 + gid;
            *(float2*)(C + (size_t)r0 * N + col) =
                make_float2(acc[mi][nf][0] + b0v, acc[mi][nf][1] + b1v);
            *(float2*)(C + (size_t)(r0 + 8) * N + col) =
                make_float2(acc[mi][nf][2] + b0v, acc[mi][nf][3] + b1v);
        }
}

// ===== conv (implicit im2col) HMMA: K=1792, N=256, k-chunk 32, 3-stage ======
__global__ __launch_bounds__(256, 2) void conv_mma3(
        const __nv_bfloat16* __restrict__ Zh, const __nv_bfloat16* __restrict__ Zl,
        const __nv_bfloat16* __restrict__ Bh, const __nv_bfloat16* __restrict__ Bl,
        const float* __restrict__ bias, float* __restrict__ C) {
    const int N = 256, K = 1792;
    extern __shared__ char sm[];
    const uint32_t sbase = smem_u32(sm);
    const int tid = threadIdx.x, lane = tid & 31, w = tid >> 5;
    const int wm = w & 3, wn = w >> 2;
    const int bm = blockIdx.y << 7, bn = blockIdx.x << 7;
    float acc[2][8][4];
#pragma unroll
    for (int i = 0; i < 2; i++)
#pragma unroll
        for (int j = 0; j < 8; j++)
#pragma unroll
            for (int q = 0; q < 4; q++) acc[i][j][q] = 0.f;
    const int nch = K >> 5;   // 56

    auto load_stage = [&](int c) {
        uint32_t st = sbase + (c % 3) * 32768;
        const int k0 = c << 5;
        const int dt = (k0 >> 8) - 3;
        const int iio = k0 & 255;
#pragma unroll
        for (int j = 0; j < 2; j++) {
            int f = j * 256 + tid;
            int row = f >> 2, ch = f & 3;
            uint32_t off = SWZ(row, ch);
            int grow = bm + row;
            int t = (grow / VV) % TT;
            int tt = t + dt;
            int ok = (tt >= 0 && tt < TT);
            size_t srcoff = ok ? ((size_t)grow + (size_t)dt * VV) * 256 + iio + ch * 8 : 0;
            cpa16z(st + off,        Zh + srcoff, ok ? 16 : 0);
            cpa16z(st + 8192 + off, Zl + srcoff, ok ? 16 : 0);
            cpa16(st + 16384 + off, Bh + (size_t)(bn + row) * K + k0 + ch * 8);
            cpa16(st + 24576 + off, Bl + (size_t)(bn + row) * K + k0 + ch * 8);
        }
        CPA_COMMIT();
    };
    load_stage(0);
    load_stage(1);
    for (int c = 0; c < nch; c++) {
        if (c + 2 < nch) { load_stage(c + 2); CPA_WAIT2(); }
        else if (c + 1 < nch) CPA_WAIT1();
        else CPA_WAIT0();
        __syncthreads();
        const uint32_t sAh = sbase + (c % 3) * 32768;
        const uint32_t sAl = sAh + 8192, sBh = sAh + 16384, sBl = sAh + 24576;
#pragma unroll
        for (int kk = 0; kk < 2; kk++) {
            uint32_t ah[2][4], al[2][4];
            const int arow = wm * 32 + (lane & 15);
            const int achunk = kk * 2 + (lane >> 4);
#pragma unroll
            for (int mi = 0; mi < 2; mi++) {
                int row = arow + mi * 16;
                ldm4(ah[mi][0], ah[mi][1], ah[mi][2], ah[mi][3], sAh + SWZ(row, achunk));
                ldm4(al[mi][0], al[mi][1], al[mi][2], al[mi][3], sAl + SWZ(row, achunk));
            }
            const int bchunk = kk * 2 + ((lane >> 3) & 1);
#pragma unroll
            for (int half = 0; half < 2; half++) {
                uint32_t bh[4][2], bl[4][2];
#pragma unroll
                for (int p = 0; p < 2; p++) {
                    int brow = wn * 64 + half * 32 + p * 16 + ((lane & 16) >> 1) + (lane & 7);
                    ldm4(bh[2*p][0], bh[2*p][1], bh[2*p+1][0], bh[2*p+1][1],
                         sBh + SWZ(brow, bchunk));
                    ldm4(bl[2*p][0], bl[2*p][1], bl[2*p+1][0], bl[2*p+1][1],
                         sBl + SWZ(brow, bchunk));
                }
#pragma unroll
                for (int mi = 0; mi < 2; mi++)
#pragma unroll
                    for (int nf = 0; nf < 4; nf++) {
                        mma16816(acc[mi][half * 4 + nf], ah[mi], bh[nf]);
                        mma16816(acc[mi][half * 4 + nf], ah[mi], bl[nf]);
                        mma16816(acc[mi][half * 4 + nf], al[mi], bh[nf]);
                    }
            }
        }
        __syncthreads();
    }
    const int gid = lane >> 2, tig = lane & 3;
#pragma unroll
    for (int mi = 0; mi < 2; mi++)
#pragma unroll
        for (int nf = 0; nf < 8; nf++) {
            int col = bn + wn * 64 + nf * 8 + tig * 2;
            float b0v = bias[col], b1v = bias[col + 1];
            int r0 = bm + wm * 32 + mi * 16 + gid;
            *(float2*)(C + (size_t)r0 * N + col) =
                make_float2(acc[mi][nf][0] + b0v, acc[mi][nf][1] + b1v);
            *(float2*)(C + (size_t)(r0 + 8) * N + col) =
                make_float2(acc[mi][nf][2] + b0v, acc[mi][nf][3] + b1v);
        }
}

// ------------------- weight transpose + bf16 split prep ---------------------
__global__ void wsplit(const float* __restrict__ W, __nv_bfloat16* __restrict__ H,
                       __nv_bfloat16* __restrict__ L, int K, int N) {
    int i = blockIdx.x * 256 + threadIdx.x;
    if (i >= K * N) return;
    int k = i / N, n = i % N;
    float v = W[i];
    __nv_bfloat16 h = __float2bfloat16(v);
    H[(size_t)n * K + k] = h;
    L[(size_t)n * K + k] = __float2bfloat16(v - __bfloat162float(h));
}
__global__ void wsplit_conv(const float* __restrict__ W, __nv_bfloat16* __restrict__ H,
                            __nv_bfloat16* __restrict__ L) {
    int i = blockIdx.x * 256 + threadIdx.x;
    if (i >= 256 * 1792) return;
    int o = i / 1792, r = i % 1792;
    int ii = r / 7, kw = r % 7;
    float v = W[i];
    __nv_bfloat16 h = __float2bfloat16(v);
    size_t dst = (size_t)o * 1792 + kw * 256 + ii;
    H[dst] = h;
    L[dst] = __float2bfloat16(v - __bfloat162float(h));
}

// activation split: fp32 -> bf16 hi/lo (vectorized)
__global__ void xsplit(const float* __restrict__ X, __nv_bfloat16* __restrict__ H,
                       __nv_bfloat16* __restrict__ L) {
    size_t i = ((size_t)blockIdx.x * 256 + threadIdx.x) * 4;
    float4 v = *(const float4*)(X + i);
    uint32_t h0, l0, h1, l1;
    split2(v.x, v.y, h0, l0);
    split2(v.z, v.w, h1, l1);
    *(uint2*)(H + i) = make_uint2(h0, h1);
    *(uint2*)(L + i) = make_uint2(l0, l1);
}

// --------- de-interleave spatial qk -> qT,kT [(n*3+s)*25+u][4096] -----------
__global__ void deint_s(const float* __restrict__ qk, float* __restrict__ qT,
                        float* __restrict__ kT) {
    size_t idx = (size_t)blockIdx.x * 256 + threadIdx.x;
    int col = (int)(idx % 384);
    size_t row = idx / 384;
    int t = (int)(row % TT);
    size_t nu = row / TT;
    int n = (int)(nu / VV), u = (int)(nu % VV);
    int ci = col / 6, r = col % 6;
    float v = qk[idx];
    int s = (r < 3) ? r : r - 3;
    size_t dst = (((size_t)(n * 3 + s) * VV + u) << 12) + t * 64 + ci;
    if (r < 3) qT[dst] = v; else kT[dst] = v;
}

// spatial attention
__global__ __launch_bounds__(128) void att_s_fast(
        const float* __restrict__ qT, const float* __restrict__ kT,
        const float* __restrict__ alphas, const float* __restrict__ att0,
        float* __restrict__ att) {
    int ns = blockIdx.x, n = ns / 3, s = ns % 3;
    __shared__ float qs[25][132], ks[25][132];
    const float* qb = qT + ((size_t)ns * VV << 12);
    const float* kb = kT + ((size_t)ns * VV << 12);
    int t = threadIdx.x;
    int u0 = (t / 25) * 5, v = t % 25;
    float acc[5] = {0.f, 0.f, 0.f, 0.f, 0.f};
    for (int kc = 0; kc < 4096; kc += 128) {
        for (int i = t; i < 25 * 128; i += 128) {
            int uu = i >> 7, e = i & 127;
            qs[uu][e] = qb[((size_t)uu << 12) + kc + e];
            ks[uu][e] = kb[((size_t)uu << 12) + kc + e];
        }
        __syncthreads();
        if (t < 125) {
#pragma unroll 4
            for (int e = 0; e < 128; e++) {
                float kv = ks[v][e];
                acc[0] = fmaf(qs[u0 + 0][e], kv, acc[0]);
                acc[1] = fmaf(qs[u0 + 1][e], kv, acc[1]);
                acc[2] = fmaf(qs[u0 + 2][e], kv, acc[2]);
                acc[3] = fmaf(qs[u0 + 3][e], kv, acc[3]);
                acc[4] = fmaf(qs[u0 + 4][e], kv, acc[4]);
            }
        }
        __syncthreads();
    }
    if (t < 125) {
        float al = alphas[s];
#pragma unroll
        for (int i = 0; i < 5; i++) {
            int u = u0 + i;
            att[((size_t)(n * VV + u) * VV + v) * 3 + s] =
                tanhf(acc[i] * (1.f / 4096.f)) * al + att0[((size_t)u * VV + v) * 3 + s];
        }
    }
}

// y_s: block per (n,t); x slice in smem; bf16 split output (768-wide)
__global__ __launch_bounds__(256) void ys2(const float* __restrict__ x,
                                           const float* __restrict__ att,
                                           __nv_bfloat16* __restrict__ yh,
                                           __nv_bfloat16* __restrict__ yl) {
    __shared__ float xs[25][256];
    __shared__ float as_[25 * 25 * 3];
    int b = blockIdx.x;             // n*64 + t
    int n = b >> 6, t = b & 63;
    int tid = threadIdx.x;
    for (int i = tid; i < 25 * 256; i += 256) {
        int u = i >> 8, c = i & 255;
        xs[u][c] = x[((size_t)(n * VV + u) * TT + t) * 256 + c];
    }
    for (int i = tid; i < 1875; i += 256) as_[i] = att[(size_t)n * 1875 + i];
    __syncthreads();
    int c = tid;
#pragma unroll 1
    for (int v = 0; v < VV; v++) {
        float a0 = 0.f, a1 = 0.f, a2 = 0.f;
#pragma unroll
        for (int u = 0; u < VV; u++) {
            float xv = xs[u][c];
            a0 = fmaf(xv, as_[(u * VV + v) * 3 + 0], a0);
            a1 = fmaf(xv, as_[(u * VV + v) * 3 + 1], a1);
            a2 = fmaf(xv, as_[(u * VV + v) * 3 + 2], a2);
        }
        size_t base = ((size_t)(n * VV + v) * TT + t) * 768 + c * 3;
        __nv_bfloat16 h0 = __float2bfloat16(a0);
        __nv_bfloat16 h1 = __float2bfloat16(a1);
        __nv_bfloat16 h2 = __float2bfloat16(a2);
        yh[base] = h0; yh[base + 1] = h1; yh[base + 2] = h2;
        yl[base]     = __float2bfloat16(a0 - __bfloat162float(h0));
        yl[base + 1] = __float2bfloat16(a1 - __bfloat162float(h1));
        yl[base + 2] = __float2bfloat16(a2 - __bfloat162float(h2));
    }
}

// LN over group + residual + gelu; writes bf16 hi/lo (+ optional fp32)
__global__ void ln2(const float* __restrict__ h, const float* __restrict__ res,
                    const float* __restrict__ g, const float* __restrict__ b,
                    float* __restrict__ outf, __nv_bfloat16* __restrict__ oh,
                    __nv_bfloat16* __restrict__ ol, int G, int mode, int wf) {
    int grp = blockIdx.x;
    const float* hp = h + (size_t)grp * G;
    const float* rp = res + (size_t)grp * G;
    float s = 0.f, sq = 0.f;
    for (int i = threadIdx.x; i < G; i += blockDim.x) {
        float v = hp[i]; s += v; sq = fmaf(v, v, sq);
    }
    for (int o = 16; o; o >>= 1) {
        s += __shfl_down_sync(0xffffffffu, s, o);
        sq += __shfl_down_sync(0xffffffffu, sq, o);
    }
    __shared__ float ss[8], sqs[8];
    __shared__ float mean_s, inv_s;
    int w = threadIdx.x >> 5;
    if ((threadIdx.x & 31) == 0) { ss[w] = s; sqs[w] = sq; }
    __syncthreads();
    if (threadIdx.x == 0) {
        float S = 0.f, Q = 0.f;
        for (int i = 0; i < 8; i++) { S += ss[i]; Q += sqs[i]; }
        float mean = S / G;
        float var = Q / G - mean * mean;
        mean_s = mean; inv_s = rsqrtf(var + 1e-5f);
    }
    __syncthreads();
    float mean = mean_s, inv = inv_s;
    int n = 0, v = 0;
    if (mode == 1) { n = grp / VV; v = grp % VV; }
    for (int i = threadIdx.x; i < G; i += blockDim.x) {
        float val = gelu_f(rp[i] + fmaf((hp[i] - mean) * inv, g[i], b[i]));
        size_t dst;
        if (mode == 0) dst = (size_t)grp * G + i;
        else {
            int t = i >> 8, c = i & 255;
            dst = ((size_t)(n * TT + t) * VV + v) * 256 + c;
        }
        if (wf) outf[dst] = val;
        __nv_bfloat16 hi = __float2bfloat16(val);
        oh[dst] = hi;
        ol[dst] = __float2bfloat16(val - __bfloat162float(hi));
    }
}

// --------- de-interleave temporal qkt -> qd,kd [(n*4+m)][t][1600] -----------
__global__ void deint_t(const float* __restrict__ qkt, float* __restrict__ qd,
                        float* __restrict__ kd) {
    size_t idx = (size_t)blockIdx.x * 256 + threadIdx.x;
    int col = (int)(idx & 511);
    size_t row = idx >> 9;
    int v = (int)(row % VV);
    size_t nt = row / VV;
    int t = (int)(nt % TT), n = (int)(nt / TT);
    int ci = col >> 3, j = col & 7;
    float val = qkt[idx];
    int m = (j < 4) ? j : j - 4;
    size_t dst = ((size_t)(n * 4 + m) * TT + t) * 1600 + v * 64 + ci;
    if (j < 4) qd[dst] = val; else kd[dst] = val;
}

// temporal attention -> TRANSPOSED layout att[n][q][t][s]
__global__ __launch_bounds__(256) void att_t_fast(
        const float* __restrict__ qd, const float* __restrict__ kd,
        const float* __restrict__ alf, const float* __restrict__ alb,
        float* __restrict__ attf, float* __restrict__ attb) {
    int nm = blockIdx.x, n = nm >> 2, m = nm & 3;
    int s = m & 1, dir = m >> 1;
    __shared__ float Qs[64][68], Ks[64][68];
    const float* qb = qd + (size_t)nm * TT * 1600;
    const float* kb = kd + (size_t)nm * TT * 1600;
    const int tid = threadIdx.x;
    const int tx = tid & 15, ty = tid >> 4;
    const int lr = tid >> 2, lc = (tid & 3) << 4;
    float acc[4][4] = {};
    for (int kc = 0; kc < 1600; kc += 64) {
#pragma unroll
        for (int j = 0; j < 4; j++) {
            float4 q4 = *(const float4*)(qb + (size_t)lr * 1600 + kc + lc + j * 4);
            float4 k4 = *(const float4*)(kb + (size_t)lr * 1600 + kc + lc + j * 4);
            Qs[lc + j*4 + 0][lr] = q4.x; Qs[lc + j*4 + 1][lr] = q4.y;
            Qs[lc + j*4 + 2][lr] = q4.z; Qs[lc + j*4 + 3][lr] = q4.w;
            Ks[lc + j*4 + 0][lr] = k4.x; Ks[lc + j*4 + 1][lr] = k4.y;
            Ks[lc + j*4 + 2][lr] = k4.z; Ks[lc + j*4 + 3][lr] = k4.w;
        }
        __syncthreads();
#pragma unroll 8
        for (int kk = 0; kk < 64; kk++) {
            float4 aq = *(const float4*)(&Qs[kk][ty << 2]);
            float4 bk = *(const float4*)(&Ks[kk][tx << 2]);
            float a[4] = {aq.x, aq.y, aq.z, aq.w};
            float b[4] = {bk.x, bk.y, bk.z, bk.w};
#pragma unroll
            for (int i = 0; i < 4; i++)
#pragma unroll
                for (int j = 0; j < 4; j++) acc[i][j] = fmaf(a[i], b[j], acc[i][j]);
        }
        __syncthreads();
    }
    float al = dir ? alb[s] : alf[s];
#pragma unroll
    for (int i = 0; i < 4; i++) {
#pragma unroll
        for (int j = 0; j < 4; j++) {
            int t_ = (ty << 2) + i, q_ = (tx << 2) + j;
            float val = tanhf(acc[i][j] * (1.f / 1600.f)) * al;
            size_t idx = ((size_t)(n * TT + q_) * TT + t_) * 2 + s;   // [n][q][t][s]
            if (dir == 0) attf[idx] = (q_ <= t_) ? val : 0.f;
            else          attb[idx] = (q_ >= t_) ? val : 0.f;
        }
    }
}

// z apply: block per (n,v); y2 slice in smem; bf16 split output (1024-wide)
__global__ __launch_bounds__(256) void z2k(const float* __restrict__ y2t,
                                           const float* __restrict__ attf,
                                           const float* __restrict__ attb,
                                           __nv_bfloat16* __restrict__ zh,
                                           __nv_bfloat16* __restrict__ zl) {
    extern __shared__ float zs[];          // 64*256 + 256
    float* ys = zs;
    float* as_ = zs + 64 * 256;
    int b = blockIdx.x;                    // n*25 + v
    int n = b / VV, v = b % VV;
    int tid = threadIdx.x;
    for (int i = tid; i < 64 * 256; i += 256) {
        int t = i >> 8, c = i & 255;
        ys[t * 256 + c] = y2t[((size_t)(n * TT + t) * VV + v) * 256 + c];
    }
    __syncthreads();
    int c = tid;
    for (int q = 0; q < TT; q++) {
        if (tid < 128) as_[tid] = attf[(size_t)n * 8192 + q * 128 + tid];
        else           as_[tid] = attb[(size_t)n * 8192 + q * 128 + (tid - 128)];
        __syncthreads();
        float f0 = 0.f, f1 = 0.f, b0 = 0.f, b1 = 0.f;
#pragma unroll 8
        for (int t = 0; t < TT; t++) {
            float yv = ys[t * 256 + c];
            f0 = fmaf(yv, as_[t * 2], f0);       f1 = fmaf(yv, as_[t * 2 + 1], f1);
            b0 = fmaf(yv, as_[128 + t * 2], b0); b1 = fmaf(yv, as_[128 + t * 2 + 1], b1);
        }
        size_t base = ((size_t)(n * TT + q) * VV + v) * 1024;
        uint32_t hf, lf, hb, lb;
        split2(f0, f1, hf, lf);
        split2(b0, b1, hb, lb);
        *(uint32_t*)(zh + base + c * 2) = hf;
        *(uint32_t*)(zl + base + c * 2) = lf;
        *(uint32_t*)(zh + base + 512 + c * 2) = hb;
        *(uint32_t*)(zl + base + 512 + c * 2) = lb;
        __syncthreads();
    }
}

__global__ void final_kernel(const float* __restrict__ z2, const float* __restrict__ cv,
                             const float* __restrict__ bn_g, const float* __restrict__ bn_b,
                             const float* __restrict__ bn_m, const float* __restrict__ bn_v,
                             float* __restrict__ out) {
    size_t i = (size_t)blockIdx.x * 256 + threadIdx.x;
    int o = (int)(i & 255);
    size_t r = i >> 8;
    int v = (int)(r % VV);
    size_t r2 = r / VV;
    int t = (int)(r2 % TT);
    int n = (int)(r2 / TT);
    float c1 = fmaf((cv[i] - bn_m[o]) * rsqrtf(bn_v[o] + 1e-5f), bn_g[o], bn_b[o]);
    out[((size_t)(n * VV + v) * TT + t) * 256 + o] = gelu_f(z2[i] + c1);
}

// ------------------------------- launcher -----------------------------------
extern "C" void kernel_launch(void* const* d_in, const int* in_sizes, int n_in,
                              void* d_out, int out_size) {
    const float* x       = (const float*)d_in[0];
    const float* Wqk_s   = (const float*)d_in[1];
    const float* bqk_s   = (const float*)d_in[2];
    const float* alphas  = (const float*)d_in[3];
    const float* att0s   = (const float*)d_in[4];
    const float* Wo_s    = (const float*)d_in[5];
    const float* bo_s    = (const float*)d_in[6];
    const float* g_os    = (const float*)d_in[7];
    const float* b_os    = (const float*)d_in[8];
    const float* Wff_s   = (const float*)d_in[9];
    const float* bff_s   = (const float*)d_in[10];
    const float* g_ffs   = (const float*)d_in[11];
    const float* b_ffs   = (const float*)d_in[12];
    const float* Wqk_t   = (const float*)d_in[13];
    const float* bqk_t   = (const float*)d_in[14];
    const float* alphat_f= (const float*)d_in[15];
    const float* alphat_b= (const float*)d_in[16];
    const float* Wo_t    = (const float*)d_in[17];
    const float* bo_t    = (const float*)d_in[18];
    const float* g_ot    = (const float*)d_in[19];
    const float* b_ot    = (const float*)d_in[20];
    const float* Wff_t   = (const float*)d_in[21];
    const float* bff_t   = (const float*)d_in[22];
    const float* g_fft   = (const float*)d_in[23];
    const float* b_fft   = (const float*)d_in[24];
    const float* conv_w  = (const float*)d_in[25];
    const float* conv_b  = (const float*)d_in[26];
    const float* bn_g    = (const float*)d_in[27];
    const float* bn_b    = (const float*)d_in[28];
    const float* bn_m    = (const float*)d_in[29];
    const float* bn_v    = (const float*)d_in[30];
    float* out = (float*)d_out;

    void *pB, *pH, *pY1, *pY2, *pZ2, *pAS, *pAF, *pAB, *pWH, *pWL;
    void *pAH, *pAL, *pXH, *pXL, *pY1H, *pY1L, *pY2H, *pY2L, *pZ2H, *pZ2L;
    cudaGetSymbolAddress(&pB,  g_bufB);
    cudaGetSymbolAddress(&pH,  g_h);
    cudaGetSymbolAddress(&pY1, g_y1);
    cudaGetSymbolAddress(&pY2, g_y2);
    cudaGetSymbolAddress(&pZ2, g_z2);
    cudaGetSymbolAddress(&pAS, g_atts);
    cudaGetSymbolAddress(&pAF, g_attf);
    cudaGetSymbolAddress(&pAB, g_attb);
    cudaGetSymbolAddress(&pWH, g_wh);
    cudaGetSymbolAddress(&pWL, g_wl);
    cudaGetSymbolAddress(&pAH, g_ah);
    cudaGetSymbolAddress(&pAL, g_al);
    cudaGetSymbolAddress(&pXH, g_xh);
    cudaGetSymbolAddress(&pXL, g_xl);
    cudaGetSymbolAddress(&pY1H, g_y1h);
    cudaGetSymbolAddress(&pY1L, g_y1l);
    cudaGetSymbolAddress(&pY2H, g_y2h);
    cudaGetSymbolAddress(&pY2L, g_y2l);
    cudaGetSymbolAddress(&pZ2H, g_z2h);
    cudaGetSymbolAddress(&pZ2L, g_z2l);
    float* bufB = (float*)pB;
    float* h    = (float*)pH;  float* y1   = (float*)pY1;
    float* y2   = (float*)pY2; float* z2b  = (float*)pZ2;
    float* atts = (float*)pAS; float* attf = (float*)pAF;
    float* attb = (float*)pAB;
    __nv_bfloat16* wh = (__nv_bfloat16*)pWH;
    __nv_bfloat16* wl = (__nv_bfloat16*)pWL;
    __nv_bfloat16* ah = (__nv_bfloat16*)pAH;
    __nv_bfloat16* al = (__nv_bfloat16*)pAL;
    __nv_bfloat16* xh = (__nv_bfloat16*)pXH;
    __nv_bfloat16* xl = (__nv_bfloat16*)pXL;
    __nv_bfloat16* y1h = (__nv_bfloat16*)pY1H;
    __nv_bfloat16* y1l = (__nv_bfloat16*)pY1L;
    __nv_bfloat16* y2h = (__nv_bfloat16*)pY2H;
    __nv_bfloat16* y2l = (__nv_bfloat16*)pY2L;
    __nv_bfloat16* z2h = (__nv_bfloat16*)pZ2H;
    __nv_bfloat16* z2l = (__nv_bfloat16*)pZ2L;

    cudaFuncSetAttribute(gemm_mma3, cudaFuncAttributeMaxDynamicSharedMemorySize, GSM);
    cudaFuncSetAttribute(conv_mma3, cudaFuncAttributeMaxDynamicSharedMemorySize, GSM);
    cudaFuncSetAttribute(z2k, cudaFuncAttributeMaxDynamicSharedMemorySize, (64*256 + 256) * 4);

    dim3 blk(256);
    const int MB = RTOT / 128;   // 400

    // weight prep
    wsplit<<<(256*384 + 255)/256, blk>>>(Wqk_s, wh + OFF_QKS, wl + OFF_QKS, 256, 384);
    wsplit<<<(768*256 + 255)/256, blk>>>(Wo_s,  wh + OFF_WOS, wl + OFF_WOS, 768, 256);
    wsplit<<<(256*256 + 255)/256, blk>>>(Wff_s, wh + OFF_FFS, wl + OFF_FFS, 256, 256);
    wsplit<<<(256*512 + 255)/256, blk>>>(Wqk_t, wh + OFF_QKT, wl + OFF_QKT, 256, 512);
    wsplit<<<(1024*256 + 255)/256, blk>>>(Wo_t, wh + OFF_WOT, wl + OFF_WOT, 1024, 256);
    wsplit<<<(256*256 + 255)/256, blk>>>(Wff_t, wh + OFF_FFT, wl + OFF_FFT, 256, 256);
    wsplit_conv<<<(256*1792 + 255)/256, blk>>>(conv_w, wh + OFF_CNV, wl + OFF_CNV);
    xsplit<<<RTOT * 256 / 1024, blk>>>(x, xh, xl);

    // Stage 1: spatial
    gemm_mma3<<<dim3(3, MB), blk, GSM>>>(xh, xl, wh + OFF_QKS, wl + OFF_QKS, bqk_s, bufB, RTOT, 384, 256);
    deint_s<<<RTOT * 384 / 256, blk>>>(bufB, h, y1);
    att_s_fast<<<NN * 3, 128>>>(h, y1, alphas, att0s, atts);
    ys2<<<NN * TT, blk>>>(x, atts, ah, al);
    gemm_mma3<<<dim3(2, MB), blk, GSM>>>(ah, al, wh + OFF_WOS, wl + OFF_WOS, bo_s, h, RTOT, 256, 768);
    ln2<<<NN*VV, blk>>>(h, x, g_os, b_os, y1, y1h, y1l, TT*256, 0, 0);
    gemm_mma3<<<dim3(2, MB), blk, GSM>>>(y1h, y1l, wh + OFF_FFS, wl + OFF_FFS, bff_s, h, RTOT, 256, 256);
    ln2<<<NN*VV, blk>>>(h, x, g_ffs, b_ffs, y2, y2h, y2l, TT*256, 1, 1);

    // Stage 2: temporal
    gemm_mma3<<<dim3(4, MB), blk, GSM>>>(y2h, y2l, wh + OFF_QKT, wl + OFF_QKT, bqk_t, bufB, RTOT, 512, 256);
    deint_t<<<RTOT * 512 / 256, blk>>>(bufB, h, y1);
    att_t_fast<<<NN * 4, blk>>>(h, y1, alphat_f, alphat_b, attf, attb);
    z2k<<<NN * VV, blk, (64*256 + 256) * 4>>>(y2, attf, attb, ah, al);
    gemm_mma3<<<dim3(2, MB), blk, GSM>>>(ah, al, wh + OFF_WOT, wl + OFF_WOT, bo_t, h, RTOT, 256, 1024);
    ln2<<<NN*TT, blk>>>(h, y2, g_ot, b_ot, y1, y1h, y1l, VV*256, 0, 0);
    gemm_mma3<<<dim3(2, MB), blk, GSM>>>(y1h, y1l, wh + OFF_FFT, wl + OFF_FFT, bff_t, h, RTOT, 256, 256);
    ln2<<<NN*TT, blk>>>(h, y2, g_fft, b_fft, z2b, z2h, z2l, VV*256, 0, 1);

    // Stage 3: conv + BN + gelu + transpose
    conv_mma3<<<dim3(2, MB), blk, GSM>>>(z2h, z2l, wh + OFF_CNV, wl + OFF_CNV, conv_b, h);
    final_kernel<<<RTOT, blk>>>(z2b, h, bn_g, bn_b, bn_m, bn_v, out);
}

// round 8
// speedup vs baseline: 2.5919x; 1.0006x over previous
#include <cuda_runtime.h>
#include <cuda_bf16.h>
#include <math.h>
#include <stdint.h>

#define NN 32
#define VV 25
#define TT 64
#define RTOT (NN*VV*TT)   /* 51200 */

// ------------------------- scratch (device globals) -------------------------
__device__ float g_bufB[(size_t)RTOT * 512];
__device__ float g_h   [(size_t)RTOT * 256];
__device__ float g_y1  [(size_t)RTOT * 256];
__device__ float g_y2  [(size_t)RTOT * 256];
__device__ float g_z2  [(size_t)RTOT * 256];
__device__ float g_atts[NN*VV*VV*3];
__device__ float g_attf[NN*TT*TT*2];   // transposed layout [n][q][t][s]
__device__ float g_attb[NN*TT*TT*2];
// bf16 split activation buffers (16B-aligned for cp.async)
__device__ __align__(128) __nv_bfloat16 g_ah [(size_t)RTOT * 1024];
__device__ __align__(128) __nv_bfloat16 g_al [(size_t)RTOT * 1024];
__device__ __align__(128) __nv_bfloat16 g_xh [(size_t)RTOT * 256];
__device__ __align__(128) __nv_bfloat16 g_xl [(size_t)RTOT * 256];
__device__ __align__(128) __nv_bfloat16 g_y1h[(size_t)RTOT * 256];
__device__ __align__(128) __nv_bfloat16 g_y1l[(size_t)RTOT * 256];
__device__ __align__(128) __nv_bfloat16 g_y2h[(size_t)RTOT * 256];
__device__ __align__(128) __nv_bfloat16 g_y2l[(size_t)RTOT * 256];
__device__ __align__(128) __nv_bfloat16 g_z2h[(size_t)RTOT * 256];
__device__ __align__(128) __nv_bfloat16 g_z2l[(size_t)RTOT * 256];
#define WTOT 1277952
__device__ __align__(128) __nv_bfloat16 g_wh[WTOT];
__device__ __align__(128) __nv_bfloat16 g_wl[WTOT];
#define OFF_QKS 0         /* K=256  N=384  */
#define OFF_WOS 98304     /* K=768  N=256  */
#define OFF_FFS 294912    /* K=256  N=256  */
#define OFF_QKT 360448    /* K=256  N=512  */
#define OFF_WOT 491520    /* K=1024 N=256  */
#define OFF_FFT 753664    /* K=256  N=256  */
#define OFF_CNV 819200    /* K=1792 N=256  */

__device__ __forceinline__ float gelu_f(float x) {
    return 0.5f * x * (1.0f + erff(x * 0.7071067811865475f));
}
__device__ __forceinline__ void split2(float a, float b, uint32_t &hi, uint32_t &lo) {
    __nv_bfloat16 ha = __float2bfloat16(a), hb = __float2bfloat16(b);
    float la = a - __bfloat162float(ha), lb = b - __bfloat162float(hb);
    __nv_bfloat16 l1 = __float2bfloat16(la), l2 = __float2bfloat16(lb);
    hi = (uint32_t)__bfloat16_as_ushort(ha) | ((uint32_t)__bfloat16_as_ushort(hb) << 16);
    lo = (uint32_t)__bfloat16_as_ushort(l1) | ((uint32_t)__bfloat16_as_ushort(l2) << 16);
}
__device__ __forceinline__ uint32_t smem_u32(const void* p) {
    uint32_t a;
    asm("{ .reg .u64 t; cvta.to.shared.u64 t, %1; cvt.u32.u64 %0, t; }" : "=r"(a) : "l"(p));
    return a;
}
__device__ __forceinline__ void ldm4(uint32_t &r0, uint32_t &r1, uint32_t &r2,
                                     uint32_t &r3, uint32_t a) {
    asm volatile("ldmatrix.sync.aligned.m8n8.x4.shared.b16 {%0,%1,%2,%3}, [%4];"
        : "=r"(r0), "=r"(r1), "=r"(r2), "=r"(r3) : "r"(a));
}
__device__ __forceinline__ void mma16816(float* c, const uint32_t* a, const uint32_t* b) {
    asm volatile(
        "mma.sync.aligned.m16n8k16.row.col.f32.bf16.bf16.f32 "
        "{%0,%1,%2,%3}, {%4,%5,%6,%7}, {%8,%9}, {%0,%1,%2,%3};"
        : "+f"(c[0]), "+f"(c[1]), "+f"(c[2]), "+f"(c[3])
        : "r"(a[0]), "r"(a[1]), "r"(a[2]), "r"(a[3]), "r"(b[0]), "r"(b[1]));
}
__device__ __forceinline__ void cpa16(uint32_t dst, const void* src) {
    asm volatile("cp.async.cg.shared.global [%0], [%1], 16;" :: "r"(dst), "l"(src));
}
__device__ __forceinline__ void cpa16z(uint32_t dst, const void* src, int sz) {
    asm volatile("cp.async.cg.shared.global [%0], [%1], 16, %2;" :: "r"(dst), "l"(src), "r"(sz));
}
#define CPA_COMMIT() asm volatile("cp.async.commit_group;" ::: "memory")
#define CPA_WAIT2() asm volatile("cp.async.wait_group 2;" ::: "memory")
#define CPA_WAIT1() asm volatile("cp.async.wait_group 1;" ::: "memory")
#define CPA_WAIT0() asm volatile("cp.async.wait_group 0;" ::: "memory")

// smem swizzle for 64B rows (32 bf16): 16B chunk ch of row r at (ch ^ ((r>>1)&3))*16
#define SWZ(row, ch) ((uint32_t)((row) * 64 + ((((ch) ^ (((row) >> 1) & 3))) << 4)))

// ========== HMMA GEMM: 128x128 tile, k-chunk 32, 3-stage, 2 CTA/SM ==========
#define GSM (3*32768)
__global__ __launch_bounds__(256, 2) void gemm_mma3(
        const __nv_bfloat16* __restrict__ Ah, const __nv_bfloat16* __restrict__ Al,
        const __nv_bfloat16* __restrict__ Bh, const __nv_bfloat16* __restrict__ Bl,
        const float* __restrict__ bias, float* __restrict__ C, int M, int N, int K) {
    extern __shared__ char sm[];
    const uint32_t sbase = smem_u32(sm);
    const int tid = threadIdx.x, lane = tid & 31, w = tid >> 5;
    const int wm = w & 3, wn = w >> 2;
    const int bm = blockIdx.y << 7, bn = blockIdx.x << 7;
    float acc[2][8][4];
#pragma unroll
    for (int i = 0; i < 2; i++)
#pragma unroll
        for (int j = 0; j < 8; j++)
#pragma unroll
            for (int q = 0; q < 4; q++) acc[i][j][q] = 0.f;
    const int nch = K >> 5;

    auto load_stage = [&](int c) {
        uint32_t st = sbase + (c % 3) * 32768;
        const int k0 = c << 5;
#pragma unroll
        for (int j = 0; j < 2; j++) {
            int f = j * 256 + tid;
            int row = f >> 2, ch = f & 3;
            uint32_t off = SWZ(row, ch);
            cpa16(st + off,         Ah + (size_t)(bm + row) * K + k0 + ch * 8);
            cpa16(st + 8192 + off,  Al + (size_t)(bm + row) * K + k0 + ch * 8);
            cpa16(st + 16384 + off, Bh + (size_t)(bn + row) * K + k0 + ch * 8);
            cpa16(st + 24576 + off, Bl + (size_t)(bn + row) * K + k0 + ch * 8);
        }
        CPA_COMMIT();
    };
    load_stage(0);
    load_stage(1);
    for (int c = 0; c < nch; c++) {
        if (c + 2 < nch) { load_stage(c + 2); CPA_WAIT2(); }
        else if (c + 1 < nch) CPA_WAIT1();
        else CPA_WAIT0();
        __syncthreads();
        const uint32_t sAh = sbase + (c % 3) * 32768;
        const uint32_t sAl = sAh + 8192, sBh = sAh + 16384, sBl = sAh + 24576;
#pragma unroll
        for (int kk = 0; kk < 2; kk++) {
            uint32_t ah[2][4], al[2][4];
            const int arow = wm * 32 + (lane & 15);
            const int achunk = kk * 2 + (lane >> 4);
#pragma unroll
            for (int mi = 0; mi < 2; mi++) {
                int row = arow + mi * 16;
                ldm4(ah[mi][0], ah[mi][1], ah[mi][2], ah[mi][3], sAh + SWZ(row, achunk));
                ldm4(al[mi][0], al[mi][1], al[mi][2], al[mi][3], sAl + SWZ(row, achunk));
            }
            const int bchunk = kk * 2 + ((lane >> 3) & 1);
#pragma unroll
            for (int half = 0; half < 2; half++) {
                uint32_t bh[4][2], bl[4][2];
#pragma unroll
                for (int p = 0; p < 2; p++) {
                    int brow = wn * 64 + half * 32 + p * 16 + ((lane & 16) >> 1) + (lane & 7);
                    ldm4(bh[2*p][0], bh[2*p][1], bh[2*p+1][0], bh[2*p+1][1],
                         sBh + SWZ(brow, bchunk));
                    ldm4(bl[2*p][0], bl[2*p][1], bl[2*p+1][0], bl[2*p+1][1],
                         sBl + SWZ(brow, bchunk));
                }
                // term-major: 8 independent accumulators between RAW reuses
#pragma unroll
                for (int mi = 0; mi < 2; mi++)
#pragma unroll
                    for (int nf = 0; nf < 4; nf++)
                        mma16816(acc[mi][half * 4 + nf], ah[mi], bh[nf]);
#pragma unroll
                for (int mi = 0; mi < 2; mi++)
#pragma unroll
                    for (int nf = 0; nf < 4; nf++)
                        mma16816(acc[mi][half * 4 + nf], ah[mi], bl[nf]);
#pragma unroll
                for (int mi = 0; mi < 2; mi++)
#pragma unroll
                    for (int nf = 0; nf < 4; nf++)
                        mma16816(acc[mi][half * 4 + nf], al[mi], bh[nf]);
            }
        }
        __syncthreads();
    }
    const int gid = lane >> 2, tig = lane & 3;
#pragma unroll
    for (int mi = 0; mi < 2; mi++)
#pragma unroll
        for (int nf = 0; nf < 8; nf++) {
            int col = bn + wn * 64 + nf * 8 + tig * 2;
            float b0v = bias[col], b1v = bias[col + 1];
            int r0 = bm + wm * 32 + mi * 16 + gid;
            *(float2*)(C + (size_t)r0 * N + col) =
                make_float2(acc[mi][nf][0] + b0v, acc[mi][nf][1] + b1v);
            *(float2*)(C + (size_t)(r0 + 8) * N + col) =
                make_float2(acc[mi][nf][2] + b0v, acc[mi][nf][3] + b1v);
        }
}

// ===== conv (implicit im2col) HMMA: K=1792, N=256, k-chunk 32, 3-stage ======
__global__ __launch_bounds__(256, 2) void conv_mma3(
        const __nv_bfloat16* __restrict__ Zh, const __nv_bfloat16* __restrict__ Zl,
        const __nv_bfloat16* __restrict__ Bh, const __nv_bfloat16* __restrict__ Bl,
        const float* __restrict__ bias, float* __restrict__ C) {
    const int N = 256, K = 1792;
    extern __shared__ char sm[];
    const uint32_t sbase = smem_u32(sm);
    const int tid = threadIdx.x, lane = tid & 31, w = tid >> 5;
    const int wm = w & 3, wn = w >> 2;
    const int bm = blockIdx.y << 7, bn = blockIdx.x << 7;
    float acc[2][8][4];
#pragma unroll
    for (int i = 0; i < 2; i++)
#pragma unroll
        for (int j = 0; j < 8; j++)
#pragma unroll
            for (int q = 0; q < 4; q++) acc[i][j][q] = 0.f;
    const int nch = K >> 5;   // 56

    auto load_stage = [&](int c) {
        uint32_t st = sbase + (c % 3) * 32768;
        const int k0 = c << 5;
        const int dt = (k0 >> 8) - 3;
        const int iio = k0 & 255;
#pragma unroll
        for (int j = 0; j < 2; j++) {
            int f = j * 256 + tid;
            int row = f >> 2, ch = f & 3;
            uint32_t off = SWZ(row, ch);
            int grow = bm + row;
            int t = (grow / VV) % TT;
            int tt = t + dt;
            int ok = (tt >= 0 && tt < TT);
            size_t srcoff = ok ? ((size_t)grow + (size_t)dt * VV) * 256 + iio + ch * 8 : 0;
            cpa16z(st + off,        Zh + srcoff, ok ? 16 : 0);
            cpa16z(st + 8192 + off, Zl + srcoff, ok ? 16 : 0);
            cpa16(st + 16384 + off, Bh + (size_t)(bn + row) * K + k0 + ch * 8);
            cpa16(st + 24576 + off, Bl + (size_t)(bn + row) * K + k0 + ch * 8);
        }
        CPA_COMMIT();
    };
    load_stage(0);
    load_stage(1);
    for (int c = 0; c < nch; c++) {
        if (c + 2 < nch) { load_stage(c + 2); CPA_WAIT2(); }
        else if (c + 1 < nch) CPA_WAIT1();
        else CPA_WAIT0();
        __syncthreads();
        const uint32_t sAh = sbase + (c % 3) * 32768;
        const uint32_t sAl = sAh + 8192, sBh = sAh + 16384, sBl = sAh + 24576;
#pragma unroll
        for (int kk = 0; kk < 2; kk++) {
            uint32_t ah[2][4], al[2][4];
            const int arow = wm * 32 + (lane & 15);
            const int achunk = kk * 2 + (lane >> 4);
#pragma unroll
            for (int mi = 0; mi < 2; mi++) {
                int row = arow + mi * 16;
                ldm4(ah[mi][0], ah[mi][1], ah[mi][2], ah[mi][3], sAh + SWZ(row, achunk));
                ldm4(al[mi][0], al[mi][1], al[mi][2], al[mi][3], sAl + SWZ(row, achunk));
            }
            const int bchunk = kk * 2 + ((lane >> 3) & 1);
#pragma unroll
            for (int half = 0; half < 2; half++) {
                uint32_t bh[4][2], bl[4][2];
#pragma unroll
                for (int p = 0; p < 2; p++) {
                    int brow = wn * 64 + half * 32 + p * 16 + ((lane & 16) >> 1) + (lane & 7);
                    ldm4(bh[2*p][0], bh[2*p][1], bh[2*p+1][0], bh[2*p+1][1],
                         sBh + SWZ(brow, bchunk));
                    ldm4(bl[2*p][0], bl[2*p][1], bl[2*p+1][0], bl[2*p+1][1],
                         sBl + SWZ(brow, bchunk));
                }
#pragma unroll
                for (int mi = 0; mi < 2; mi++)
#pragma unroll
                    for (int nf = 0; nf < 4; nf++)
                        mma16816(acc[mi][half * 4 + nf], ah[mi], bh[nf]);
#pragma unroll
                for (int mi = 0; mi < 2; mi++)
#pragma unroll
                    for (int nf = 0; nf < 4; nf++)
                        mma16816(acc[mi][half * 4 + nf], ah[mi], bl[nf]);
#pragma unroll
                for (int mi = 0; mi < 2; mi++)
#pragma unroll
                    for (int nf = 0; nf < 4; nf++)
                        mma16816(acc[mi][half * 4 + nf], al[mi], bh[nf]);
            }
        }
        __syncthreads();
    }
    const int gid = lane >> 2, tig = lane & 3;
#pragma unroll
    for (int mi = 0; mi < 2; mi++)
#pragma unroll
        for (int nf = 0; nf < 8; nf++) {
            int col = bn + wn * 64 + nf * 8 + tig * 2;
            float b0v = bias[col], b1v = bias[col + 1];
            int r0 = bm + wm * 32 + mi * 16 + gid;
            *(float2*)(C + (size_t)r0 * N + col) =
                make_float2(acc[mi][nf][0] + b0v, acc[mi][nf][1] + b1v);
            *(float2*)(C + (size_t)(r0 + 8) * N + col) =
                make_float2(acc[mi][nf][2] + b0v, acc[mi][nf][3] + b1v);
        }
}

// ============ ONE merged prep kernel: x split + all weight splits ============
// items [0, 3276800): xsplit vec4; items beyond: weight elems (concatenated).
#define XITEMS 3276800
__global__ void prep_all(
        const float* __restrict__ x,
        const float* __restrict__ Wqks, const float* __restrict__ Wos,
        const float* __restrict__ Wffs, const float* __restrict__ Wqkt,
        const float* __restrict__ Wot,  const float* __restrict__ Wfft,
        const float* __restrict__ Wcnv,
        __nv_bfloat16* __restrict__ xh, __nv_bfloat16* __restrict__ xl,
        __nv_bfloat16* __restrict__ wh, __nv_bfloat16* __restrict__ wl) {
    size_t idx = (size_t)blockIdx.x * 256 + threadIdx.x;
    if (idx < XITEMS) {
        size_t i = idx * 4;
        float4 v = *(const float4*)(x + i);
        uint32_t h0, l0, h1, l1;
        split2(v.x, v.y, h0, l0);
        split2(v.z, v.w, h1, l1);
        *(uint2*)(xh + i) = make_uint2(h0, h1);
        *(uint2*)(xl + i) = make_uint2(l0, l1);
        return;
    }
    long j = (long)(idx - XITEMS);
    const float* W; int K, N, off; int isconv = 0;
    if (j < 98304)                    { W = Wqks; K = 256;  N = 384; off = OFF_QKS; }
    else if ((j -= 98304)  < 196608)  { W = Wos;  K = 768;  N = 256; off = OFF_WOS; }
    else if ((j -= 196608) < 65536)   { W = Wffs; K = 256;  N = 256; off = OFF_FFS; }
    else if ((j -= 65536)  < 131072)  { W = Wqkt; K = 256;  N = 512; off = OFF_QKT; }
    else if ((j -= 131072) < 262144)  { W = Wot;  K = 1024; N = 256; off = OFF_WOT; }
    else if ((j -= 262144) < 65536)   { W = Wfft; K = 256;  N = 256; off = OFF_FFT; }
    else if ((j -= 65536)  < 458752)  { W = Wcnv; K = 1792; N = 256; off = OFF_CNV; isconv = 1; }
    else return;
    float v = W[j];
    __nv_bfloat16 h = __float2bfloat16(v);
    size_t dst;
    if (isconv) {
        int o = (int)(j / 1792), r = (int)(j % 1792);
        int ii = r / 7, kw = r % 7;
        dst = (size_t)off + (size_t)o * 1792 + kw * 256 + ii;
    } else {
        int k = (int)(j / N), n = (int)(j % N);
        dst = (size_t)off + (size_t)n * K + k;
    }
    wh[dst] = h;
    wl[dst] = __float2bfloat16(v - __bfloat162float(h));
}

// --------- de-interleave spatial qk -> qT,kT [(n*3+s)*25+u][4096] -----------
__global__ void deint_s(const float* __restrict__ qk, float* __restrict__ qT,
                        float* __restrict__ kT) {
    size_t idx = (size_t)blockIdx.x * 256 + threadIdx.x;
    int col = (int)(idx % 384);
    size_t row = idx / 384;
    int t = (int)(row % TT);
    size_t nu = row / TT;
    int n = (int)(nu / VV), u = (int)(nu % VV);
    int ci = col / 6, r = col % 6;
    float v = qk[idx];
    int s = (r < 3) ? r : r - 3;
    size_t dst = (((size_t)(n * 3 + s) * VV + u) << 12) + t * 64 + ci;
    if (r < 3) qT[dst] = v; else kT[dst] = v;
}

// spatial attention
__global__ __launch_bounds__(128) void att_s_fast(
        const float* __restrict__ qT, const float* __restrict__ kT,
        const float* __restrict__ alphas, const float* __restrict__ att0,
        float* __restrict__ att) {
    int ns = blockIdx.x, n = ns / 3, s = ns % 3;
    __shared__ float qs[25][132], ks[25][132];
    const float* qb = qT + ((size_t)ns * VV << 12);
    const float* kb = kT + ((size_t)ns * VV << 12);
    int t = threadIdx.x;
    int u0 = (t / 25) * 5, v = t % 25;
    float acc[5] = {0.f, 0.f, 0.f, 0.f, 0.f};
    for (int kc = 0; kc < 4096; kc += 128) {
        for (int i = t; i < 25 * 128; i += 128) {
            int uu = i >> 7, e = i & 127;
            qs[uu][e] = qb[((size_t)uu << 12) + kc + e];
            ks[uu][e] = kb[((size_t)uu << 12) + kc + e];
        }
        __syncthreads();
        if (t < 125) {
#pragma unroll 4
            for (int e = 0; e < 128; e++) {
                float kv = ks[v][e];
                acc[0] = fmaf(qs[u0 + 0][e], kv, acc[0]);
                acc[1] = fmaf(qs[u0 + 1][e], kv, acc[1]);
                acc[2] = fmaf(qs[u0 + 2][e], kv, acc[2]);
                acc[3] = fmaf(qs[u0 + 3][e], kv, acc[3]);
                acc[4] = fmaf(qs[u0 + 4][e], kv, acc[4]);
            }
        }
        __syncthreads();
    }
    if (t < 125) {
        float al = alphas[s];
#pragma unroll
        for (int i = 0; i < 5; i++) {
            int u = u0 + i;
            att[((size_t)(n * VV + u) * VV + v) * 3 + s] =
                tanhf(acc[i] * (1.f / 4096.f)) * al + att0[((size_t)u * VV + v) * 3 + s];
        }
    }
}

// y_s: block per (n,t); x slice in smem; bf16 split output (768-wide)
__global__ __launch_bounds__(256) void ys2(const float* __restrict__ x,
                                           const float* __restrict__ att,
                                           __nv_bfloat16* __restrict__ yh,
                                           __nv_bfloat16* __restrict__ yl) {
    __shared__ float xs[25][256];
    __shared__ float as_[25 * 25 * 3];
    int b = blockIdx.x;             // n*64 + t
    int n = b >> 6, t = b & 63;
    int tid = threadIdx.x;
    for (int i = tid; i < 25 * 256; i += 256) {
        int u = i >> 8, c = i & 255;
        xs[u][c] = x[((size_t)(n * VV + u) * TT + t) * 256 + c];
    }
    for (int i = tid; i < 1875; i += 256) as_[i] = att[(size_t)n * 1875 + i];
    __syncthreads();
    int c = tid;
#pragma unroll 1
    for (int v = 0; v < VV; v++) {
        float a0 = 0.f, a1 = 0.f, a2 = 0.f;
#pragma unroll
        for (int u = 0; u < VV; u++) {
            float xv = xs[u][c];
            a0 = fmaf(xv, as_[(u * VV + v) * 3 + 0], a0);
            a1 = fmaf(xv, as_[(u * VV + v) * 3 + 1], a1);
            a2 = fmaf(xv, as_[(u * VV + v) * 3 + 2], a2);
        }
        size_t base = ((size_t)(n * VV + v) * TT + t) * 768 + c * 3;
        __nv_bfloat16 h0 = __float2bfloat16(a0);
        __nv_bfloat16 h1 = __float2bfloat16(a1);
        __nv_bfloat16 h2 = __float2bfloat16(a2);
        yh[base] = h0; yh[base + 1] = h1; yh[base + 2] = h2;
        yl[base]     = __float2bfloat16(a0 - __bfloat162float(h0));
        yl[base + 1] = __float2bfloat16(a1 - __bfloat162float(h1));
        yl[base + 2] = __float2bfloat16(a2 - __bfloat162float(h2));
    }
}

// LN over group + residual + gelu; writes bf16 hi/lo (+ optional fp32)
__global__ void ln2(const float* __restrict__ h, const float* __restrict__ res,
                    const float* __restrict__ g, const float* __restrict__ b,
                    float* __restrict__ outf, __nv_bfloat16* __restrict__ oh,
                    __nv_bfloat16* __restrict__ ol, int G, int mode, int wf) {
    int grp = blockIdx.x;
    const float* hp = h + (size_t)grp * G;
    const float* rp = res + (size_t)grp * G;
    float s = 0.f, sq = 0.f;
    for (int i = threadIdx.x; i < G; i += blockDim.x) {
        float v = hp[i]; s += v; sq = fmaf(v, v, sq);
    }
    for (int o = 16; o; o >>= 1) {
        s += __shfl_down_sync(0xffffffffu, s, o);
        sq += __shfl_down_sync(0xffffffffu, sq, o);
    }
    __shared__ float ss[8], sqs[8];
    __shared__ float mean_s, inv_s;
    int w = threadIdx.x >> 5;
    if ((threadIdx.x & 31) == 0) { ss[w] = s; sqs[w] = sq; }
    __syncthreads();
    if (threadIdx.x == 0) {
        float S = 0.f, Q = 0.f;
        for (int i = 0; i < 8; i++) { S += ss[i]; Q += sqs[i]; }
        float mean = S / G;
        float var = Q / G - mean * mean;
        mean_s = mean; inv_s = rsqrtf(var + 1e-5f);
    }
    __syncthreads();
    float mean = mean_s, inv = inv_s;
    int n = 0, v = 0;
    if (mode == 1) { n = grp / VV; v = grp % VV; }
    for (int i = threadIdx.x; i < G; i += blockDim.x) {
        float val = gelu_f(rp[i] + fmaf((hp[i] - mean) * inv, g[i], b[i]));
        size_t dst;
        if (mode == 0) dst = (size_t)grp * G + i;
        else {
            int t = i >> 8, c = i & 255;
            dst = ((size_t)(n * TT + t) * VV + v) * 256 + c;
        }
        if (wf) outf[dst] = val;
        __nv_bfloat16 hi = __float2bfloat16(val);
        oh[dst] = hi;
        ol[dst] = __float2bfloat16(val - __bfloat162float(hi));
    }
}

// --------- de-interleave temporal qkt -> qd,kd [(n*4+m)][t][1600] -----------
__global__ void deint_t(const float* __restrict__ qkt, float* __restrict__ qd,
                        float* __restrict__ kd) {
    size_t idx = (size_t)blockIdx.x * 256 + threadIdx.x;
    int col = (int)(idx & 511);
    size_t row = idx >> 9;
    int v = (int)(row % VV);
    size_t nt = row / VV;
    int t = (int)(nt % TT), n = (int)(nt / TT);
    int ci = col >> 3, j = col & 7;
    float val = qkt[idx];
    int m = (j < 4) ? j : j - 4;
    size_t dst = ((size_t)(n * 4 + m) * TT + t) * 1600 + v * 64 + ci;
    if (j < 4) qd[dst] = val; else kd[dst] = val;
}

// temporal attention -> TRANSPOSED layout att[n][q][t][s]
__global__ __launch_bounds__(256) void att_t_fast(
        const float* __restrict__ qd, const float* __restrict__ kd,
        const float* __restrict__ alf, const float* __restrict__ alb,
        float* __restrict__ attf, float* __restrict__ attb) {
    int nm = blockIdx.x, n = nm >> 2, m = nm & 3;
    int s = m & 1, dir = m >> 1;
    __shared__ float Qs[64][68], Ks[64][68];
    const float* qb = qd + (size_t)nm * TT * 1600;
    const float* kb = kd + (size_t)nm * TT * 1600;
    const int tid = threadIdx.x;
    const int tx = tid & 15, ty = tid >> 4;
    const int lr = tid >> 2, lc = (tid & 3) << 4;
    float acc[4][4] = {};
    for (int kc = 0; kc < 1600; kc += 64) {
#pragma unroll
        for (int j = 0; j < 4; j++) {
            float4 q4 = *(const float4*)(qb + (size_t)lr * 1600 + kc + lc + j * 4);
            float4 k4 = *(const float4*)(kb + (size_t)lr * 1600 + kc + lc + j * 4);
            Qs[lc + j*4 + 0][lr] = q4.x; Qs[lc + j*4 + 1][lr] = q4.y;
            Qs[lc + j*4 + 2][lr] = q4.z; Qs[lc + j*4 + 3][lr] = q4.w;
            Ks[lc + j*4 + 0][lr] = k4.x; Ks[lc + j*4 + 1][lr] = k4.y;
            Ks[lc + j*4 + 2][lr] = k4.z; Ks[lc + j*4 + 3][lr] = k4.w;
        }
        __syncthreads();
#pragma unroll 8
        for (int kk = 0; kk < 64; kk++) {
            float4 aq = *(const float4*)(&Qs[kk][ty << 2]);
            float4 bk = *(const float4*)(&Ks[kk][tx << 2]);
            float a[4] = {aq.x, aq.y, aq.z, aq.w};
            float b[4] = {bk.x, bk.y, bk.z, bk.w};
#pragma unroll
            for (int i = 0; i < 4; i++)
#pragma unroll
                for (int j = 0; j < 4; j++) acc[i][j] = fmaf(a[i], b[j], acc[i][j]);
        }
        __syncthreads();
    }
    float al = dir ? alb[s] : alf[s];
#pragma unroll
    for (int i = 0; i < 4; i++) {
#pragma unroll
        for (int j = 0; j < 4; j++) {
            int t_ = (ty << 2) + i, q_ = (tx << 2) + j;
            float val = tanhf(acc[i][j] * (1.f / 1600.f)) * al;
            size_t idx = ((size_t)(n * TT + q_) * TT + t_) * 2 + s;   // [n][q][t][s]
            if (dir == 0) attf[idx] = (q_ <= t_) ? val : 0.f;
            else          attb[idx] = (q_ >= t_) ? val : 0.f;
        }
    }
}

// z apply: block per (n,v); y2 slice in smem; bf16 split output (1024-wide)
__global__ __launch_bounds__(256) void z2k(const float* __restrict__ y2t,
                                           const float* __restrict__ attf,
                                           const float* __restrict__ attb,
                                           __nv_bfloat16* __restrict__ zh,
                                           __nv_bfloat16* __restrict__ zl) {
    extern __shared__ float zs[];          // 64*256 + 256
    float* ys = zs;
    float* as_ = zs + 64 * 256;
    int b = blockIdx.x;                    // n*25 + v
    int n = b / VV, v = b % VV;
    int tid = threadIdx.x;
    for (int i = tid; i < 64 * 256; i += 256) {
        int t = i >> 8, c = i & 255;
        ys[t * 256 + c] = y2t[((size_t)(n * TT + t) * VV + v) * 256 + c];
    }
    __syncthreads();
    int c = tid;
    for (int q = 0; q < TT; q++) {
        if (tid < 128) as_[tid] = attf[(size_t)n * 8192 + q * 128 + tid];
        else           as_[tid] = attb[(size_t)n * 8192 + q * 128 + (tid - 128)];
        __syncthreads();
        float f0 = 0.f, f1 = 0.f, b0 = 0.f, b1 = 0.f;
#pragma unroll 8
        for (int t = 0; t < TT; t++) {
            float yv = ys[t * 256 + c];
            f0 = fmaf(yv, as_[t * 2], f0);       f1 = fmaf(yv, as_[t * 2 + 1], f1);
            b0 = fmaf(yv, as_[128 + t * 2], b0); b1 = fmaf(yv, as_[128 + t * 2 + 1], b1);
        }
        size_t base = ((size_t)(n * TT + q) * VV + v) * 1024;
        uint32_t hf, lf, hb, lb;
        split2(f0, f1, hf, lf);
        split2(b0, b1, hb, lb);
        *(uint32_t*)(zh + base + c * 2) = hf;
        *(uint32_t*)(zl + base + c * 2) = lf;
        *(uint32_t*)(zh + base + 512 + c * 2) = hb;
        *(uint32_t*)(zl + base + 512 + c * 2) = lb;
        __syncthreads();
    }
}

__global__ void final_kernel(const float* __restrict__ z2, const float* __restrict__ cv,
                             const float* __restrict__ bn_g, const float* __restrict__ bn_b,
                             const float* __restrict__ bn_m, const float* __restrict__ bn_v,
                             float* __restrict__ out) {
    size_t i = (size_t)blockIdx.x * 256 + threadIdx.x;
    int o = (int)(i & 255);
    size_t r = i >> 8;
    int v = (int)(r % VV);
    size_t r2 = r / VV;
    int t = (int)(r2 % TT);
    int n = (int)(r2 / TT);
    float c1 = fmaf((cv[i] - bn_m[o]) * rsqrtf(bn_v[o] + 1e-5f), bn_g[o], bn_b[o]);
    out[((size_t)(n * VV + v) * TT + t) * 256 + o] = gelu_f(z2[i] + c1);
}

// ------------------------------- launcher -----------------------------------
extern "C" void kernel_launch(void* const* d_in, const int* in_sizes, int n_in,
                              void* d_out, int out_size) {
    const float* x       = (const float*)d_in[0];
    const float* Wqk_s   = (const float*)d_in[1];
    const float* bqk_s   = (const float*)d_in[2];
    const float* alphas  = (const float*)d_in[3];
    const float* att0s   = (const float*)d_in[4];
    const float* Wo_s    = (const float*)d_in[5];
    const float* bo_s    = (const float*)d_in[6];
    const float* g_os    = (const float*)d_in[7];
    const float* b_os    = (const float*)d_in[8];
    const float* Wff_s   = (const float*)d_in[9];
    const float* bff_s   = (const float*)d_in[10];
    const float* g_ffs   = (const float*)d_in[11];
    const float* b_ffs   = (const float*)d_in[12];
    const float* Wqk_t   = (const float*)d_in[13];
    const float* bqk_t   = (const float*)d_in[14];
    const float* alphat_f= (const float*)d_in[15];
    const float* alphat_b= (const float*)d_in[16];
    const float* Wo_t    = (const float*)d_in[17];
    const float* bo_t    = (const float*)d_in[18];
    const float* g_ot    = (const float*)d_in[19];
    const float* b_ot    = (const float*)d_in[20];
    const float* Wff_t   = (const float*)d_in[21];
    const float* bff_t   = (const float*)d_in[22];
    const float* g_fft   = (const float*)d_in[23];
    const float* b_fft   = (const float*)d_in[24];
    const float* conv_w  = (const float*)d_in[25];
    const float* conv_b  = (const float*)d_in[26];
    const float* bn_g    = (const float*)d_in[27];
    const float* bn_b    = (const float*)d_in[28];
    const float* bn_m    = (const float*)d_in[29];
    const float* bn_v    = (const float*)d_in[30];
    float* out = (float*)d_out;

    void *pB, *pH, *pY1, *pY2, *pZ2, *pAS, *pAF, *pAB, *pWH, *pWL;
    void *pAH, *pAL, *pXH, *pXL, *pY1H, *pY1L, *pY2H, *pY2L, *pZ2H, *pZ2L;
    cudaGetSymbolAddress(&pB,  g_bufB);
    cudaGetSymbolAddress(&pH,  g_h);
    cudaGetSymbolAddress(&pY1, g_y1);
    cudaGetSymbolAddress(&pY2, g_y2);
    cudaGetSymbolAddress(&pZ2, g_z2);
    cudaGetSymbolAddress(&pAS, g_atts);
    cudaGetSymbolAddress(&pAF, g_attf);
    cudaGetSymbolAddress(&pAB, g_attb);
    cudaGetSymbolAddress(&pWH, g_wh);
    cudaGetSymbolAddress(&pWL, g_wl);
    cudaGetSymbolAddress(&pAH, g_ah);
    cudaGetSymbolAddress(&pAL, g_al);
    cudaGetSymbolAddress(&pXH, g_xh);
    cudaGetSymbolAddress(&pXL, g_xl);
    cudaGetSymbolAddress(&pY1H, g_y1h);
    cudaGetSymbolAddress(&pY1L, g_y1l);
    cudaGetSymbolAddress(&pY2H, g_y2h);
    cudaGetSymbolAddress(&pY2L, g_y2l);
    cudaGetSymbolAddress(&pZ2H, g_z2h);
    cudaGetSymbolAddress(&pZ2L, g_z2l);
    float* bufB = (float*)pB;
    float* h    = (float*)pH;  float* y1   = (float*)pY1;
    float* y2   = (float*)pY2; float* z2b  = (float*)pZ2;
    float* atts = (float*)pAS; float* attf = (float*)pAF;
    float* attb = (float*)pAB;
    __nv_bfloat16* wh = (__nv_bfloat16*)pWH;
    __nv_bfloat16* wl = (__nv_bfloat16*)pWL;
    __nv_bfloat16* ah = (__nv_bfloat16*)pAH;
    __nv_bfloat16* al = (__nv_bfloat16*)pAL;
    __nv_bfloat16* xh = (__nv_bfloat16*)pXH;
    __nv_bfloat16* xl = (__nv_bfloat16*)pXL;
    __nv_bfloat16* y1h = (__nv_bfloat16*)pY1H;
    __nv_bfloat16* y1l = (__nv_bfloat16*)pY1L;
    __nv_bfloat16* y2h = (__nv_bfloat16*)pY2H;
    __nv_bfloat16* y2l = (__nv_bfloat16*)pY2L;
    __nv_bfloat16* z2h = (__nv_bfloat16*)pZ2H;
    __nv_bfloat16* z2l = (__nv_bfloat16*)pZ2L;

    cudaFuncSetAttribute(gemm_mma3, cudaFuncAttributeMaxDynamicSharedMemorySize, GSM);
    cudaFuncSetAttribute(conv_mma3, cudaFuncAttributeMaxDynamicSharedMemorySize, GSM);
    cudaFuncSetAttribute(z2k, cudaFuncAttributeMaxDynamicSharedMemorySize, (64*256 + 256) * 4);

    dim3 blk(256);
    const int MB = RTOT / 128;   // 400

    // merged prep: x split + all weight splits (ONE launch)
    prep_all<<<(XITEMS + WTOT + 255) / 256, blk>>>(
        x, Wqk_s, Wo_s, Wff_s, Wqk_t, Wo_t, Wff_t, conv_w, xh, xl, wh, wl);

    // Stage 1: spatial
    gemm_mma3<<<dim3(3, MB), blk, GSM>>>(xh, xl, wh + OFF_QKS, wl + OFF_QKS, bqk_s, bufB, RTOT, 384, 256);
    deint_s<<<RTOT * 384 / 256, blk>>>(bufB, h, y1);
    att_s_fast<<<NN * 3, 128>>>(h, y1, alphas, att0s, atts);
    ys2<<<NN * TT, blk>>>(x, atts, ah, al);
    gemm_mma3<<<dim3(2, MB), blk, GSM>>>(ah, al, wh + OFF_WOS, wl + OFF_WOS, bo_s, h, RTOT, 256, 768);
    ln2<<<NN*VV, blk>>>(h, x, g_os, b_os, y1, y1h, y1l, TT*256, 0, 0);
    gemm_mma3<<<dim3(2, MB), blk, GSM>>>(y1h, y1l, wh + OFF_FFS, wl + OFF_FFS, bff_s, h, RTOT, 256, 256);
    ln2<<<NN*VV, blk>>>(h, x, g_ffs, b_ffs, y2, y2h, y2l, TT*256, 1, 1);

    // Stage 2: temporal
    gemm_mma3<<<dim3(4, MB), blk, GSM>>>(y2h, y2l, wh + OFF_QKT, wl + OFF_QKT, bqk_t, bufB, RTOT, 512, 256);
    deint_t<<<RTOT * 512 / 256, blk>>>(bufB, h, y1);
    att_t_fast<<<NN * 4, blk>>>(h, y1, alphat_f, alphat_b, attf, attb);
    z2k<<<NN * VV, blk, (64*256 + 256) * 4>>>(y2, attf, attb, ah, al);
    gemm_mma3<<<dim3(2, MB), blk, GSM>>>(ah, al, wh + OFF_WOT, wl + OFF_WOT, bo_t, h, RTOT, 256, 1024);
    ln2<<<NN*TT, blk>>>(h, y2, g_ot, b_ot, y1, y1h, y1l, VV*256, 0, 0);
    gemm_mma3<<<dim3(2, MB), blk, GSM>>>(y1h, y1l, wh + OFF_FFT, wl + OFF_FFT, bff_t, h, RTOT, 256, 256);
    ln2<<<NN*TT, blk>>>(h, y2, g_fft, b_fft, z2b, z2h, z2l, VV*256, 0, 1);

    // Stage 3: conv + BN + gelu + transpose
    conv_mma3<<<dim3(2, MB), blk, GSM>>>(z2h, z2l, wh + OFF_CNV, wl + OFF_CNV, conv_b, h);
    final_kernel<<<RTOT, blk>>>(z2b, h, bn_g, bn_b, bn_m, bn_v, out);
}

// round 9
// speedup vs baseline: 2.7996x; 1.0801x over previous
#include <cuda_runtime.h>
#include <cuda_bf16.h>
#include <math.h>
#include <stdint.h>

#define NN 32
#define VV 25
#define TT 64
#define RTOT (NN*VV*TT)   /* 51200 */

// ------------------------- scratch (device globals) -------------------------
__device__ float g_bufB[(size_t)RTOT * 512];
__device__ float g_h   [(size_t)RTOT * 256];
__device__ float g_y1  [(size_t)RTOT * 256];
__device__ float g_y2  [(size_t)RTOT * 256];
__device__ float g_z2  [(size_t)RTOT * 256];
__device__ float g_atts[NN*VV*VV*3];
__device__ float g_attf[NN*TT*TT*2];   // transposed layout [n][q][t][s]
__device__ float g_attb[NN*TT*TT*2];
__device__ float g_ps  [96*625];       // spatial attention partials
__device__ float g_pt  [128*64*64];    // temporal attention partials
// bf16 split activation buffers (16B-aligned for cp.async)
__device__ __align__(128) __nv_bfloat16 g_ah [(size_t)RTOT * 1024];
__device__ __align__(128) __nv_bfloat16 g_al [(size_t)RTOT * 1024];
__device__ __align__(128) __nv_bfloat16 g_xh [(size_t)RTOT * 256];
__device__ __align__(128) __nv_bfloat16 g_xl [(size_t)RTOT * 256];
__device__ __align__(128) __nv_bfloat16 g_y1h[(size_t)RTOT * 256];
__device__ __align__(128) __nv_bfloat16 g_y1l[(size_t)RTOT * 256];
__device__ __align__(128) __nv_bfloat16 g_y2h[(size_t)RTOT * 256];
__device__ __align__(128) __nv_bfloat16 g_y2l[(size_t)RTOT * 256];
__device__ __align__(128) __nv_bfloat16 g_z2h[(size_t)RTOT * 256];
__device__ __align__(128) __nv_bfloat16 g_z2l[(size_t)RTOT * 256];
#define WTOT 1277952
__device__ __align__(128) __nv_bfloat16 g_wh[WTOT];
__device__ __align__(128) __nv_bfloat16 g_wl[WTOT];
#define OFF_QKS 0         /* K=256  N=384  */
#define OFF_WOS 98304     /* K=768  N=256  */
#define OFF_FFS 294912    /* K=256  N=256  */
#define OFF_QKT 360448    /* K=256  N=512  */
#define OFF_WOT 491520    /* K=1024 N=256  */
#define OFF_FFT 753664    /* K=256  N=256  */
#define OFF_CNV 819200    /* K=1792 N=256  */

__device__ __forceinline__ float gelu_f(float x) {
    return 0.5f * x * (1.0f + erff(x * 0.7071067811865475f));
}
__device__ __forceinline__ void split2(float a, float b, uint32_t &hi, uint32_t &lo) {
    __nv_bfloat16 ha = __float2bfloat16(a), hb = __float2bfloat16(b);
    float la = a - __bfloat162float(ha), lb = b - __bfloat162float(hb);
    __nv_bfloat16 l1 = __float2bfloat16(la), l2 = __float2bfloat16(lb);
    hi = (uint32_t)__bfloat16_as_ushort(ha) | ((uint32_t)__bfloat16_as_ushort(hb) << 16);
    lo = (uint32_t)__bfloat16_as_ushort(l1) | ((uint32_t)__bfloat16_as_ushort(l2) << 16);
}
__device__ __forceinline__ uint32_t smem_u32(const void* p) {
    uint32_t a;
    asm("{ .reg .u64 t; cvta.to.shared.u64 t, %1; cvt.u32.u64 %0, t; }" : "=r"(a) : "l"(p));
    return a;
}
__device__ __forceinline__ void ldm4(uint32_t &r0, uint32_t &r1, uint32_t &r2,
                                     uint32_t &r3, uint32_t a) {
    asm volatile("ldmatrix.sync.aligned.m8n8.x4.shared.b16 {%0,%1,%2,%3}, [%4];"
        : "=r"(r0), "=r"(r1), "=r"(r2), "=r"(r3) : "r"(a));
}
__device__ __forceinline__ void mma16816(float* c, const uint32_t* a, const uint32_t* b) {
    asm volatile(
        "mma.sync.aligned.m16n8k16.row.col.f32.bf16.bf16.f32 "
        "{%0,%1,%2,%3}, {%4,%5,%6,%7}, {%8,%9}, {%0,%1,%2,%3};"
        : "+f"(c[0]), "+f"(c[1]), "+f"(c[2]), "+f"(c[3])
        : "r"(a[0]), "r"(a[1]), "r"(a[2]), "r"(a[3]), "r"(b[0]), "r"(b[1]));
}
__device__ __forceinline__ void cpa16(uint32_t dst, const void* src) {
    asm volatile("cp.async.cg.shared.global [%0], [%1], 16;" :: "r"(dst), "l"(src));
}
__device__ __forceinline__ void cpa16z(uint32_t dst, const void* src, int sz) {
    asm volatile("cp.async.cg.shared.global [%0], [%1], 16, %2;" :: "r"(dst), "l"(src), "r"(sz));
}
#define CPA_COMMIT() asm volatile("cp.async.commit_group;" ::: "memory")
#define CPA_WAIT2() asm volatile("cp.async.wait_group 2;" ::: "memory")
#define CPA_WAIT1() asm volatile("cp.async.wait_group 1;" ::: "memory")
#define CPA_WAIT0() asm volatile("cp.async.wait_group 0;" ::: "memory")

// smem swizzle for 64B rows (32 bf16): 16B chunk ch of row r at (ch ^ ((r>>1)&3))*16
#define SWZ(row, ch) ((uint32_t)((row) * 64 + ((((ch) ^ (((row) >> 1) & 3))) << 4)))

// ========== HMMA GEMM: 128x128 tile, k-chunk 32, 3-stage, 2 CTA/SM ==========
#define GSM (3*32768)
__global__ __launch_bounds__(256, 2) void gemm_mma3(
        const __nv_bfloat16* __restrict__ Ah, const __nv_bfloat16* __restrict__ Al,
        const __nv_bfloat16* __restrict__ Bh, const __nv_bfloat16* __restrict__ Bl,
        const float* __restrict__ bias, float* __restrict__ C, int M, int N, int K) {
    extern __shared__ char sm[];
    const uint32_t sbase = smem_u32(sm);
    const int tid = threadIdx.x, lane = tid & 31, w = tid >> 5;
    const int wm = w & 3, wn = w >> 2;
    const int bm = blockIdx.y << 7, bn = blockIdx.x << 7;
    float acc[2][8][4];
#pragma unroll
    for (int i = 0; i < 2; i++)
#pragma unroll
        for (int j = 0; j < 8; j++)
#pragma unroll
            for (int q = 0; q < 4; q++) acc[i][j][q] = 0.f;
    const int nch = K >> 5;

    auto load_stage = [&](int c) {
        uint32_t st = sbase + (c % 3) * 32768;
        const int k0 = c << 5;
#pragma unroll
        for (int j = 0; j < 2; j++) {
            int f = j * 256 + tid;
            int row = f >> 2, ch = f & 3;
            uint32_t off = SWZ(row, ch);
            cpa16(st + off,         Ah + (size_t)(bm + row) * K + k0 + ch * 8);
            cpa16(st + 8192 + off,  Al + (size_t)(bm + row) * K + k0 + ch * 8);
            cpa16(st + 16384 + off, Bh + (size_t)(bn + row) * K + k0 + ch * 8);
            cpa16(st + 24576 + off, Bl + (size_t)(bn + row) * K + k0 + ch * 8);
        }
        CPA_COMMIT();
    };
    load_stage(0);
    load_stage(1);
    for (int c = 0; c < nch; c++) {
        if (c + 2 < nch) { load_stage(c + 2); CPA_WAIT2(); }
        else if (c + 1 < nch) CPA_WAIT1();
        else CPA_WAIT0();
        __syncthreads();
        const uint32_t sAh = sbase + (c % 3) * 32768;
        const uint32_t sAl = sAh + 8192, sBh = sAh + 16384, sBl = sAh + 24576;
#pragma unroll
        for (int kk = 0; kk < 2; kk++) {
            uint32_t ah[2][4], al[2][4];
            const int arow = wm * 32 + (lane & 15);
            const int achunk = kk * 2 + (lane >> 4);
#pragma unroll
            for (int mi = 0; mi < 2; mi++) {
                int row = arow + mi * 16;
                ldm4(ah[mi][0], ah[mi][1], ah[mi][2], ah[mi][3], sAh + SWZ(row, achunk));
                ldm4(al[mi][0], al[mi][1], al[mi][2], al[mi][3], sAl + SWZ(row, achunk));
            }
            const int bchunk = kk * 2 + ((lane >> 3) & 1);
#pragma unroll
            for (int half = 0; half < 2; half++) {
                uint32_t bh[4][2], bl[4][2];
#pragma unroll
                for (int p = 0; p < 2; p++) {
                    int brow = wn * 64 + half * 32 + p * 16 + ((lane & 16) >> 1) + (lane & 7);
                    ldm4(bh[2*p][0], bh[2*p][1], bh[2*p+1][0], bh[2*p+1][1],
                         sBh + SWZ(brow, bchunk));
                    ldm4(bl[2*p][0], bl[2*p][1], bl[2*p+1][0], bl[2*p+1][1],
                         sBl + SWZ(brow, bchunk));
                }
#pragma unroll
                for (int mi = 0; mi < 2; mi++)
#pragma unroll
                    for (int nf = 0; nf < 4; nf++)
                        mma16816(acc[mi][half * 4 + nf], ah[mi], bh[nf]);
#pragma unroll
                for (int mi = 0; mi < 2; mi++)
#pragma unroll
                    for (int nf = 0; nf < 4; nf++)
                        mma16816(acc[mi][half * 4 + nf], ah[mi], bl[nf]);
#pragma unroll
                for (int mi = 0; mi < 2; mi++)
#pragma unroll
                    for (int nf = 0; nf < 4; nf++)
                        mma16816(acc[mi][half * 4 + nf], al[mi], bh[nf]);
            }
        }
        __syncthreads();
    }
    const int gid = lane >> 2, tig = lane & 3;
#pragma unroll
    for (int mi = 0; mi < 2; mi++)
#pragma unroll
        for (int nf = 0; nf < 8; nf++) {
            int col = bn + wn * 64 + nf * 8 + tig * 2;
            float b0v = bias[col], b1v = bias[col + 1];
            int r0 = bm + wm * 32 + mi * 16 + gid;
            *(float2*)(C + (size_t)r0 * N + col) =
                make_float2(acc[mi][nf][0] + b0v, acc[mi][nf][1] + b1v);
            *(float2*)(C + (size_t)(r0 + 8) * N + col) =
                make_float2(acc[mi][nf][2] + b0v, acc[mi][nf][3] + b1v);
        }
}

// ===== conv (implicit im2col) HMMA: K=1792, N=256, k-chunk 32, 3-stage ======
__global__ __launch_bounds__(256, 2) void conv_mma3(
        const __nv_bfloat16* __restrict__ Zh, const __nv_bfloat16* __restrict__ Zl,
        const __nv_bfloat16* __restrict__ Bh, const __nv_bfloat16* __restrict__ Bl,
        const float* __restrict__ bias, float* __restrict__ C) {
    const int N = 256, K = 1792;
    extern __shared__ char sm[];
    const uint32_t sbase = smem_u32(sm);
    const int tid = threadIdx.x, lane = tid & 31, w = tid >> 5;
    const int wm = w & 3, wn = w >> 2;
    const int bm = blockIdx.y << 7, bn = blockIdx.x << 7;
    float acc[2][8][4];
#pragma unroll
    for (int i = 0; i < 2; i++)
#pragma unroll
        for (int j = 0; j < 8; j++)
#pragma unroll
            for (int q = 0; q < 4; q++) acc[i][j][q] = 0.f;
    const int nch = K >> 5;   // 56

    auto load_stage = [&](int c) {
        uint32_t st = sbase + (c % 3) * 32768;
        const int k0 = c << 5;
        const int dt = (k0 >> 8) - 3;
        const int iio = k0 & 255;
#pragma unroll
        for (int j = 0; j < 2; j++) {
            int f = j * 256 + tid;
            int row = f >> 2, ch = f & 3;
            uint32_t off = SWZ(row, ch);
            int grow = bm + row;
            int t = (grow / VV) % TT;
            int tt = t + dt;
            int ok = (tt >= 0 && tt < TT);
            size_t srcoff = ok ? ((size_t)grow + (size_t)dt * VV) * 256 + iio + ch * 8 : 0;
            cpa16z(st + off,        Zh + srcoff, ok ? 16 : 0);
            cpa16z(st + 8192 + off, Zl + srcoff, ok ? 16 : 0);
            cpa16(st + 16384 + off, Bh + (size_t)(bn + row) * K + k0 + ch * 8);
            cpa16(st + 24576 + off, Bl + (size_t)(bn + row) * K + k0 + ch * 8);
        }
        CPA_COMMIT();
    };
    load_stage(0);
    load_stage(1);
    for (int c = 0; c < nch; c++) {
        if (c + 2 < nch) { load_stage(c + 2); CPA_WAIT2(); }
        else if (c + 1 < nch) CPA_WAIT1();
        else CPA_WAIT0();
        __syncthreads();
        const uint32_t sAh = sbase + (c % 3) * 32768;
        const uint32_t sAl = sAh + 8192, sBh = sAh + 16384, sBl = sAh + 24576;
#pragma unroll
        for (int kk = 0; kk < 2; kk++) {
            uint32_t ah[2][4], al[2][4];
            const int arow = wm * 32 + (lane & 15);
            const int achunk = kk * 2 + (lane >> 4);
#pragma unroll
            for (int mi = 0; mi < 2; mi++) {
                int row = arow + mi * 16;
                ldm4(ah[mi][0], ah[mi][1], ah[mi][2], ah[mi][3], sAh + SWZ(row, achunk));
                ldm4(al[mi][0], al[mi][1], al[mi][2], al[mi][3], sAl + SWZ(row, achunk));
            }
            const int bchunk = kk * 2 + ((lane >> 3) & 1);
#pragma unroll
            for (int half = 0; half < 2; half++) {
                uint32_t bh[4][2], bl[4][2];
#pragma unroll
                for (int p = 0; p < 2; p++) {
                    int brow = wn * 64 + half * 32 + p * 16 + ((lane & 16) >> 1) + (lane & 7);
                    ldm4(bh[2*p][0], bh[2*p][1], bh[2*p+1][0], bh[2*p+1][1],
                         sBh + SWZ(brow, bchunk));
                    ldm4(bl[2*p][0], bl[2*p][1], bl[2*p+1][0], bl[2*p+1][1],
                         sBl + SWZ(brow, bchunk));
                }
#pragma unroll
                for (int mi = 0; mi < 2; mi++)
#pragma unroll
                    for (int nf = 0; nf < 4; nf++)
                        mma16816(acc[mi][half * 4 + nf], ah[mi], bh[nf]);
#pragma unroll
                for (int mi = 0; mi < 2; mi++)
#pragma unroll
                    for (int nf = 0; nf < 4; nf++)
                        mma16816(acc[mi][half * 4 + nf], ah[mi], bl[nf]);
#pragma unroll
                for (int mi = 0; mi < 2; mi++)
#pragma unroll
                    for (int nf = 0; nf < 4; nf++)
                        mma16816(acc[mi][half * 4 + nf], al[mi], bh[nf]);
            }
        }
        __syncthreads();
    }
    const int gid = lane >> 2, tig = lane & 3;
#pragma unroll
    for (int mi = 0; mi < 2; mi++)
#pragma unroll
        for (int nf = 0; nf < 8; nf++) {
            int col = bn + wn * 64 + nf * 8 + tig * 2;
            float b0v = bias[col], b1v = bias[col + 1];
            int r0 = bm + wm * 32 + mi * 16 + gid;
            *(float2*)(C + (size_t)r0 * N + col) =
                make_float2(acc[mi][nf][0] + b0v, acc[mi][nf][1] + b1v);
            *(float2*)(C + (size_t)(r0 + 8) * N + col) =
                make_float2(acc[mi][nf][2] + b0v, acc[mi][nf][3] + b1v);
        }
}

// ============ ONE merged prep kernel: x split + all weight splits ============
#define XITEMS 3276800
__global__ void prep_all(
        const float* __restrict__ x,
        const float* __restrict__ Wqks, const float* __restrict__ Wos,
        const float* __restrict__ Wffs, const float* __restrict__ Wqkt,
        const float* __restrict__ Wot,  const float* __restrict__ Wfft,
        const float* __restrict__ Wcnv,
        __nv_bfloat16* __restrict__ xh, __nv_bfloat16* __restrict__ xl,
        __nv_bfloat16* __restrict__ wh, __nv_bfloat16* __restrict__ wl) {
    size_t idx = (size_t)blockIdx.x * 256 + threadIdx.x;
    if (idx < XITEMS) {
        size_t i = idx * 4;
        float4 v = *(const float4*)(x + i);
        uint32_t h0, l0, h1, l1;
        split2(v.x, v.y, h0, l0);
        split2(v.z, v.w, h1, l1);
        *(uint2*)(xh + i) = make_uint2(h0, h1);
        *(uint2*)(xl + i) = make_uint2(l0, l1);
        return;
    }
    long j = (long)(idx - XITEMS);
    const float* W; int K, N, off; int isconv = 0;
    if (j < 98304)                    { W = Wqks; K = 256;  N = 384; off = OFF_QKS; }
    else if ((j -= 98304)  < 196608)  { W = Wos;  K = 768;  N = 256; off = OFF_WOS; }
    else if ((j -= 196608) < 65536)   { W = Wffs; K = 256;  N = 256; off = OFF_FFS; }
    else if ((j -= 65536)  < 131072)  { W = Wqkt; K = 256;  N = 512; off = OFF_QKT; }
    else if ((j -= 131072) < 262144)  { W = Wot;  K = 1024; N = 256; off = OFF_WOT; }
    else if ((j -= 262144) < 65536)   { W = Wfft; K = 256;  N = 256; off = OFF_FFT; }
    else if ((j -= 65536)  < 458752)  { W = Wcnv; K = 1792; N = 256; off = OFF_CNV; isconv = 1; }
    else return;
    float v = W[j];
    __nv_bfloat16 h = __float2bfloat16(v);
    size_t dst;
    if (isconv) {
        int o = (int)(j / 1792), r = (int)(j % 1792);
        int ii = r / 7, kw = r % 7;
        dst = (size_t)off + (size_t)o * 1792 + kw * 256 + ii;
    } else {
        int k = (int)(j / N), n = (int)(j % N);
        dst = (size_t)off + (size_t)n * K + k;
    }
    wh[dst] = h;
    wl[dst] = __float2bfloat16(v - __bfloat162float(h));
}

// --------- de-interleave spatial qk -> qT,kT [(n*3+s)*25+u][4096] -----------
__global__ void deint_s(const float* __restrict__ qk, float* __restrict__ qT,
                        float* __restrict__ kT) {
    size_t idx = (size_t)blockIdx.x * 256 + threadIdx.x;
    int col = (int)(idx % 384);
    size_t row = idx / 384;
    int t = (int)(row % TT);
    size_t nu = row / TT;
    int n = (int)(nu / VV), u = (int)(nu % VV);
    int ci = col / 6, r = col % 6;
    float v = qk[idx];
    int s = (r < 3) ? r : r - 3;
    size_t dst = (((size_t)(n * 3 + s) * VV + u) << 12) + t * 64 + ci;
    if (r < 3) qT[dst] = v; else kT[dst] = v;
}

// spatial attention: split-K partials. grid (96, 8), block 128.
__global__ __launch_bounds__(128) void att_s_part(
        const float* __restrict__ qT, const float* __restrict__ kT,
        float* __restrict__ ps) {
    int ns = blockIdx.x;
    int kc0 = blockIdx.y << 9;     // *512
    __shared__ float qs[25][132], ks[25][132];
    const float* qb = qT + ((size_t)ns * VV << 12);
    const float* kb = kT + ((size_t)ns * VV << 12);
    int t = threadIdx.x;
    int u0 = (t / 25) * 5, v = t % 25;
    float acc[5] = {0.f, 0.f, 0.f, 0.f, 0.f};
    for (int kc = kc0; kc < kc0 + 512; kc += 128) {
        for (int i = t; i < 25 * 128; i += 128) {
            int uu = i >> 7, e = i & 127;
            qs[uu][e] = qb[((size_t)uu << 12) + kc + e];
            ks[uu][e] = kb[((size_t)uu << 12) + kc + e];
        }
        __syncthreads();
        if (t < 125) {
#pragma unroll 4
            for (int e = 0; e < 128; e++) {
                float kv = ks[v][e];
                acc[0] = fmaf(qs[u0 + 0][e], kv, acc[0]);
                acc[1] = fmaf(qs[u0 + 1][e], kv, acc[1]);
                acc[2] = fmaf(qs[u0 + 2][e], kv, acc[2]);
                acc[3] = fmaf(qs[u0 + 3][e], kv, acc[3]);
                acc[4] = fmaf(qs[u0 + 4][e], kv, acc[4]);
            }
        }
        __syncthreads();
    }
    if (t < 125) {
#pragma unroll
        for (int i = 0; i < 5; i++)
            atomicAdd(&ps[(size_t)ns * 625 + (u0 + i) * 25 + v], acc[i]);
    }
}

// finalize spatial attention
__global__ void att_s_fin(const float* __restrict__ ps, const float* __restrict__ alphas,
                          const float* __restrict__ att0, float* __restrict__ att) {
    int idx = blockIdx.x * 256 + threadIdx.x;
    if (idx >= 96 * 625) return;
    int ns = idx / 625, r = idx % 625;
    int n = ns / 3, s = ns % 3, u = r / 25, v = r % 25;
    att[((size_t)(n * VV + u) * VV + v) * 3 + s] =
        tanhf(ps[idx] * (1.f / 4096.f)) * alphas[s] + att0[((size_t)u * VV + v) * 3 + s];
}

// y_s: block per (n,t); x slice in smem; bf16 split output (768-wide)
__global__ __launch_bounds__(256) void ys2(const float* __restrict__ x,
                                           const float* __restrict__ att,
                                           __nv_bfloat16* __restrict__ yh,
                                           __nv_bfloat16* __restrict__ yl) {
    __shared__ float xs[25][256];
    __shared__ float as_[25 * 25 * 3];
    int b = blockIdx.x;             // n*64 + t
    int n = b >> 6, t = b & 63;
    int tid = threadIdx.x;
    for (int i = tid; i < 25 * 256; i += 256) {
        int u = i >> 8, c = i & 255;
        xs[u][c] = x[((size_t)(n * VV + u) * TT + t) * 256 + c];
    }
    for (int i = tid; i < 1875; i += 256) as_[i] = att[(size_t)n * 1875 + i];
    __syncthreads();
    int c = tid;
#pragma unroll 1
    for (int v = 0; v < VV; v++) {
        float a0 = 0.f, a1 = 0.f, a2 = 0.f;
#pragma unroll
        for (int u = 0; u < VV; u++) {
            float xv = xs[u][c];
            a0 = fmaf(xv, as_[(u * VV + v) * 3 + 0], a0);
            a1 = fmaf(xv, as_[(u * VV + v) * 3 + 1], a1);
            a2 = fmaf(xv, as_[(u * VV + v) * 3 + 2], a2);
        }
        size_t base = ((size_t)(n * VV + v) * TT + t) * 768 + c * 3;
        __nv_bfloat16 h0 = __float2bfloat16(a0);
        __nv_bfloat16 h1 = __float2bfloat16(a1);
        __nv_bfloat16 h2 = __float2bfloat16(a2);
        yh[base] = h0; yh[base + 1] = h1; yh[base + 2] = h2;
        yl[base]     = __float2bfloat16(a0 - __bfloat162float(h0));
        yl[base + 1] = __float2bfloat16(a1 - __bfloat162float(h1));
        yl[base + 2] = __float2bfloat16(a2 - __bfloat162float(h2));
    }
}

// LN over group + residual + gelu; writes bf16 hi/lo (+ optional fp32)
__global__ void ln2(const float* __restrict__ h, const float* __restrict__ res,
                    const float* __restrict__ g, const float* __restrict__ b,
                    float* __restrict__ outf, __nv_bfloat16* __restrict__ oh,
                    __nv_bfloat16* __restrict__ ol, int G, int mode, int wf) {
    int grp = blockIdx.x;
    const float* hp = h + (size_t)grp * G;
    const float* rp = res + (size_t)grp * G;
    float s = 0.f, sq = 0.f;
    for (int i = threadIdx.x; i < G; i += blockDim.x) {
        float v = hp[i]; s += v; sq = fmaf(v, v, sq);
    }
    for (int o = 16; o; o >>= 1) {
        s += __shfl_down_sync(0xffffffffu, s, o);
        sq += __shfl_down_sync(0xffffffffu, sq, o);
    }
    __shared__ float ss[8], sqs[8];
    __shared__ float mean_s, inv_s;
    int w = threadIdx.x >> 5;
    if ((threadIdx.x & 31) == 0) { ss[w] = s; sqs[w] = sq; }
    __syncthreads();
    if (threadIdx.x == 0) {
        float S = 0.f, Q = 0.f;
        for (int i = 0; i < 8; i++) { S += ss[i]; Q += sqs[i]; }
        float mean = S / G;
        float var = Q / G - mean * mean;
        mean_s = mean; inv_s = rsqrtf(var + 1e-5f);
    }
    __syncthreads();
    float mean = mean_s, inv = inv_s;
    int n = 0, v = 0;
    if (mode == 1) { n = grp / VV; v = grp % VV; }
    for (int i = threadIdx.x; i < G; i += blockDim.x) {
        float val = gelu_f(rp[i] + fmaf((hp[i] - mean) * inv, g[i], b[i]));
        size_t dst;
        if (mode == 0) dst = (size_t)grp * G + i;
        else {
            int t = i >> 8, c = i & 255;
            dst = ((size_t)(n * TT + t) * VV + v) * 256 + c;
        }
        if (wf) outf[dst] = val;
        __nv_bfloat16 hi = __float2bfloat16(val);
        oh[dst] = hi;
        ol[dst] = __float2bfloat16(val - __bfloat162float(hi));
    }
}

// --------- de-interleave temporal qkt -> qd,kd [(n*4+m)][t][1600] -----------
__global__ void deint_t(const float* __restrict__ qkt, float* __restrict__ qd,
                        float* __restrict__ kd) {
    size_t idx = (size_t)blockIdx.x * 256 + threadIdx.x;
    int col = (int)(idx & 511);
    size_t row = idx >> 9;
    int v = (int)(row % VV);
    size_t nt = row / VV;
    int t = (int)(nt % TT), n = (int)(nt / TT);
    int ci = col >> 3, j = col & 7;
    float val = qkt[idx];
    int m = (j < 4) ? j : j - 4;
    size_t dst = ((size_t)(n * 4 + m) * TT + t) * 1600 + v * 64 + ci;
    if (j < 4) qd[dst] = val; else kd[dst] = val;
}

// temporal attention split-K partials: grid (128, 5), block 256
__global__ __launch_bounds__(256) void att_t_part(
        const float* __restrict__ qd, const float* __restrict__ kd,
        float* __restrict__ pt) {
    int nm = blockIdx.x;
    int kb = blockIdx.y * 320;
    __shared__ float Qs[64][68], Ks[64][68];
    const float* qb = qd + (size_t)nm * TT * 1600;
    const float* kb_ = kd + (size_t)nm * TT * 1600;
    const int tid = threadIdx.x;
    const int tx = tid & 15, ty = tid >> 4;
    const int lr = tid >> 2, lc = (tid & 3) << 4;
    float acc[4][4] = {};
    for (int kc = kb; kc < kb + 320; kc += 64) {
#pragma unroll
        for (int j = 0; j < 4; j++) {
            float4 q4 = *(const float4*)(qb + (size_t)lr * 1600 + kc + lc + j * 4);
            float4 k4 = *(const float4*)(kb_ + (size_t)lr * 1600 + kc + lc + j * 4);
            Qs[lc + j*4 + 0][lr] = q4.x; Qs[lc + j*4 + 1][lr] = q4.y;
            Qs[lc + j*4 + 2][lr] = q4.z; Qs[lc + j*4 + 3][lr] = q4.w;
            Ks[lc + j*4 + 0][lr] = k4.x; Ks[lc + j*4 + 1][lr] = k4.y;
            Ks[lc + j*4 + 2][lr] = k4.z; Ks[lc + j*4 + 3][lr] = k4.w;
        }
        __syncthreads();
#pragma unroll 8
        for (int kk = 0; kk < 64; kk++) {
            float4 aq = *(const float4*)(&Qs[kk][ty << 2]);
            float4 bk = *(const float4*)(&Ks[kk][tx << 2]);
            float a[4] = {aq.x, aq.y, aq.z, aq.w};
            float b[4] = {bk.x, bk.y, bk.z, bk.w};
#pragma unroll
            for (int i = 0; i < 4; i++)
#pragma unroll
                for (int j = 0; j < 4; j++) acc[i][j] = fmaf(a[i], b[j], acc[i][j]);
        }
        __syncthreads();
    }
#pragma unroll
    for (int i = 0; i < 4; i++)
#pragma unroll
        for (int j = 0; j < 4; j++) {
            int t_ = (ty << 2) + i, q_ = (tx << 2) + j;
            atomicAdd(&pt[(size_t)nm * 4096 + t_ * 64 + q_], acc[i][j]);
        }
}

// finalize temporal attention -> att[n][q][t][s] with mask
__global__ void att_t_fin(const float* __restrict__ pt, const float* __restrict__ alf,
                          const float* __restrict__ alb, float* __restrict__ attf,
                          float* __restrict__ attb) {
    int idx = blockIdx.x * 256 + threadIdx.x;
    if (idx >= 128 * 4096) return;
    int nm = idx >> 12, r = idx & 4095;
    int t = r >> 6, q = r & 63;
    int n = nm >> 2, m = nm & 3, s = m & 1, dir = m >> 1;
    float val = tanhf(pt[idx] * (1.f / 1600.f)) * (dir ? alb[s] : alf[s]);
    size_t o = ((size_t)(n * TT + q) * TT + t) * 2 + s;
    if (dir == 0) attf[o] = (q <= t) ? val : 0.f;
    else          attb[o] = (q >= t) ? val : 0.f;
}

// z apply: block per (n,v); y2 slice in smem; bf16 split output (1024-wide)
__global__ __launch_bounds__(256) void z2k(const float* __restrict__ y2t,
                                           const float* __restrict__ attf,
                                           const float* __restrict__ attb,
                                           __nv_bfloat16* __restrict__ zh,
                                           __nv_bfloat16* __restrict__ zl) {
    extern __shared__ float zs[];          // 64*256 + 256
    float* ys = zs;
    float* as_ = zs + 64 * 256;
    int b = blockIdx.x;                    // n*25 + v
    int n = b / VV, v = b % VV;
    int tid = threadIdx.x;
    for (int i = tid; i < 64 * 256; i += 256) {
        int t = i >> 8, c = i & 255;
        ys[t * 256 + c] = y2t[((size_t)(n * TT + t) * VV + v) * 256 + c];
    }
    __syncthreads();
    int c = tid;
    for (int q = 0; q < TT; q++) {
        if (tid < 128) as_[tid] = attf[(size_t)n * 8192 + q * 128 + tid];
        else           as_[tid] = attb[(size_t)n * 8192 + q * 128 + (tid - 128)];
        __syncthreads();
        float f0 = 0.f, f1 = 0.f, b0 = 0.f, b1 = 0.f;
#pragma unroll 8
        for (int t = 0; t < TT; t++) {
            float yv = ys[t * 256 + c];
            f0 = fmaf(yv, as_[t * 2], f0);       f1 = fmaf(yv, as_[t * 2 + 1], f1);
            b0 = fmaf(yv, as_[128 + t * 2], b0); b1 = fmaf(yv, as_[128 + t * 2 + 1], b1);
        }
        size_t base = ((size_t)(n * TT + q) * VV + v) * 1024;
        uint32_t hf, lf, hb, lb;
        split2(f0, f1, hf, lf);
        split2(b0, b1, hb, lb);
        *(uint32_t*)(zh + base + c * 2) = hf;
        *(uint32_t*)(zl + base + c * 2) = lf;
        *(uint32_t*)(zh + base + 512 + c * 2) = hb;
        *(uint32_t*)(zl + base + 512 + c * 2) = lb;
        __syncthreads();
    }
}

__global__ void final_kernel(const float* __restrict__ z2, const float* __restrict__ cv,
                             const float* __restrict__ bn_g, const float* __restrict__ bn_b,
                             const float* __restrict__ bn_m, const float* __restrict__ bn_v,
                             float* __restrict__ out) {
    size_t i = (size_t)blockIdx.x * 256 + threadIdx.x;
    int o = (int)(i & 255);
    size_t r = i >> 8;
    int v = (int)(r % VV);
    size_t r2 = r / VV;
    int t = (int)(r2 % TT);
    int n = (int)(r2 / TT);
    float c1 = fmaf((cv[i] - bn_m[o]) * rsqrtf(bn_v[o] + 1e-5f), bn_g[o], bn_b[o]);
    out[((size_t)(n * VV + v) * TT + t) * 256 + o] = gelu_f(z2[i] + c1);
}

// ------------------------------- launcher -----------------------------------
extern "C" void kernel_launch(void* const* d_in, const int* in_sizes, int n_in,
                              void* d_out, int out_size) {
    const float* x       = (const float*)d_in[0];
    const float* Wqk_s   = (const float*)d_in[1];
    const float* bqk_s   = (const float*)d_in[2];
    const float* alphas  = (const float*)d_in[3];
    const float* att0s   = (const float*)d_in[4];
    const float* Wo_s    = (const float*)d_in[5];
    const float* bo_s    = (const float*)d_in[6];
    const float* g_os    = (const float*)d_in[7];
    const float* b_os    = (const float*)d_in[8];
    const float* Wff_s   = (const float*)d_in[9];
    const float* bff_s   = (const float*)d_in[10];
    const float* g_ffs   = (const float*)d_in[11];
    const float* b_ffs   = (const float*)d_in[12];
    const float* Wqk_t   = (const float*)d_in[13];
    const float* bqk_t   = (const float*)d_in[14];
    const float* alphat_f= (const float*)d_in[15];
    const float* alphat_b= (const float*)d_in[16];
    const float* Wo_t    = (const float*)d_in[17];
    const float* bo_t    = (const float*)d_in[18];
    const float* g_ot    = (const float*)d_in[19];
    const float* b_ot    = (const float*)d_in[20];
    const float* Wff_t   = (const float*)d_in[21];
    const float* bff_t   = (const float*)d_in[22];
    const float* g_fft   = (const float*)d_in[23];
    const float* b_fft   = (const float*)d_in[24];
    const float* conv_w  = (const float*)d_in[25];
    const float* conv_b  = (const float*)d_in[26];
    const float* bn_g    = (const float*)d_in[27];
    const float* bn_b    = (const float*)d_in[28];
    const float* bn_m    = (const float*)d_in[29];
    const float* bn_v    = (const float*)d_in[30];
    float* out = (float*)d_out;

    void *pB, *pH, *pY1, *pY2, *pZ2, *pAS, *pAF, *pAB, *pWH, *pWL, *pPS, *pPT;
    void *pAH, *pAL, *pXH, *pXL, *pY1H, *pY1L, *pY2H, *pY2L, *pZ2H, *pZ2L;
    cudaGetSymbolAddress(&pB,  g_bufB);
    cudaGetSymbolAddress(&pH,  g_h);
    cudaGetSymbolAddress(&pY1, g_y1);
    cudaGetSymbolAddress(&pY2, g_y2);
    cudaGetSymbolAddress(&pZ2, g_z2);
    cudaGetSymbolAddress(&pAS, g_atts);
    cudaGetSymbolAddress(&pAF, g_attf);
    cudaGetSymbolAddress(&pAB, g_attb);
    cudaGetSymbolAddress(&pPS, g_ps);
    cudaGetSymbolAddress(&pPT, g_pt);
    cudaGetSymbolAddress(&pWH, g_wh);
    cudaGetSymbolAddress(&pWL, g_wl);
    cudaGetSymbolAddress(&pAH, g_ah);
    cudaGetSymbolAddress(&pAL, g_al);
    cudaGetSymbolAddress(&pXH, g_xh);
    cudaGetSymbolAddress(&pXL, g_xl);
    cudaGetSymbolAddress(&pY1H, g_y1h);
    cudaGetSymbolAddress(&pY1L, g_y1l);
    cudaGetSymbolAddress(&pY2H, g_y2h);
    cudaGetSymbolAddress(&pY2L, g_y2l);
    cudaGetSymbolAddress(&pZ2H, g_z2h);
    cudaGetSymbolAddress(&pZ2L, g_z2l);
    float* bufB = (float*)pB;
    float* h    = (float*)pH;  float* y1   = (float*)pY1;
    float* y2   = (float*)pY2; float* z2b  = (float*)pZ2;
    float* atts = (float*)pAS; float* attf = (float*)pAF;
    float* attb = (float*)pAB;
    float* ps   = (float*)pPS; float* pt   = (float*)pPT;
    __nv_bfloat16* wh = (__nv_bfloat16*)pWH;
    __nv_bfloat16* wl = (__nv_bfloat16*)pWL;
    __nv_bfloat16* ah = (__nv_bfloat16*)pAH;
    __nv_bfloat16* al = (__nv_bfloat16*)pAL;
    __nv_bfloat16* xh = (__nv_bfloat16*)pXH;
    __nv_bfloat16* xl = (__nv_bfloat16*)pXL;
    __nv_bfloat16* y1h = (__nv_bfloat16*)pY1H;
    __nv_bfloat16* y1l = (__nv_bfloat16*)pY1L;
    __nv_bfloat16* y2h = (__nv_bfloat16*)pY2H;
    __nv_bfloat16* y2l = (__nv_bfloat16*)pY2L;
    __nv_bfloat16* z2h = (__nv_bfloat16*)pZ2H;
    __nv_bfloat16* z2l = (__nv_bfloat16*)pZ2L;

    cudaFuncSetAttribute(gemm_mma3, cudaFuncAttributeMaxDynamicSharedMemorySize, GSM);
    cudaFuncSetAttribute(conv_mma3, cudaFuncAttributeMaxDynamicSharedMemorySize, GSM);
    cudaFuncSetAttribute(z2k, cudaFuncAttributeMaxDynamicSharedMemorySize, (64*256 + 256) * 4);

    dim3 blk(256);
    const int MB = RTOT / 128;   // 400

    // merged prep + zero the attention partial buffers
    prep_all<<<(XITEMS + WTOT + 255) / 256, blk>>>(
        x, Wqk_s, Wo_s, Wff_s, Wqk_t, Wo_t, Wff_t, conv_w, xh, xl, wh, wl);
    cudaMemsetAsync(ps, 0, 96 * 625 * sizeof(float));
    cudaMemsetAsync(pt, 0, 128 * 4096 * sizeof(float));

    // Stage 1: spatial
    gemm_mma3<<<dim3(3, MB), blk, GSM>>>(xh, xl, wh + OFF_QKS, wl + OFF_QKS, bqk_s, bufB, RTOT, 384, 256);
    deint_s<<<RTOT * 384 / 256, blk>>>(bufB, h, y1);
    att_s_part<<<dim3(96, 8), 128>>>(h, y1, ps);
    att_s_fin<<<(96 * 625 + 255) / 256, blk>>>(ps, alphas, att0s, atts);
    ys2<<<NN * TT, blk>>>(x, atts, ah, al);
    gemm_mma3<<<dim3(2, MB), blk, GSM>>>(ah, al, wh + OFF_WOS, wl + OFF_WOS, bo_s, h, RTOT, 256, 768);
    ln2<<<NN*VV, blk>>>(h, x, g_os, b_os, y1, y1h, y1l, TT*256, 0, 0);
    gemm_mma3<<<dim3(2, MB), blk, GSM>>>(y1h, y1l, wh + OFF_FFS, wl + OFF_FFS, bff_s, h, RTOT, 256, 256);
    ln2<<<NN*VV, blk>>>(h, x, g_ffs, b_ffs, y2, y2h, y2l, TT*256, 1, 1);

    // Stage 2: temporal
    gemm_mma3<<<dim3(4, MB), blk, GSM>>>(y2h, y2l, wh + OFF_QKT, wl + OFF_QKT, bqk_t, bufB, RTOT, 512, 256);
    deint_t<<<RTOT * 512 / 256, blk>>>(bufB, h, y1);
    att_t_part<<<dim3(128, 5), blk>>>(h, y1, pt);
    att_t_fin<<<(128 * 4096 + 255) / 256, blk>>>(pt, alphat_f, alphat_b, attf, attb);
    z2k<<<NN * VV, blk, (64*256 + 256) * 4>>>(y2, attf, attb, ah, al);
    gemm_mma3<<<dim3(2, MB), blk, GSM>>>(ah, al, wh + OFF_WOT, wl + OFF_WOT, bo_t, h, RTOT, 256, 1024);
    ln2<<<NN*TT, blk>>>(h, y2, g_ot, b_ot, y1, y1h, y1l, VV*256, 0, 0);
    gemm_mma3<<<dim3(2, MB), blk, GSM>>>(y1h, y1l, wh + OFF_FFT, wl + OFF_FFT, bff_t, h, RTOT, 256, 256);
    ln2<<<NN*TT, blk>>>(h, y2, g_fft, b_fft, z2b, z2h, z2l, VV*256, 0, 1);

    // Stage 3: conv + BN + gelu + transpose
    conv_mma3<<<dim3(2, MB), blk, GSM>>>(z2h, z2l, wh + OFF_CNV, wl + OFF_CNV, conv_b, h);
    final_kernel<<<RTOT, blk>>>(z2b, h, bn_g, bn_b, bn_m, bn_v, out);
}

// round 10
// speedup vs baseline: 2.8445x; 1.0160x over previous
#include <cuda_runtime.h>
#include <cuda_bf16.h>
#include <math.h>
#include <stdint.h>

#define NN 32
#define VV 25
#define TT 64
#define RTOT (NN*VV*TT)   /* 51200 */

// ------------------------- scratch (device globals) -------------------------
__device__ float g_bufB[(size_t)RTOT * 512];
__device__ float g_h   [(size_t)RTOT * 256];
__device__ float g_y1  [(size_t)RTOT * 256];
__device__ float g_y2  [(size_t)RTOT * 256];
__device__ float g_z2  [(size_t)RTOT * 256];
__device__ float g_atts[NN*VV*VV*3];
__device__ float g_attf[NN*TT*TT*2];   // transposed layout [n][q][t][s]
__device__ float g_attb[NN*TT*TT*2];
__device__ float g_ps  [96*625];       // spatial attention partials
__device__ float g_pt  [128*64*64];    // temporal attention partials
// bf16 split activation buffers (16B-aligned for cp.async)
__device__ __align__(128) __nv_bfloat16 g_ah [(size_t)RTOT * 1024];
__device__ __align__(128) __nv_bfloat16 g_al [(size_t)RTOT * 1024];
__device__ __align__(128) __nv_bfloat16 g_xh [(size_t)RTOT * 256];
__device__ __align__(128) __nv_bfloat16 g_xl [(size_t)RTOT * 256];
__device__ __align__(128) __nv_bfloat16 g_y1h[(size_t)RTOT * 256];
__device__ __align__(128) __nv_bfloat16 g_y1l[(size_t)RTOT * 256];
__device__ __align__(128) __nv_bfloat16 g_y2h[(size_t)RTOT * 256];
__device__ __align__(128) __nv_bfloat16 g_y2l[(size_t)RTOT * 256];
__device__ __align__(128) __nv_bfloat16 g_z2h[(size_t)RTOT * 256];
__device__ __align__(128) __nv_bfloat16 g_z2l[(size_t)RTOT * 256];
#define WTOT 1277952
__device__ __align__(128) __nv_bfloat16 g_wh[WTOT];
__device__ __align__(128) __nv_bfloat16 g_wl[WTOT];
#define OFF_QKS 0         /* K=256  N=384  */
#define OFF_WOS 98304     /* K=768  N=256  */
#define OFF_FFS 294912    /* K=256  N=256  */
#define OFF_QKT 360448    /* K=256  N=512  */
#define OFF_WOT 491520    /* K=1024 N=256  */
#define OFF_FFT 753664    /* K=256  N=256  */
#define OFF_CNV 819200    /* K=1792 N=256  */

__device__ __forceinline__ float gelu_f(float x) {
    return 0.5f * x * (1.0f + erff(x * 0.7071067811865475f));
}
__device__ __forceinline__ void split2(float a, float b, uint32_t &hi, uint32_t &lo) {
    __nv_bfloat16 ha = __float2bfloat16(a), hb = __float2bfloat16(b);
    float la = a - __bfloat162float(ha), lb = b - __bfloat162float(hb);
    __nv_bfloat16 l1 = __float2bfloat16(la), l2 = __float2bfloat16(lb);
    hi = (uint32_t)__bfloat16_as_ushort(ha) | ((uint32_t)__bfloat16_as_ushort(hb) << 16);
    lo = (uint32_t)__bfloat16_as_ushort(l1) | ((uint32_t)__bfloat16_as_ushort(l2) << 16);
}
__device__ __forceinline__ uint32_t smem_u32(const void* p) {
    uint32_t a;
    asm("{ .reg .u64 t; cvta.to.shared.u64 t, %1; cvt.u32.u64 %0, t; }" : "=r"(a) : "l"(p));
    return a;
}
__device__ __forceinline__ void ldm4(uint32_t &r0, uint32_t &r1, uint32_t &r2,
                                     uint32_t &r3, uint32_t a) {
    asm volatile("ldmatrix.sync.aligned.m8n8.x4.shared.b16 {%0,%1,%2,%3}, [%4];"
        : "=r"(r0), "=r"(r1), "=r"(r2), "=r"(r3) : "r"(a));
}
__device__ __forceinline__ void mma16816(float* c, const uint32_t* a, const uint32_t* b) {
    asm volatile(
        "mma.sync.aligned.m16n8k16.row.col.f32.bf16.bf16.f32 "
        "{%0,%1,%2,%3}, {%4,%5,%6,%7}, {%8,%9}, {%0,%1,%2,%3};"
        : "+f"(c[0]), "+f"(c[1]), "+f"(c[2]), "+f"(c[3])
        : "r"(a[0]), "r"(a[1]), "r"(a[2]), "r"(a[3]), "r"(b[0]), "r"(b[1]));
}
__device__ __forceinline__ void cpa16(uint32_t dst, const void* src) {
    asm volatile("cp.async.cg.shared.global [%0], [%1], 16;" :: "r"(dst), "l"(src));
}
__device__ __forceinline__ void cpa16z(uint32_t dst, const void* src, int sz) {
    asm volatile("cp.async.cg.shared.global [%0], [%1], 16, %2;" :: "r"(dst), "l"(src), "r"(sz));
}
#define CPA_COMMIT() asm volatile("cp.async.commit_group;" ::: "memory")
#define CPA_WAIT2() asm volatile("cp.async.wait_group 2;" ::: "memory")
#define CPA_WAIT1() asm volatile("cp.async.wait_group 1;" ::: "memory")
#define CPA_WAIT0() asm volatile("cp.async.wait_group 0;" ::: "memory")

// smem swizzle for 64B rows (32 bf16): 16B chunk ch of row r at (ch ^ ((r>>1)&3))*16
#define SWZ(row, ch) ((uint32_t)((row) * 64 + ((((ch) ^ (((row) >> 1) & 3))) << 4)))

// ========== HMMA GEMM: 128x128 tile, k-chunk 32, 3-stage, 2 CTA/SM ==========
#define GSM (3*32768)
__global__ __launch_bounds__(256, 2) void gemm_mma3(
        const __nv_bfloat16* __restrict__ Ah, const __nv_bfloat16* __restrict__ Al,
        const __nv_bfloat16* __restrict__ Bh, const __nv_bfloat16* __restrict__ Bl,
        const float* __restrict__ bias, float* __restrict__ C, int M, int N, int K) {
    extern __shared__ char sm[];
    const uint32_t sbase = smem_u32(sm);
    const int tid = threadIdx.x, lane = tid & 31, w = tid >> 5;
    const int wm = w & 3, wn = w >> 2;
    const int bm = blockIdx.y << 7, bn = blockIdx.x << 7;
    float acc[2][8][4];
#pragma unroll
    for (int i = 0; i < 2; i++)
#pragma unroll
        for (int j = 0; j < 8; j++)
#pragma unroll
            for (int q = 0; q < 4; q++) acc[i][j][q] = 0.f;
    const int nch = K >> 5;

    auto load_stage = [&](int c) {
        uint32_t st = sbase + (c % 3) * 32768;
        const int k0 = c << 5;
#pragma unroll
        for (int j = 0; j < 2; j++) {
            int f = j * 256 + tid;
            int row = f >> 2, ch = f & 3;
            uint32_t off = SWZ(row, ch);
            cpa16(st + off,         Ah + (size_t)(bm + row) * K + k0 + ch * 8);
            cpa16(st + 8192 + off,  Al + (size_t)(bm + row) * K + k0 + ch * 8);
            cpa16(st + 16384 + off, Bh + (size_t)(bn + row) * K + k0 + ch * 8);
            cpa16(st + 24576 + off, Bl + (size_t)(bn + row) * K + k0 + ch * 8);
        }
        CPA_COMMIT();
    };
    load_stage(0);
    load_stage(1);
    for (int c = 0; c < nch; c++) {
        if (c + 2 < nch) { load_stage(c + 2); CPA_WAIT2(); }
        else if (c + 1 < nch) CPA_WAIT1();
        else CPA_WAIT0();
        __syncthreads();
        const uint32_t sAh = sbase + (c % 3) * 32768;
        const uint32_t sAl = sAh + 8192, sBh = sAh + 16384, sBl = sAh + 24576;
#pragma unroll
        for (int kk = 0; kk < 2; kk++) {
            uint32_t ah[2][4], al[2][4];
            const int arow = wm * 32 + (lane & 15);
            const int achunk = kk * 2 + (lane >> 4);
#pragma unroll
            for (int mi = 0; mi < 2; mi++) {
                int row = arow + mi * 16;
                ldm4(ah[mi][0], ah[mi][1], ah[mi][2], ah[mi][3], sAh + SWZ(row, achunk));
                ldm4(al[mi][0], al[mi][1], al[mi][2], al[mi][3], sAl + SWZ(row, achunk));
            }
            const int bchunk = kk * 2 + ((lane >> 3) & 1);
#pragma unroll
            for (int half = 0; half < 2; half++) {
                uint32_t bh[4][2], bl[4][2];
#pragma unroll
                for (int p = 0; p < 2; p++) {
                    int brow = wn * 64 + half * 32 + p * 16 + ((lane & 16) >> 1) + (lane & 7);
                    ldm4(bh[2*p][0], bh[2*p][1], bh[2*p+1][0], bh[2*p+1][1],
                         sBh + SWZ(brow, bchunk));
                    ldm4(bl[2*p][0], bl[2*p][1], bl[2*p+1][0], bl[2*p+1][1],
                         sBl + SWZ(brow, bchunk));
                }
#pragma unroll
                for (int mi = 0; mi < 2; mi++)
#pragma unroll
                    for (int nf = 0; nf < 4; nf++)
                        mma16816(acc[mi][half * 4 + nf], ah[mi], bh[nf]);
#pragma unroll
                for (int mi = 0; mi < 2; mi++)
#pragma unroll
                    for (int nf = 0; nf < 4; nf++)
                        mma16816(acc[mi][half * 4 + nf], ah[mi], bl[nf]);
#pragma unroll
                for (int mi = 0; mi < 2; mi++)
#pragma unroll
                    for (int nf = 0; nf < 4; nf++)
                        mma16816(acc[mi][half * 4 + nf], al[mi], bh[nf]);
            }
        }
        __syncthreads();
    }
    const int gid = lane >> 2, tig = lane & 3;
#pragma unroll
    for (int mi = 0; mi < 2; mi++)
#pragma unroll
        for (int nf = 0; nf < 8; nf++) {
            int col = bn + wn * 64 + nf * 8 + tig * 2;
            float b0v = bias[col], b1v = bias[col + 1];
            int r0 = bm + wm * 32 + mi * 16 + gid;
            *(float2*)(C + (size_t)r0 * N + col) =
                make_float2(acc[mi][nf][0] + b0v, acc[mi][nf][1] + b1v);
            *(float2*)(C + (size_t)(r0 + 8) * N + col) =
                make_float2(acc[mi][nf][2] + b0v, acc[mi][nf][3] + b1v);
        }
}

// ===== conv (implicit im2col) HMMA: K=1792, N=256, k-chunk 32, 3-stage ======
__global__ __launch_bounds__(256, 2) void conv_mma3(
        const __nv_bfloat16* __restrict__ Zh, const __nv_bfloat16* __restrict__ Zl,
        const __nv_bfloat16* __restrict__ Bh, const __nv_bfloat16* __restrict__ Bl,
        const float* __restrict__ bias, float* __restrict__ C) {
    const int N = 256, K = 1792;
    extern __shared__ char sm[];
    const uint32_t sbase = smem_u32(sm);
    const int tid = threadIdx.x, lane = tid & 31, w = tid >> 5;
    const int wm = w & 3, wn = w >> 2;
    const int bm = blockIdx.y << 7, bn = blockIdx.x << 7;
    float acc[2][8][4];
#pragma unroll
    for (int i = 0; i < 2; i++)
#pragma unroll
        for (int j = 0; j < 8; j++)
#pragma unroll
            for (int q = 0; q < 4; q++) acc[i][j][q] = 0.f;
    const int nch = K >> 5;   // 56

    auto load_stage = [&](int c) {
        uint32_t st = sbase + (c % 3) * 32768;
        const int k0 = c << 5;
        const int dt = (k0 >> 8) - 3;
        const int iio = k0 & 255;
#pragma unroll
        for (int j = 0; j < 2; j++) {
            int f = j * 256 + tid;
            int row = f >> 2, ch = f & 3;
            uint32_t off = SWZ(row, ch);
            int grow = bm + row;
            int t = (grow / VV) % TT;
            int tt = t + dt;
            int ok = (tt >= 0 && tt < TT);
            size_t srcoff = ok ? ((size_t)grow + (size_t)dt * VV) * 256 + iio + ch * 8 : 0;
            cpa16z(st + off,        Zh + srcoff, ok ? 16 : 0);
            cpa16z(st + 8192 + off, Zl + srcoff, ok ? 16 : 0);
            cpa16(st + 16384 + off, Bh + (size_t)(bn + row) * K + k0 + ch * 8);
            cpa16(st + 24576 + off, Bl + (size_t)(bn + row) * K + k0 + ch * 8);
        }
        CPA_COMMIT();
    };
    load_stage(0);
    load_stage(1);
    for (int c = 0; c < nch; c++) {
        if (c + 2 < nch) { load_stage(c + 2); CPA_WAIT2(); }
        else if (c + 1 < nch) CPA_WAIT1();
        else CPA_WAIT0();
        __syncthreads();
        const uint32_t sAh = sbase + (c % 3) * 32768;
        const uint32_t sAl = sAh + 8192, sBh = sAh + 16384, sBl = sAh + 24576;
#pragma unroll
        for (int kk = 0; kk < 2; kk++) {
            uint32_t ah[2][4], al[2][4];
            const int arow = wm * 32 + (lane & 15);
            const int achunk = kk * 2 + (lane >> 4);
#pragma unroll
            for (int mi = 0; mi < 2; mi++) {
                int row = arow + mi * 16;
                ldm4(ah[mi][0], ah[mi][1], ah[mi][2], ah[mi][3], sAh + SWZ(row, achunk));
                ldm4(al[mi][0], al[mi][1], al[mi][2], al[mi][3], sAl + SWZ(row, achunk));
            }
            const int bchunk = kk * 2 + ((lane >> 3) & 1);
#pragma unroll
            for (int half = 0; half < 2; half++) {
                uint32_t bh[4][2], bl[4][2];
#pragma unroll
                for (int p = 0; p < 2; p++) {
                    int brow = wn * 64 + half * 32 + p * 16 + ((lane & 16) >> 1) + (lane & 7);
                    ldm4(bh[2*p][0], bh[2*p][1], bh[2*p+1][0], bh[2*p+1][1],
                         sBh + SWZ(brow, bchunk));
                    ldm4(bl[2*p][0], bl[2*p][1], bl[2*p+1][0], bl[2*p+1][1],
                         sBl + SWZ(brow, bchunk));
                }
#pragma unroll
                for (int mi = 0; mi < 2; mi++)
#pragma unroll
                    for (int nf = 0; nf < 4; nf++)
                        mma16816(acc[mi][half * 4 + nf], ah[mi], bh[nf]);
#pragma unroll
                for (int mi = 0; mi < 2; mi++)
#pragma unroll
                    for (int nf = 0; nf < 4; nf++)
                        mma16816(acc[mi][half * 4 + nf], ah[mi], bl[nf]);
#pragma unroll
                for (int mi = 0; mi < 2; mi++)
#pragma unroll
                    for (int nf = 0; nf < 4; nf++)
                        mma16816(acc[mi][half * 4 + nf], al[mi], bh[nf]);
            }
        }
        __syncthreads();
    }
    const int gid = lane >> 2, tig = lane & 3;
#pragma unroll
    for (int mi = 0; mi < 2; mi++)
#pragma unroll
        for (int nf = 0; nf < 8; nf++) {
            int col = bn + wn * 64 + nf * 8 + tig * 2;
            float b0v = bias[col], b1v = bias[col + 1];
            int r0 = bm + wm * 32 + mi * 16 + gid;
            *(float2*)(C + (size_t)r0 * N + col) =
                make_float2(acc[mi][nf][0] + b0v, acc[mi][nf][1] + b1v);
            *(float2*)(C + (size_t)(r0 + 8) * N + col) =
                make_float2(acc[mi][nf][2] + b0v, acc[mi][nf][3] + b1v);
        }
}

// ---------------- prep kernels (x split; weight splits in 2 halves) ----------
#define XITEMS 3276800
__global__ void prep_x(const float* __restrict__ x,
                       __nv_bfloat16* __restrict__ xh, __nv_bfloat16* __restrict__ xl) {
    size_t idx = (size_t)blockIdx.x * 256 + threadIdx.x;
    if (idx >= XITEMS) return;
    size_t i = idx * 4;
    float4 v = *(const float4*)(x + i);
    uint32_t h0, l0, h1, l1;
    split2(v.x, v.y, h0, l0);
    split2(v.z, v.w, h1, l1);
    *(uint2*)(xh + i) = make_uint2(h0, h1);
    *(uint2*)(xl + i) = make_uint2(l0, l1);
}
__global__ void prep_w(
        const float* __restrict__ Wqks, const float* __restrict__ Wos,
        const float* __restrict__ Wffs, const float* __restrict__ Wqkt,
        const float* __restrict__ Wot,  const float* __restrict__ Wfft,
        const float* __restrict__ Wcnv,
        __nv_bfloat16* __restrict__ wh, __nv_bfloat16* __restrict__ wl,
        int jbase, int jcount) {
    int li = blockIdx.x * 256 + threadIdx.x;
    if (li >= jcount) return;
    long j = (long)jbase + li;
    const float* W; int K, N, off; int isconv = 0;
    if (j < 98304)                    { W = Wqks; K = 256;  N = 384; off = OFF_QKS; }
    else if ((j -= 98304)  < 196608)  { W = Wos;  K = 768;  N = 256; off = OFF_WOS; }
    else if ((j -= 196608) < 65536)   { W = Wffs; K = 256;  N = 256; off = OFF_FFS; }
    else if ((j -= 65536)  < 131072)  { W = Wqkt; K = 256;  N = 512; off = OFF_QKT; }
    else if ((j -= 131072) < 262144)  { W = Wot;  K = 1024; N = 256; off = OFF_WOT; }
    else if ((j -= 262144) < 65536)   { W = Wfft; K = 256;  N = 256; off = OFF_FFT; }
    else if ((j -= 65536)  < 458752)  { W = Wcnv; K = 1792; N = 256; off = OFF_CNV; isconv = 1; }
    else return;
    float v = W[j];
    __nv_bfloat16 h = __float2bfloat16(v);
    size_t dst;
    if (isconv) {
        int o = (int)(j / 1792), r = (int)(j % 1792);
        int ii = r / 7, kw = r % 7;
        dst = (size_t)off + (size_t)o * 1792 + kw * 256 + ii;
    } else {
        int k = (int)(j / N), n = (int)(j % N);
        dst = (size_t)off + (size_t)n * K + k;
    }
    wh[dst] = h;
    wl[dst] = __float2bfloat16(v - __bfloat162float(h));
}

// ------ deint_s: smem-staged, coalesced writes. block per (n,u,t-half) ------
#define DS_SMEM (6 * 2049 * 4)
__global__ __launch_bounds__(256) void deint_s2(const float* __restrict__ qk,
                                                float* __restrict__ qT,
                                                float* __restrict__ kT) {
    extern __shared__ float sms[];   // 6 planes, stride 2049
    int b = blockIdx.x;
    int th = b & 1;
    int u = (b >> 1) % VV;
    int n = b / (VV * 2);
    int t0 = th << 5;
    const float* src = qk + ((size_t)(n * VV + u) * TT + t0) * 384;
    for (int i = threadIdx.x; i < 32 * 384; i += 256) {
        int tt = i / 384, col = i % 384;
        int ci = col / 6, r = col % 6;
        int plane = (r < 3) ? r : r;           // q: plane r (0..2); k: plane 3..5
        // r<3 -> q plane r ; r>=3 -> k plane 3 + (r-3) = r
        sms[plane * 2049 + tt * 64 + ci] = src[i];
    }
    __syncthreads();
#pragma unroll
    for (int p = 0; p < 6; p++) {
        int s = (p < 3) ? p : p - 3;
        float* dst = ((p < 3) ? qT : kT) +
                     (((size_t)(n * 3 + s) * VV + u) << 12) + (size_t)t0 * 64;
        for (int i = threadIdx.x; i < 2048; i += 256)
            dst[i] = sms[p * 2049 + i];
    }
}

// ------ deint_t: smem-staged, coalesced writes. block per (n,t) --------------
#define DT_SMEM (8 * 1665 * 4)
__global__ __launch_bounds__(256) void deint_t2(const float* __restrict__ qkt,
                                                float* __restrict__ qd,
                                                float* __restrict__ kd) {
    extern __shared__ float smt[];   // 8 planes (j), stride 1665
    int b = blockIdx.x;
    int t = b % TT, n = b / TT;
    const float* src = qkt + ((size_t)(n * TT + t) * VV) * 512;
    for (int i = threadIdx.x; i < 25 * 512; i += 256) {
        int v = i >> 9, col = i & 511;
        int ci = col >> 3, j = col & 7;
        smt[j * 1665 + v * 64 + ci] = src[i];
    }
    __syncthreads();
#pragma unroll
    for (int p = 0; p < 8; p++) {
        int m = p & 3;
        float* dst = ((p < 4) ? qd : kd) + ((size_t)(n * 4 + m) * TT + t) * 1600;
        for (int i = threadIdx.x; i < 1600; i += 256)
            dst[i] = smt[p * 1665 + i];
    }
}

// spatial attention: split-K partials. grid (96, 8), block 128.
__global__ __launch_bounds__(128) void att_s_part(
        const float* __restrict__ qT, const float* __restrict__ kT,
        float* __restrict__ ps) {
    int ns = blockIdx.x;
    int kc0 = blockIdx.y << 9;     // *512
    __shared__ float qs[25][132], ks[25][132];
    const float* qb = qT + ((size_t)ns * VV << 12);
    const float* kb = kT + ((size_t)ns * VV << 12);
    int t = threadIdx.x;
    int u0 = (t / 25) * 5, v = t % 25;
    float acc[5] = {0.f, 0.f, 0.f, 0.f, 0.f};
    for (int kc = kc0; kc < kc0 + 512; kc += 128) {
        for (int i = t; i < 25 * 128; i += 128) {
            int uu = i >> 7, e = i & 127;
            qs[uu][e] = qb[((size_t)uu << 12) + kc + e];
            ks[uu][e] = kb[((size_t)uu << 12) + kc + e];
        }
        __syncthreads();
        if (t < 125) {
#pragma unroll 4
            for (int e = 0; e < 128; e++) {
                float kv = ks[v][e];
                acc[0] = fmaf(qs[u0 + 0][e], kv, acc[0]);
                acc[1] = fmaf(qs[u0 + 1][e], kv, acc[1]);
                acc[2] = fmaf(qs[u0 + 2][e], kv, acc[2]);
                acc[3] = fmaf(qs[u0 + 3][e], kv, acc[3]);
                acc[4] = fmaf(qs[u0 + 4][e], kv, acc[4]);
            }
        }
        __syncthreads();
    }
    if (t < 125) {
#pragma unroll
        for (int i = 0; i < 5; i++)
            atomicAdd(&ps[(size_t)ns * 625 + (u0 + i) * 25 + v], acc[i]);
    }
}

// finalize spatial attention
__global__ void att_s_fin(const float* __restrict__ ps, const float* __restrict__ alphas,
                          const float* __restrict__ att0, float* __restrict__ att) {
    int idx = blockIdx.x * 256 + threadIdx.x;
    if (idx >= 96 * 625) return;
    int ns = idx / 625, r = idx % 625;
    int n = ns / 3, s = ns % 3, u = r / 25, v = r % 25;
    att[((size_t)(n * VV + u) * VV + v) * 3 + s] =
        tanhf(ps[idx] * (1.f / 4096.f)) * alphas[s] + att0[((size_t)u * VV + v) * 3 + s];
}

// y_s: block per (n,t); x slice in smem; bf16 split output (768-wide)
__global__ __launch_bounds__(256) void ys2(const float* __restrict__ x,
                                           const float* __restrict__ att,
                                           __nv_bfloat16* __restrict__ yh,
                                           __nv_bfloat16* __restrict__ yl) {
    __shared__ float xs[25][256];
    __shared__ float as_[25 * 25 * 3];
    int b = blockIdx.x;             // n*64 + t
    int n = b >> 6, t = b & 63;
    int tid = threadIdx.x;
    for (int i = tid; i < 25 * 256; i += 256) {
        int u = i >> 8, c = i & 255;
        xs[u][c] = x[((size_t)(n * VV + u) * TT + t) * 256 + c];
    }
    for (int i = tid; i < 1875; i += 256) as_[i] = att[(size_t)n * 1875 + i];
    __syncthreads();
    int c = tid;
#pragma unroll 1
    for (int v = 0; v < VV; v++) {
        float a0 = 0.f, a1 = 0.f, a2 = 0.f;
#pragma unroll
        for (int u = 0; u < VV; u++) {
            float xv = xs[u][c];
            a0 = fmaf(xv, as_[(u * VV + v) * 3 + 0], a0);
            a1 = fmaf(xv, as_[(u * VV + v) * 3 + 1], a1);
            a2 = fmaf(xv, as_[(u * VV + v) * 3 + 2], a2);
        }
        size_t base = ((size_t)(n * VV + v) * TT + t) * 768 + c * 3;
        __nv_bfloat16 h0 = __float2bfloat16(a0);
        __nv_bfloat16 h1 = __float2bfloat16(a1);
        __nv_bfloat16 h2 = __float2bfloat16(a2);
        yh[base] = h0; yh[base + 1] = h1; yh[base + 2] = h2;
        yl[base]     = __float2bfloat16(a0 - __bfloat162float(h0));
        yl[base + 1] = __float2bfloat16(a1 - __bfloat162float(h1));
        yl[base + 2] = __float2bfloat16(a2 - __bfloat162float(h2));
    }
}

// LN over group + residual + gelu; writes bf16 hi/lo (+ optional fp32)
__global__ void ln2(const float* __restrict__ h, const float* __restrict__ res,
                    const float* __restrict__ g, const float* __restrict__ b,
                    float* __restrict__ outf, __nv_bfloat16* __restrict__ oh,
                    __nv_bfloat16* __restrict__ ol, int G, int mode, int wf) {
    int grp = blockIdx.x;
    const float* hp = h + (size_t)grp * G;
    const float* rp = res + (size_t)grp * G;
    float s = 0.f, sq = 0.f;
    for (int i = threadIdx.x; i < G; i += blockDim.x) {
        float v = hp[i]; s += v; sq = fmaf(v, v, sq);
    }
    for (int o = 16; o; o >>= 1) {
        s += __shfl_down_sync(0xffffffffu, s, o);
        sq += __shfl_down_sync(0xffffffffu, sq, o);
    }
    __shared__ float ss[8], sqs[8];
    __shared__ float mean_s, inv_s;
    int w = threadIdx.x >> 5;
    if ((threadIdx.x & 31) == 0) { ss[w] = s; sqs[w] = sq; }
    __syncthreads();
    if (threadIdx.x == 0) {
        float S = 0.f, Q = 0.f;
        for (int i = 0; i < 8; i++) { S += ss[i]; Q += sqs[i]; }
        float mean = S / G;
        float var = Q / G - mean * mean;
        mean_s = mean; inv_s = rsqrtf(var + 1e-5f);
    }
    __syncthreads();
    float mean = mean_s, inv = inv_s;
    int n = 0, v = 0;
    if (mode == 1) { n = grp / VV; v = grp % VV; }
    for (int i = threadIdx.x; i < G; i += blockDim.x) {
        float val = gelu_f(rp[i] + fmaf((hp[i] - mean) * inv, g[i], b[i]));
        size_t dst;
        if (mode == 0) dst = (size_t)grp * G + i;
        else {
            int t = i >> 8, c = i & 255;
            dst = ((size_t)(n * TT + t) * VV + v) * 256 + c;
        }
        if (wf) outf[dst] = val;
        __nv_bfloat16 hi = __float2bfloat16(val);
        oh[dst] = hi;
        ol[dst] = __float2bfloat16(val - __bfloat162float(hi));
    }
}

// temporal attention split-K partials: grid (128, 5), block 256
__global__ __launch_bounds__(256) void att_t_part(
        const float* __restrict__ qd, const float* __restrict__ kd,
        float* __restrict__ pt) {
    int nm = blockIdx.x;
    int kb = blockIdx.y * 320;
    __shared__ float Qs[64][68], Ks[64][68];
    const float* qb = qd + (size_t)nm * TT * 1600;
    const float* kb_ = kd + (size_t)nm * TT * 1600;
    const int tid = threadIdx.x;
    const int tx = tid & 15, ty = tid >> 4;
    const int lr = tid >> 2, lc = (tid & 3) << 4;
    float acc[4][4] = {};
    for (int kc = kb; kc < kb + 320; kc += 64) {
#pragma unroll
        for (int j = 0; j < 4; j++) {
            float4 q4 = *(const float4*)(qb + (size_t)lr * 1600 + kc + lc + j * 4);
            float4 k4 = *(const float4*)(kb_ + (size_t)lr * 1600 + kc + lc + j * 4);
            Qs[lc + j*4 + 0][lr] = q4.x; Qs[lc + j*4 + 1][lr] = q4.y;
            Qs[lc + j*4 + 2][lr] = q4.z; Qs[lc + j*4 + 3][lr] = q4.w;
            Ks[lc + j*4 + 0][lr] = k4.x; Ks[lc + j*4 + 1][lr] = k4.y;
            Ks[lc + j*4 + 2][lr] = k4.z; Ks[lc + j*4 + 3][lr] = k4.w;
        }
        __syncthreads();
#pragma unroll 8
        for (int kk = 0; kk < 64; kk++) {
            float4 aq = *(const float4*)(&Qs[kk][ty << 2]);
            float4 bk = *(const float4*)(&Ks[kk][tx << 2]);
            float a[4] = {aq.x, aq.y, aq.z, aq.w};
            float b[4] = {bk.x, bk.y, bk.z, bk.w};
#pragma unroll
            for (int i = 0; i < 4; i++)
#pragma unroll
                for (int j = 0; j < 4; j++) acc[i][j] = fmaf(a[i], b[j], acc[i][j]);
        }
        __syncthreads();
    }
#pragma unroll
    for (int i = 0; i < 4; i++)
#pragma unroll
        for (int j = 0; j < 4; j++) {
            int t_ = (ty << 2) + i, q_ = (tx << 2) + j;
            atomicAdd(&pt[(size_t)nm * 4096 + t_ * 64 + q_], acc[i][j]);
        }
}

// finalize temporal attention -> att[n][q][t][s] with mask
__global__ void att_t_fin(const float* __restrict__ pt, const float* __restrict__ alf,
                          const float* __restrict__ alb, float* __restrict__ attf,
                          float* __restrict__ attb) {
    int idx = blockIdx.x * 256 + threadIdx.x;
    if (idx >= 128 * 4096) return;
    int nm = idx >> 12, r = idx & 4095;
    int t = r >> 6, q = r & 63;
    int n = nm >> 2, m = nm & 3, s = m & 1, dir = m >> 1;
    float val = tanhf(pt[idx] * (1.f / 1600.f)) * (dir ? alb[s] : alf[s]);
    size_t o = ((size_t)(n * TT + q) * TT + t) * 2 + s;
    if (dir == 0) attf[o] = (q <= t) ? val : 0.f;
    else          attb[o] = (q >= t) ? val : 0.f;
}

// z apply: block per (n,v); y2 slice in smem; bf16 split output (1024-wide)
__global__ __launch_bounds__(256) void z2k(const float* __restrict__ y2t,
                                           const float* __restrict__ attf,
                                           const float* __restrict__ attb,
                                           __nv_bfloat16* __restrict__ zh,
                                           __nv_bfloat16* __restrict__ zl) {
    extern __shared__ float zs[];          // 64*256 + 256
    float* ys = zs;
    float* as_ = zs + 64 * 256;
    int b = blockIdx.x;                    // n*25 + v
    int n = b / VV, v = b % VV;
    int tid = threadIdx.x;
    for (int i = tid; i < 64 * 256; i += 256) {
        int t = i >> 8, c = i & 255;
        ys[t * 256 + c] = y2t[((size_t)(n * TT + t) * VV + v) * 256 + c];
    }
    __syncthreads();
    int c = tid;
    for (int q = 0; q < TT; q++) {
        if (tid < 128) as_[tid] = attf[(size_t)n * 8192 + q * 128 + tid];
        else           as_[tid] = attb[(size_t)n * 8192 + q * 128 + (tid - 128)];
        __syncthreads();
        float f0 = 0.f, f1 = 0.f, b0 = 0.f, b1 = 0.f;
#pragma unroll 8
        for (int t = 0; t < TT; t++) {
            float yv = ys[t * 256 + c];
            f0 = fmaf(yv, as_[t * 2], f0);       f1 = fmaf(yv, as_[t * 2 + 1], f1);
            b0 = fmaf(yv, as_[128 + t * 2], b0); b1 = fmaf(yv, as_[128 + t * 2 + 1], b1);
        }
        size_t base = ((size_t)(n * TT + q) * VV + v) * 1024;
        uint32_t hf, lf, hb, lb;
        split2(f0, f1, hf, lf);
        split2(b0, b1, hb, lb);
        *(uint32_t*)(zh + base + c * 2) = hf;
        *(uint32_t*)(zl + base + c * 2) = lf;
        *(uint32_t*)(zh + base + 512 + c * 2) = hb;
        *(uint32_t*)(zl + base + 512 + c * 2) = lb;
        __syncthreads();
    }
}

__global__ void final_kernel(const float* __restrict__ z2, const float* __restrict__ cv,
                             const float* __restrict__ bn_g, const float* __restrict__ bn_b,
                             const float* __restrict__ bn_m, const float* __restrict__ bn_v,
                             float* __restrict__ out) {
    size_t i = (size_t)blockIdx.x * 256 + threadIdx.x;
    int o = (int)(i & 255);
    size_t r = i >> 8;
    int v = (int)(r % VV);
    size_t r2 = r / VV;
    int t = (int)(r2 % TT);
    int n = (int)(r2 / TT);
    float c1 = fmaf((cv[i] - bn_m[o]) * rsqrtf(bn_v[o] + 1e-5f), bn_g[o], bn_b[o]);
    out[((size_t)(n * VV + v) * TT + t) * 256 + o] = gelu_f(z2[i] + c1);
}

// ------------------------------- launcher -----------------------------------
extern "C" void kernel_launch(void* const* d_in, const int* in_sizes, int n_in,
                              void* d_out, int out_size) {
    const float* x       = (const float*)d_in[0];
    const float* Wqk_s   = (const float*)d_in[1];
    const float* bqk_s   = (const float*)d_in[2];
    const float* alphas  = (const float*)d_in[3];
    const float* att0s   = (const float*)d_in[4];
    const float* Wo_s    = (const float*)d_in[5];
    const float* bo_s    = (const float*)d_in[6];
    const float* g_os    = (const float*)d_in[7];
    const float* b_os    = (const float*)d_in[8];
    const float* Wff_s   = (const float*)d_in[9];
    const float* bff_s   = (const float*)d_in[10];
    const float* g_ffs   = (const float*)d_in[11];
    const float* b_ffs   = (const float*)d_in[12];
    const float* Wqk_t   = (const float*)d_in[13];
    const float* bqk_t   = (const float*)d_in[14];
    const float* alphat_f= (const float*)d_in[15];
    const float* alphat_b= (const float*)d_in[16];
    const float* Wo_t    = (const float*)d_in[17];
    const float* bo_t    = (const float*)d_in[18];
    const float* g_ot    = (const float*)d_in[19];
    const float* b_ot    = (const float*)d_in[20];
    const float* Wff_t   = (const float*)d_in[21];
    const float* bff_t   = (const float*)d_in[22];
    const float* g_fft   = (const float*)d_in[23];
    const float* b_fft   = (const float*)d_in[24];
    const float* conv_w  = (const float*)d_in[25];
    const float* conv_b  = (const float*)d_in[26];
    const float* bn_g    = (const float*)d_in[27];
    const float* bn_b    = (const float*)d_in[28];
    const float* bn_m    = (const float*)d_in[29];
    const float* bn_v    = (const float*)d_in[30];
    float* out = (float*)d_out;

    void *pB, *pH, *pY1, *pY2, *pZ2, *pAS, *pAF, *pAB, *pWH, *pWL, *pPS, *pPT;
    void *pAH, *pAL, *pXH, *pXL, *pY1H, *pY1L, *pY2H, *pY2L, *pZ2H, *pZ2L;
    cudaGetSymbolAddress(&pB,  g_bufB);
    cudaGetSymbolAddress(&pH,  g_h);
    cudaGetSymbolAddress(&pY1, g_y1);
    cudaGetSymbolAddress(&pY2, g_y2);
    cudaGetSymbolAddress(&pZ2, g_z2);
    cudaGetSymbolAddress(&pAS, g_atts);
    cudaGetSymbolAddress(&pAF, g_attf);
    cudaGetSymbolAddress(&pAB, g_attb);
    cudaGetSymbolAddress(&pPS, g_ps);
    cudaGetSymbolAddress(&pPT, g_pt);
    cudaGetSymbolAddress(&pWH, g_wh);
    cudaGetSymbolAddress(&pWL, g_wl);
    cudaGetSymbolAddress(&pAH, g_ah);
    cudaGetSymbolAddress(&pAL, g_al);
    cudaGetSymbolAddress(&pXH, g_xh);
    cudaGetSymbolAddress(&pXL, g_xl);
    cudaGetSymbolAddress(&pY1H, g_y1h);
    cudaGetSymbolAddress(&pY1L, g_y1l);
    cudaGetSymbolAddress(&pY2H, g_y2h);
    cudaGetSymbolAddress(&pY2L, g_y2l);
    cudaGetSymbolAddress(&pZ2H, g_z2h);
    cudaGetSymbolAddress(&pZ2L, g_z2l);
    float* bufB = (float*)pB;
    float* h    = (float*)pH;  float* y1   = (float*)pY1;
    float* y2   = (float*)pY2; float* z2b  = (float*)pZ2;
    float* atts = (float*)pAS; float* attf = (float*)pAF;
    float* attb = (float*)pAB;
    float* ps   = (float*)pPS; float* pt   = (float*)pPT;
    __nv_bfloat16* wh = (__nv_bfloat16*)pWH;
    __nv_bfloat16* wl = (__nv_bfloat16*)pWL;
    __nv_bfloat16* ah = (__nv_bfloat16*)pAH;
    __nv_bfloat16* al = (__nv_bfloat16*)pAL;
    __nv_bfloat16* xh = (__nv_bfloat16*)pXH;
    __nv_bfloat16* xl = (__nv_bfloat16*)pXL;
    __nv_bfloat16* y1h = (__nv_bfloat16*)pY1H;
    __nv_bfloat16* y1l = (__nv_bfloat16*)pY1L;
    __nv_bfloat16* y2h = (__nv_bfloat16*)pY2H;
    __nv_bfloat16* y2l = (__nv_bfloat16*)pY2L;
    __nv_bfloat16* z2h = (__nv_bfloat16*)pZ2H;
    __nv_bfloat16* z2l = (__nv_bfloat16*)pZ2L;

    cudaFuncSetAttribute(gemm_mma3, cudaFuncAttributeMaxDynamicSharedMemorySize, GSM);
    cudaFuncSetAttribute(conv_mma3, cudaFuncAttributeMaxDynamicSharedMemorySize, GSM);
    cudaFuncSetAttribute(z2k, cudaFuncAttributeMaxDynamicSharedMemorySize, (64*256 + 256) * 4);
    cudaFuncSetAttribute(deint_s2, cudaFuncAttributeMaxDynamicSharedMemorySize, DS_SMEM);
    cudaFuncSetAttribute(deint_t2, cudaFuncAttributeMaxDynamicSharedMemorySize, DT_SMEM);

    dim3 blk(256);
    const int MB = RTOT / 128;   // 400
    const int WHALF = WTOT / 2;  // 638976

    // prep (3 launches) + partial-buffer zeroing -> gemm is launch #6 for ncu
    prep_x<<<(XITEMS + 255) / 256, blk>>>(x, xh, xl);
    prep_w<<<(WHALF + 255) / 256, blk>>>(Wqk_s, Wo_s, Wff_s, Wqk_t, Wo_t, Wff_t,
                                         conv_w, wh, wl, 0, WHALF);
    prep_w<<<(WHALF + 255) / 256, blk>>>(Wqk_s, Wo_s, Wff_s, Wqk_t, Wo_t, Wff_t,
                                         conv_w, wh, wl, WHALF, WTOT - WHALF);
    cudaMemsetAsync(ps, 0, 96 * 625 * sizeof(float));
    cudaMemsetAsync(pt, 0, 128 * 4096 * sizeof(float));

    // Stage 1: spatial
    gemm_mma3<<<dim3(3, MB), blk, GSM>>>(xh, xl, wh + OFF_QKS, wl + OFF_QKS, bqk_s, bufB, RTOT, 384, 256);
    deint_s2<<<NN * VV * 2, blk, DS_SMEM>>>(bufB, h, y1);
    att_s_part<<<dim3(96, 8), 128>>>(h, y1, ps);
    att_s_fin<<<(96 * 625 + 255) / 256, blk>>>(ps, alphas, att0s, atts);
    ys2<<<NN * TT, blk>>>(x, atts, ah, al);
    gemm_mma3<<<dim3(2, MB), blk, GSM>>>(ah, al, wh + OFF_WOS, wl + OFF_WOS, bo_s, h, RTOT, 256, 768);
    ln2<<<NN*VV, blk>>>(h, x, g_os, b_os, y1, y1h, y1l, TT*256, 0, 0);
    gemm_mma3<<<dim3(2, MB), blk, GSM>>>(y1h, y1l, wh + OFF_FFS, wl + OFF_FFS, bff_s, h, RTOT, 256, 256);
    ln2<<<NN*VV, blk>>>(h, x, g_ffs, b_ffs, y2, y2h, y2l, TT*256, 1, 1);

    // Stage 2: temporal
    gemm_mma3<<<dim3(4, MB), blk, GSM>>>(y2h, y2l, wh + OFF_QKT, wl + OFF_QKT, bqk_t, bufB, RTOT, 512, 256);
    deint_t2<<<NN * TT, blk, DT_SMEM>>>(bufB, h, y1);
    att_t_part<<<dim3(128, 5), blk>>>(h, y1, pt);
    att_t_fin<<<(128 * 4096 + 255) / 256, blk>>>(pt, alphat_f, alphat_b, attf, attb);
    z2k<<<NN * VV, blk, (64*256 + 256) * 4>>>(y2, attf, attb, ah, al);
    gemm_mma3<<<dim3(2, MB), blk, GSM>>>(ah, al, wh + OFF_WOT, wl + OFF_WOT, bo_t, h, RTOT, 256, 1024);
    ln2<<<NN*TT, blk>>>(h, y2, g_ot, b_ot, y1, y1h, y1l, VV*256, 0, 0);
    gemm_mma3<<<dim3(2, MB), blk, GSM>>>(y1h, y1l, wh + OFF_FFT, wl + OFF_FFT, bff_t, h, RTOT, 256, 256);
    ln2<<<NN*TT, blk>>>(h, y2, g_fft, b_fft, z2b, z2h, z2l, VV*256, 0, 1);

    // Stage 3: conv + BN + gelu + transpose
    conv_mma3<<<dim3(2, MB), blk, GSM>>>(z2h, z2l, wh + OFF_CNV, wl + OFF_CNV, conv_b, h);
    final_kernel<<<RTOT, blk>>>(z2b, h, bn_g, bn_b, bn_m, bn_v, out);
}

// round 11
// speedup vs baseline: 3.4024x; 1.1961x over previous
#include <cuda_runtime.h>
#include <cuda_fp16.h>
#include <math.h>
#include <stdint.h>

#define NN 32
#define VV 25
#define TT 64
#define RTOT (NN*VV*TT)   /* 51200 */

// ------------------------- scratch (device globals) -------------------------
__device__ float g_bufB[(size_t)RTOT * 512];
__device__ float g_h   [(size_t)RTOT * 256];
__device__ float g_y1  [(size_t)RTOT * 256];
__device__ float g_y2  [(size_t)RTOT * 256];
__device__ float g_z2  [(size_t)RTOT * 256];
__device__ float g_atts[NN*VV*VV*3];
__device__ float g_attf[NN*TT*TT*2];   // transposed layout [n][q][t][s]
__device__ float g_attb[NN*TT*TT*2];
__device__ float g_ps  [96*625];
__device__ float g_pt  [128*64*64];
// fp16 activation buffers (16B-aligned for cp.async)
__device__ __align__(128) __half g_ah [(size_t)RTOT * 1024];
__device__ __align__(128) __half g_xh [(size_t)RTOT * 256];
__device__ __align__(128) __half g_y1h[(size_t)RTOT * 256];
__device__ __align__(128) __half g_y2h[(size_t)RTOT * 256];
__device__ __align__(128) __half g_z2h[(size_t)RTOT * 256];
#define WTOT 1277952
__device__ __align__(128) __half g_wh[WTOT];
__device__ __align__(128) __half g_wl[WTOT];
#define OFF_QKS 0         /* K=256  N=384  */
#define OFF_WOS 98304     /* K=768  N=256  */
#define OFF_FFS 294912    /* K=256  N=256  */
#define OFF_QKT 360448    /* K=256  N=512  */
#define OFF_WOT 491520    /* K=1024 N=256  */
#define OFF_FFT 753664    /* K=256  N=256  */
#define OFF_CNV 819200    /* K=1792 N=256  */

__device__ __forceinline__ float gelu_f(float x) {
    return 0.5f * x * (1.0f + erff(x * 0.7071067811865475f));
}
__device__ __forceinline__ uint32_t packh2(float a, float b) {
    __half2 h = __floats2half2_rn(a, b);
    return *(uint32_t*)&h;
}
__device__ __forceinline__ uint32_t smem_u32(const void* p) {
    uint32_t a;
    asm("{ .reg .u64 t; cvta.to.shared.u64 t, %1; cvt.u32.u64 %0, t; }" : "=r"(a) : "l"(p));
    return a;
}
__device__ __forceinline__ void ldm4(uint32_t &r0, uint32_t &r1, uint32_t &r2,
                                     uint32_t &r3, uint32_t a) {
    asm volatile("ldmatrix.sync.aligned.m8n8.x4.shared.b16 {%0,%1,%2,%3}, [%4];"
        : "=r"(r0), "=r"(r1), "=r"(r2), "=r"(r3) : "r"(a));
}
__device__ __forceinline__ void mma16816h(float* c, const uint32_t* a, const uint32_t* b) {
    asm volatile(
        "mma.sync.aligned.m16n8k16.row.col.f32.f16.f16.f32 "
        "{%0,%1,%2,%3}, {%4,%5,%6,%7}, {%8,%9}, {%0,%1,%2,%3};"
        : "+f"(c[0]), "+f"(c[1]), "+f"(c[2]), "+f"(c[3])
        : "r"(a[0]), "r"(a[1]), "r"(a[2]), "r"(a[3]), "r"(b[0]), "r"(b[1]));
}
__device__ __forceinline__ void cpa16(uint32_t dst, const void* src) {
    asm volatile("cp.async.cg.shared.global [%0], [%1], 16;" :: "r"(dst), "l"(src));
}
__device__ __forceinline__ void cpa16z(uint32_t dst, const void* src, int sz) {
    asm volatile("cp.async.cg.shared.global [%0], [%1], 16, %2;" :: "r"(dst), "l"(src), "r"(sz));
}
#define CPA_COMMIT() asm volatile("cp.async.commit_group;" ::: "memory")
#define CPA_WAIT3() asm volatile("cp.async.wait_group 3;" ::: "memory")
#define CPA_WAIT2() asm volatile("cp.async.wait_group 2;" ::: "memory")
#define CPA_WAIT1() asm volatile("cp.async.wait_group 1;" ::: "memory")
#define CPA_WAIT0() asm volatile("cp.async.wait_group 0;" ::: "memory")

// smem swizzle for 64B rows (32 fp16): 16B chunk ch of row r at (ch ^ ((r>>1)&3))*16
#define SWZ(row, ch) ((uint32_t)((row) * 64 + ((((ch) ^ (((row) >> 1) & 3))) << 4)))

// ==== fp16 HMMA GEMM: 128x128 tile, k-chunk 32, 4-stage, 2 CTA/SM ===========
// C[M,N] = A[M,K](fp16) @ (Bh+Bl)[K,N] + bias; B stored [N][K].
// stage 24KB: A(8K) Bh(8K) Bl(8K); 4 stages = 96KB.
#define GSM (4*24576)
__global__ __launch_bounds__(256, 2) void gemm_h(
        const __half* __restrict__ A, const __half* __restrict__ Bh,
        const __half* __restrict__ Bl, const float* __restrict__ bias,
        float* __restrict__ C, int M, int N, int K) {
    extern __shared__ char sm[];
    const uint32_t sbase = smem_u32(sm);
    const int tid = threadIdx.x, lane = tid & 31, w = tid >> 5;
    const int wm = w & 3, wn = w >> 2;
    const int bm = blockIdx.y << 7, bn = blockIdx.x << 7;
    float acc[2][8][4];
#pragma unroll
    for (int i = 0; i < 2; i++)
#pragma unroll
        for (int j = 0; j < 8; j++)
#pragma unroll
            for (int q = 0; q < 4; q++) acc[i][j][q] = 0.f;
    const int nch = K >> 5;

    auto load_stage = [&](int c) {
        uint32_t st = sbase + (c & 3) * 24576;
        const int k0 = c << 5;
#pragma unroll
        for (int j = 0; j < 2; j++) {
            int f = j * 256 + tid;
            int row = f >> 2, ch = f & 3;
            uint32_t off = SWZ(row, ch);
            cpa16(st + off,         A  + (size_t)(bm + row) * K + k0 + ch * 8);
            cpa16(st + 8192 + off,  Bh + (size_t)(bn + row) * K + k0 + ch * 8);
            cpa16(st + 16384 + off, Bl + (size_t)(bn + row) * K + k0 + ch * 8);
        }
        CPA_COMMIT();
    };
    load_stage(0);
    load_stage(1);
    load_stage(2);
    for (int c = 0; c < nch; c++) {
        if (c + 3 < nch) { load_stage(c + 3); CPA_WAIT3(); }
        else if (c + 2 < nch) CPA_WAIT2();
        else if (c + 1 < nch) CPA_WAIT1();
        else CPA_WAIT0();
        __syncthreads();
        const uint32_t sA = sbase + (c & 3) * 24576;
        const uint32_t sBh = sA + 8192, sBl = sA + 16384;
#pragma unroll
        for (int kk = 0; kk < 2; kk++) {
            uint32_t af[2][4];
            const int arow = wm * 32 + (lane & 15);
            const int achunk = kk * 2 + (lane >> 4);
#pragma unroll
            for (int mi = 0; mi < 2; mi++) {
                int row = arow + mi * 16;
                ldm4(af[mi][0], af[mi][1], af[mi][2], af[mi][3], sA + SWZ(row, achunk));
            }
            const int bchunk = kk * 2 + ((lane >> 3) & 1);
#pragma unroll
            for (int half = 0; half < 2; half++) {
                uint32_t bh[4][2], bl[4][2];
#pragma unroll
                for (int p = 0; p < 2; p++) {
                    int brow = wn * 64 + half * 32 + p * 16 + ((lane & 16) >> 1) + (lane & 7);
                    ldm4(bh[2*p][0], bh[2*p][1], bh[2*p+1][0], bh[2*p+1][1],
                         sBh + SWZ(brow, bchunk));
                    ldm4(bl[2*p][0], bl[2*p][1], bl[2*p+1][0], bl[2*p+1][1],
                         sBl + SWZ(brow, bchunk));
                }
#pragma unroll
                for (int mi = 0; mi < 2; mi++)
#pragma unroll
                    for (int nf = 0; nf < 4; nf++)
                        mma16816h(acc[mi][half * 4 + nf], af[mi], bh[nf]);
#pragma unroll
                for (int mi = 0; mi < 2; mi++)
#pragma unroll
                    for (int nf = 0; nf < 4; nf++)
                        mma16816h(acc[mi][half * 4 + nf], af[mi], bl[nf]);
            }
        }
        __syncthreads();
    }
    const int gid = lane >> 2, tig = lane & 3;
#pragma unroll
    for (int mi = 0; mi < 2; mi++)
#pragma unroll
        for (int nf = 0; nf < 8; nf++) {
            int col = bn + wn * 64 + nf * 8 + tig * 2;
            float b0v = bias[col], b1v = bias[col + 1];
            int r0 = bm + wm * 32 + mi * 16 + gid;
            *(float2*)(C + (size_t)r0 * N + col) =
                make_float2(acc[mi][nf][0] + b0v, acc[mi][nf][1] + b1v);
            *(float2*)(C + (size_t)(r0 + 8) * N + col) =
                make_float2(acc[mi][nf][2] + b0v, acc[mi][nf][3] + b1v);
        }
}

// ===== conv (implicit im2col) fp16 HMMA: K=1792, N=256, 4-stage ==============
__global__ __launch_bounds__(256, 2) void conv_h(
        const __half* __restrict__ Z, const __half* __restrict__ Bh,
        const __half* __restrict__ Bl, const float* __restrict__ bias,
        float* __restrict__ C) {
    const int N = 256, K = 1792;
    extern __shared__ char sm[];
    const uint32_t sbase = smem_u32(sm);
    const int tid = threadIdx.x, lane = tid & 31, w = tid >> 5;
    const int wm = w & 3, wn = w >> 2;
    const int bm = blockIdx.y << 7, bn = blockIdx.x << 7;
    float acc[2][8][4];
#pragma unroll
    for (int i = 0; i < 2; i++)
#pragma unroll
        for (int j = 0; j < 8; j++)
#pragma unroll
            for (int q = 0; q < 4; q++) acc[i][j][q] = 0.f;
    const int nch = K >> 5;   // 56

    auto load_stage = [&](int c) {
        uint32_t st = sbase + (c & 3) * 24576;
        const int k0 = c << 5;
        const int dt = (k0 >> 8) - 3;
        const int iio = k0 & 255;
#pragma unroll
        for (int j = 0; j < 2; j++) {
            int f = j * 256 + tid;
            int row = f >> 2, ch = f & 3;
            uint32_t off = SWZ(row, ch);
            int grow = bm + row;
            int t = (grow / VV) % TT;
            int tt = t + dt;
            int ok = (tt >= 0 && tt < TT);
            size_t srcoff = ok ? ((size_t)grow + (size_t)dt * VV) * 256 + iio + ch * 8 : 0;
            cpa16z(st + off, Z + srcoff, ok ? 16 : 0);
            cpa16(st + 8192 + off,  Bh + (size_t)(bn + row) * K + k0 + ch * 8);
            cpa16(st + 16384 + off, Bl + (size_t)(bn + row) * K + k0 + ch * 8);
        }
        CPA_COMMIT();
    };
    load_stage(0);
    load_stage(1);
    load_stage(2);
    for (int c = 0; c < nch; c++) {
        if (c + 3 < nch) { load_stage(c + 3); CPA_WAIT3(); }
        else if (c + 2 < nch) CPA_WAIT2();
        else if (c + 1 < nch) CPA_WAIT1();
        else CPA_WAIT0();
        __syncthreads();
        const uint32_t sA = sbase + (c & 3) * 24576;
        const uint32_t sBh = sA + 8192, sBl = sA + 16384;
#pragma unroll
        for (int kk = 0; kk < 2; kk++) {
            uint32_t af[2][4];
            const int arow = wm * 32 + (lane & 15);
            const int achunk = kk * 2 + (lane >> 4);
#pragma unroll
            for (int mi = 0; mi < 2; mi++) {
                int row = arow + mi * 16;
                ldm4(af[mi][0], af[mi][1], af[mi][2], af[mi][3], sA + SWZ(row, achunk));
            }
            const int bchunk = kk * 2 + ((lane >> 3) & 1);
#pragma unroll
            for (int half = 0; half < 2; half++) {
                uint32_t bh[4][2], bl[4][2];
#pragma unroll
                for (int p = 0; p < 2; p++) {
                    int brow = wn * 64 + half * 32 + p * 16 + ((lane & 16) >> 1) + (lane & 7);
                    ldm4(bh[2*p][0], bh[2*p][1], bh[2*p+1][0], bh[2*p+1][1],
                         sBh + SWZ(brow, bchunk));
                    ldm4(bl[2*p][0], bl[2*p][1], bl[2*p+1][0], bl[2*p+1][1],
                         sBl + SWZ(brow, bchunk));
                }
#pragma unroll
                for (int mi = 0; mi < 2; mi++)
#pragma unroll
                    for (int nf = 0; nf < 4; nf++)
                        mma16816h(acc[mi][half * 4 + nf], af[mi], bh[nf]);
#pragma unroll
                for (int mi = 0; mi < 2; mi++)
#pragma unroll
                    for (int nf = 0; nf < 4; nf++)
                        mma16816h(acc[mi][half * 4 + nf], af[mi], bl[nf]);
            }
        }
        __syncthreads();
    }
    const int gid = lane >> 2, tig = lane & 3;
#pragma unroll
    for (int mi = 0; mi < 2; mi++)
#pragma unroll
        for (int nf = 0; nf < 8; nf++) {
            int col = bn + wn * 64 + nf * 8 + tig * 2;
            float b0v = bias[col], b1v = bias[col + 1];
            int r0 = bm + wm * 32 + mi * 16 + gid;
            *(float2*)(C + (size_t)r0 * N + col) =
                make_float2(acc[mi][nf][0] + b0v, acc[mi][nf][1] + b1v);
            *(float2*)(C + (size_t)(r0 + 8) * N + col) =
                make_float2(acc[mi][nf][2] + b0v, acc[mi][nf][3] + b1v);
        }
}

// ---------------- prep kernels (x convert; weight fp16 hi/lo splits) --------
#define XITEMS 3276800
__global__ void prep_x(const float* __restrict__ x, __half* __restrict__ xh) {
    size_t idx = (size_t)blockIdx.x * 256 + threadIdx.x;
    if (idx >= XITEMS) return;
    size_t i = idx * 4;
    float4 v = *(const float4*)(x + i);
    *(uint2*)(xh + i) = make_uint2(packh2(v.x, v.y), packh2(v.z, v.w));
}
__global__ void prep_w(
        const float* __restrict__ Wqks, const float* __restrict__ Wos,
        const float* __restrict__ Wffs, const float* __restrict__ Wqkt,
        const float* __restrict__ Wot,  const float* __restrict__ Wfft,
        const float* __restrict__ Wcnv,
        __half* __restrict__ wh, __half* __restrict__ wl,
        int jbase, int jcount) {
    int li = blockIdx.x * 256 + threadIdx.x;
    if (li >= jcount) return;
    long j = (long)jbase + li;
    const float* W; int K, N, off; int isconv = 0;
    if (j < 98304)                    { W = Wqks; K = 256;  N = 384; off = OFF_QKS; }
    else if ((j -= 98304)  < 196608)  { W = Wos;  K = 768;  N = 256; off = OFF_WOS; }
    else if ((j -= 196608) < 65536)   { W = Wffs; K = 256;  N = 256; off = OFF_FFS; }
    else if ((j -= 65536)  < 131072)  { W = Wqkt; K = 256;  N = 512; off = OFF_QKT; }
    else if ((j -= 131072) < 262144)  { W = Wot;  K = 1024; N = 256; off = OFF_WOT; }
    else if ((j -= 262144) < 65536)   { W = Wfft; K = 256;  N = 256; off = OFF_FFT; }
    else if ((j -= 65536)  < 458752)  { W = Wcnv; K = 1792; N = 256; off = OFF_CNV; isconv = 1; }
    else return;
    float v = W[j];
    __half h = __float2half(v);
    size_t dst;
    if (isconv) {
        int o = (int)(j / 1792), r = (int)(j % 1792);
        int ii = r / 7, kw = r % 7;
        dst = (size_t)off + (size_t)o * 1792 + kw * 256 + ii;
    } else {
        int k = (int)(j / N), n = (int)(j % N);
        dst = (size_t)off + (size_t)n * K + k;
    }
    wh[dst] = h;
    wl[dst] = __float2half(v - __half2float(h));
}

// ------ deint_s: smem-staged, coalesced writes. block per (n,u,t-half) ------
#define DS_SMEM (6 * 2049 * 4)
__global__ __launch_bounds__(256) void deint_s2(const float* __restrict__ qk,
                                                float* __restrict__ qT,
                                                float* __restrict__ kT) {
    extern __shared__ float sms[];
    int b = blockIdx.x;
    int th = b & 1;
    int u = (b >> 1) % VV;
    int n = b / (VV * 2);
    int t0 = th << 5;
    const float* src = qk + ((size_t)(n * VV + u) * TT + t0) * 384;
    for (int i = threadIdx.x; i < 32 * 384; i += 256) {
        int tt = i / 384, col = i % 384;
        int ci = col / 6, r = col % 6;
        sms[r * 2049 + tt * 64 + ci] = src[i];
    }
    __syncthreads();
#pragma unroll
    for (int p = 0; p < 6; p++) {
        int s = (p < 3) ? p : p - 3;
        float* dst = ((p < 3) ? qT : kT) +
                     (((size_t)(n * 3 + s) * VV + u) << 12) + (size_t)t0 * 64;
        for (int i = threadIdx.x; i < 2048; i += 256)
            dst[i] = sms[p * 2049 + i];
    }
}

// ------ deint_t: smem-staged, coalesced writes. block per (n,t) --------------
#define DT_SMEM (8 * 1665 * 4)
__global__ __launch_bounds__(256) void deint_t2(const float* __restrict__ qkt,
                                                float* __restrict__ qd,
                                                float* __restrict__ kd) {
    extern __shared__ float smt[];
    int b = blockIdx.x;
    int t = b % TT, n = b / TT;
    const float* src = qkt + ((size_t)(n * TT + t) * VV) * 512;
    for (int i = threadIdx.x; i < 25 * 512; i += 256) {
        int v = i >> 9, col = i & 511;
        int ci = col >> 3, j = col & 7;
        smt[j * 1665 + v * 64 + ci] = src[i];
    }
    __syncthreads();
#pragma unroll
    for (int p = 0; p < 8; p++) {
        int m = p & 3;
        float* dst = ((p < 4) ? qd : kd) + ((size_t)(n * 4 + m) * TT + t) * 1600;
        for (int i = threadIdx.x; i < 1600; i += 256)
            dst[i] = smt[p * 1665 + i];
    }
}

// spatial attention split-K partials
__global__ __launch_bounds__(128) void att_s_part(
        const float* __restrict__ qT, const float* __restrict__ kT,
        float* __restrict__ ps) {
    int ns = blockIdx.x;
    int kc0 = blockIdx.y << 9;
    __shared__ float qs[25][132], ks[25][132];
    const float* qb = qT + ((size_t)ns * VV << 12);
    const float* kb = kT + ((size_t)ns * VV << 12);
    int t = threadIdx.x;
    int u0 = (t / 25) * 5, v = t % 25;
    float acc[5] = {0.f, 0.f, 0.f, 0.f, 0.f};
    for (int kc = kc0; kc < kc0 + 512; kc += 128) {
        for (int i = t; i < 25 * 128; i += 128) {
            int uu = i >> 7, e = i & 127;
            qs[uu][e] = qb[((size_t)uu << 12) + kc + e];
            ks[uu][e] = kb[((size_t)uu << 12) + kc + e];
        }
        __syncthreads();
        if (t < 125) {
#pragma unroll 4
            for (int e = 0; e < 128; e++) {
                float kv = ks[v][e];
                acc[0] = fmaf(qs[u0 + 0][e], kv, acc[0]);
                acc[1] = fmaf(qs[u0 + 1][e], kv, acc[1]);
                acc[2] = fmaf(qs[u0 + 2][e], kv, acc[2]);
                acc[3] = fmaf(qs[u0 + 3][e], kv, acc[3]);
                acc[4] = fmaf(qs[u0 + 4][e], kv, acc[4]);
            }
        }
        __syncthreads();
    }
    if (t < 125) {
#pragma unroll
        for (int i = 0; i < 5; i++)
            atomicAdd(&ps[(size_t)ns * 625 + (u0 + i) * 25 + v], acc[i]);
    }
}

__global__ void att_s_fin(const float* __restrict__ ps, const float* __restrict__ alphas,
                          const float* __restrict__ att0, float* __restrict__ att) {
    int idx = blockIdx.x * 256 + threadIdx.x;
    if (idx >= 96 * 625) return;
    int ns = idx / 625, r = idx % 625;
    int n = ns / 3, s = ns % 3, u = r / 25, v = r % 25;
    att[((size_t)(n * VV + u) * VV + v) * 3 + s] =
        tanhf(ps[idx] * (1.f / 4096.f)) * alphas[s] + att0[((size_t)u * VV + v) * 3 + s];
}

// y_s: block per (n,t); fp16 output
__global__ __launch_bounds__(256) void ys2(const float* __restrict__ x,
                                           const float* __restrict__ att,
                                           __half* __restrict__ yh) {
    __shared__ float xs[25][256];
    __shared__ float as_[25 * 25 * 3];
    int b = blockIdx.x;
    int n = b >> 6, t = b & 63;
    int tid = threadIdx.x;
    for (int i = tid; i < 25 * 256; i += 256) {
        int u = i >> 8, c = i & 255;
        xs[u][c] = x[((size_t)(n * VV + u) * TT + t) * 256 + c];
    }
    for (int i = tid; i < 1875; i += 256) as_[i] = att[(size_t)n * 1875 + i];
    __syncthreads();
    int c = tid;
#pragma unroll 1
    for (int v = 0; v < VV; v++) {
        float a0 = 0.f, a1 = 0.f, a2 = 0.f;
#pragma unroll
        for (int u = 0; u < VV; u++) {
            float xv = xs[u][c];
            a0 = fmaf(xv, as_[(u * VV + v) * 3 + 0], a0);
            a1 = fmaf(xv, as_[(u * VV + v) * 3 + 1], a1);
            a2 = fmaf(xv, as_[(u * VV + v) * 3 + 2], a2);
        }
        size_t base = ((size_t)(n * VV + v) * TT + t) * 768 + c * 3;
        yh[base]     = __float2half(a0);
        yh[base + 1] = __float2half(a1);
        yh[base + 2] = __float2half(a2);
    }
}

// LN + residual + gelu; writes fp16 (+ optional fp32)
__global__ void ln2(const float* __restrict__ h, const float* __restrict__ res,
                    const float* __restrict__ g, const float* __restrict__ b,
                    float* __restrict__ outf, __half* __restrict__ oh,
                    int G, int mode, int wf) {
    int grp = blockIdx.x;
    const float* hp = h + (size_t)grp * G;
    const float* rp = res + (size_t)grp * G;
    float s = 0.f, sq = 0.f;
    for (int i = threadIdx.x; i < G; i += blockDim.x) {
        float v = hp[i]; s += v; sq = fmaf(v, v, sq);
    }
    for (int o = 16; o; o >>= 1) {
        s += __shfl_down_sync(0xffffffffu, s, o);
        sq += __shfl_down_sync(0xffffffffu, sq, o);
    }
    __shared__ float ss[8], sqs[8];
    __shared__ float mean_s, inv_s;
    int w = threadIdx.x >> 5;
    if ((threadIdx.x & 31) == 0) { ss[w] = s; sqs[w] = sq; }
    __syncthreads();
    if (threadIdx.x == 0) {
        float S = 0.f, Q = 0.f;
        for (int i = 0; i < 8; i++) { S += ss[i]; Q += sqs[i]; }
        float mean = S / G;
        float var = Q / G - mean * mean;
        mean_s = mean; inv_s = rsqrtf(var + 1e-5f);
    }
    __syncthreads();
    float mean = mean_s, inv = inv_s;
    int n = 0, v = 0;
    if (mode == 1) { n = grp / VV; v = grp % VV; }
    for (int i = threadIdx.x; i < G; i += blockDim.x) {
        float val = gelu_f(rp[i] + fmaf((hp[i] - mean) * inv, g[i], b[i]));
        size_t dst;
        if (mode == 0) dst = (size_t)grp * G + i;
        else {
            int t = i >> 8, c = i & 255;
            dst = ((size_t)(n * TT + t) * VV + v) * 256 + c;
        }
        if (wf) outf[dst] = val;
        oh[dst] = __float2half(val);
    }
}

// temporal attention split-K partials
__global__ __launch_bounds__(256) void att_t_part(
        const float* __restrict__ qd, const float* __restrict__ kd,
        float* __restrict__ pt) {
    int nm = blockIdx.x;
    int kb = blockIdx.y * 320;
    __shared__ float Qs[64][68], Ks[64][68];
    const float* qb = qd + (size_t)nm * TT * 1600;
    const float* kb_ = kd + (size_t)nm * TT * 1600;
    const int tid = threadIdx.x;
    const int tx = tid & 15, ty = tid >> 4;
    const int lr = tid >> 2, lc = (tid & 3) << 4;
    float acc[4][4] = {};
    for (int kc = kb; kc < kb + 320; kc += 64) {
#pragma unroll
        for (int j = 0; j < 4; j++) {
            float4 q4 = *(const float4*)(qb + (size_t)lr * 1600 + kc + lc + j * 4);
            float4 k4 = *(const float4*)(kb_ + (size_t)lr * 1600 + kc + lc + j * 4);
            Qs[lc + j*4 + 0][lr] = q4.x; Qs[lc + j*4 + 1][lr] = q4.y;
            Qs[lc + j*4 + 2][lr] = q4.z; Qs[lc + j*4 + 3][lr] = q4.w;
            Ks[lc + j*4 + 0][lr] = k4.x; Ks[lc + j*4 + 1][lr] = k4.y;
            Ks[lc + j*4 + 2][lr] = k4.z; Ks[lc + j*4 + 3][lr] = k4.w;
        }
        __syncthreads();
#pragma unroll 8
        for (int kk = 0; kk < 64; kk++) {
            float4 aq = *(const float4*)(&Qs[kk][ty << 2]);
            float4 bk = *(const float4*)(&Ks[kk][tx << 2]);
            float a[4] = {aq.x, aq.y, aq.z, aq.w};
            float b[4] = {bk.x, bk.y, bk.z, bk.w};
#pragma unroll
            for (int i = 0; i < 4; i++)
#pragma unroll
                for (int j = 0; j < 4; j++) acc[i][j] = fmaf(a[i], b[j], acc[i][j]);
        }
        __syncthreads();
    }
#pragma unroll
    for (int i = 0; i < 4; i++)
#pragma unroll
        for (int j = 0; j < 4; j++) {
            int t_ = (ty << 2) + i, q_ = (tx << 2) + j;
            atomicAdd(&pt[(size_t)nm * 4096 + t_ * 64 + q_], acc[i][j]);
        }
}

__global__ void att_t_fin(const float* __restrict__ pt, const float* __restrict__ alf,
                          const float* __restrict__ alb, float* __restrict__ attf,
                          float* __restrict__ attb) {
    int idx = blockIdx.x * 256 + threadIdx.x;
    if (idx >= 128 * 4096) return;
    int nm = idx >> 12, r = idx & 4095;
    int t = r >> 6, q = r & 63;
    int n = nm >> 2, m = nm & 3, s = m & 1, dir = m >> 1;
    float val = tanhf(pt[idx] * (1.f / 1600.f)) * (dir ? alb[s] : alf[s]);
    size_t o = ((size_t)(n * TT + q) * TT + t) * 2 + s;
    if (dir == 0) attf[o] = (q <= t) ? val : 0.f;
    else          attb[o] = (q >= t) ? val : 0.f;
}

// z apply: fp16 output
__global__ __launch_bounds__(256) void z2k(const float* __restrict__ y2t,
                                           const float* __restrict__ attf,
                                           const float* __restrict__ attb,
                                           __half* __restrict__ zh) {
    extern __shared__ float zs[];
    float* ys = zs;
    float* as_ = zs + 64 * 256;
    int b = blockIdx.x;
    int n = b / VV, v = b % VV;
    int tid = threadIdx.x;
    for (int i = tid; i < 64 * 256; i += 256) {
        int t = i >> 8, c = i & 255;
        ys[t * 256 + c] = y2t[((size_t)(n * TT + t) * VV + v) * 256 + c];
    }
    __syncthreads();
    int c = tid;
    for (int q = 0; q < TT; q++) {
        if (tid < 128) as_[tid] = attf[(size_t)n * 8192 + q * 128 + tid];
        else           as_[tid] = attb[(size_t)n * 8192 + q * 128 + (tid - 128)];
        __syncthreads();
        float f0 = 0.f, f1 = 0.f, b0 = 0.f, b1 = 0.f;
#pragma unroll 8
        for (int t = 0; t < TT; t++) {
            float yv = ys[t * 256 + c];
            f0 = fmaf(yv, as_[t * 2], f0);       f1 = fmaf(yv, as_[t * 2 + 1], f1);
            b0 = fmaf(yv, as_[128 + t * 2], b0); b1 = fmaf(yv, as_[128 + t * 2 + 1], b1);
        }
        size_t base = ((size_t)(n * TT + q) * VV + v) * 1024;
        *(uint32_t*)(zh + base + c * 2) = packh2(f0, f1);
        *(uint32_t*)(zh + base + 512 + c * 2) = packh2(b0, b1);
        __syncthreads();
    }
}

__global__ void final_kernel(const float* __restrict__ z2, const float* __restrict__ cv,
                             const float* __restrict__ bn_g, const float* __restrict__ bn_b,
                             const float* __restrict__ bn_m, const float* __restrict__ bn_v,
                             float* __restrict__ out) {
    size_t i = (size_t)blockIdx.x * 256 + threadIdx.x;
    int o = (int)(i & 255);
    size_t r = i >> 8;
    int v = (int)(r % VV);
    size_t r2 = r / VV;
    int t = (int)(r2 % TT);
    int n = (int)(r2 / TT);
    float c1 = fmaf((cv[i] - bn_m[o]) * rsqrtf(bn_v[o] + 1e-5f), bn_g[o], bn_b[o]);
    out[((size_t)(n * VV + v) * TT + t) * 256 + o] = gelu_f(z2[i] + c1);
}

// ------------------------------- launcher -----------------------------------
extern "C" void kernel_launch(void* const* d_in, const int* in_sizes, int n_in,
                              void* d_out, int out_size) {
    const float* x       = (const float*)d_in[0];
    const float* Wqk_s   = (const float*)d_in[1];
    const float* bqk_s   = (const float*)d_in[2];
    const float* alphas  = (const float*)d_in[3];
    const float* att0s   = (const float*)d_in[4];
    const float* Wo_s    = (const float*)d_in[5];
    const float* bo_s    = (const float*)d_in[6];
    const float* g_os    = (const float*)d_in[7];
    const float* b_os    = (const float*)d_in[8];
    const float* Wff_s   = (const float*)d_in[9];
    const float* bff_s   = (const float*)d_in[10];
    const float* g_ffs   = (const float*)d_in[11];
    const float* b_ffs   = (const float*)d_in[12];
    const float* Wqk_t   = (const float*)d_in[13];
    const float* bqk_t   = (const float*)d_in[14];
    const float* alphat_f= (const float*)d_in[15];
    const float* alphat_b= (const float*)d_in[16];
    const float* Wo_t    = (const float*)d_in[17];
    const float* bo_t    = (const float*)d_in[18];
    const float* g_ot    = (const float*)d_in[19];
    const float* b_ot    = (const float*)d_in[20];
    const float* Wff_t   = (const float*)d_in[21];
    const float* bff_t   = (const float*)d_in[22];
    const float* g_fft   = (const float*)d_in[23];
    const float* b_fft   = (const float*)d_in[24];
    const float* conv_w  = (const float*)d_in[25];
    const float* conv_b  = (const float*)d_in[26];
    const float* bn_g    = (const float*)d_in[27];
    const float* bn_b    = (const float*)d_in[28];
    const float* bn_m    = (const float*)d_in[29];
    const float* bn_v    = (const float*)d_in[30];
    float* out = (float*)d_out;

    void *pB, *pH, *pY1, *pY2, *pZ2, *pAS, *pAF, *pAB, *pWH, *pWL, *pPS, *pPT;
    void *pAH, *pXH, *pY1H, *pY2H, *pZ2H;
    cudaGetSymbolAddress(&pB,  g_bufB);
    cudaGetSymbolAddress(&pH,  g_h);
    cudaGetSymbolAddress(&pY1, g_y1);
    cudaGetSymbolAddress(&pY2, g_y2);
    cudaGetSymbolAddress(&pZ2, g_z2);
    cudaGetSymbolAddress(&pAS, g_atts);
    cudaGetSymbolAddress(&pAF, g_attf);
    cudaGetSymbolAddress(&pAB, g_attb);
    cudaGetSymbolAddress(&pPS, g_ps);
    cudaGetSymbolAddress(&pPT, g_pt);
    cudaGetSymbolAddress(&pWH, g_wh);
    cudaGetSymbolAddress(&pWL, g_wl);
    cudaGetSymbolAddress(&pAH, g_ah);
    cudaGetSymbolAddress(&pXH, g_xh);
    cudaGetSymbolAddress(&pY1H, g_y1h);
    cudaGetSymbolAddress(&pY2H, g_y2h);
    cudaGetSymbolAddress(&pZ2H, g_z2h);
    float* bufB = (float*)pB;
    float* h    = (float*)pH;  float* y1   = (float*)pY1;
    float* y2   = (float*)pY2; float* z2b  = (float*)pZ2;
    float* atts = (float*)pAS; float* attf = (float*)pAF;
    float* attb = (float*)pAB;
    float* ps   = (float*)pPS; float* pt   = (float*)pPT;
    __half* wh  = (__half*)pWH;
    __half* wl  = (__half*)pWL;
    __half* ah  = (__half*)pAH;
    __half* xh  = (__half*)pXH;
    __half* y1h = (__half*)pY1H;
    __half* y2h = (__half*)pY2H;
    __half* z2h = (__half*)pZ2H;

    cudaFuncSetAttribute(gemm_h, cudaFuncAttributeMaxDynamicSharedMemorySize, GSM);
    cudaFuncSetAttribute(conv_h, cudaFuncAttributeMaxDynamicSharedMemorySize, GSM);
    cudaFuncSetAttribute(z2k, cudaFuncAttributeMaxDynamicSharedMemorySize, (64*256 + 256) * 4);
    cudaFuncSetAttribute(deint_s2, cudaFuncAttributeMaxDynamicSharedMemorySize, DS_SMEM);
    cudaFuncSetAttribute(deint_t2, cudaFuncAttributeMaxDynamicSharedMemorySize, DT_SMEM);

    dim3 blk(256);
    const int MB = RTOT / 128;   // 400
    const int WHALF = WTOT / 2;

    prep_x<<<(XITEMS + 255) / 256, blk>>>(x, xh);
    prep_w<<<(WHALF + 255) / 256, blk>>>(Wqk_s, Wo_s, Wff_s, Wqk_t, Wo_t, Wff_t,
                                         conv_w, wh, wl, 0, WHALF);
    prep_w<<<(WHALF + 255) / 256, blk>>>(Wqk_s, Wo_s, Wff_s, Wqk_t, Wo_t, Wff_t,
                                         conv_w, wh, wl, WHALF, WTOT - WHALF);
    cudaMemsetAsync(ps, 0, 96 * 625 * sizeof(float));
    cudaMemsetAsync(pt, 0, 128 * 4096 * sizeof(float));

    // Stage 1: spatial
    gemm_h<<<dim3(3, MB), blk, GSM>>>(xh, wh + OFF_QKS, wl + OFF_QKS, bqk_s, bufB, RTOT, 384, 256);
    deint_s2<<<NN * VV * 2, blk, DS_SMEM>>>(bufB, h, y1);
    att_s_part<<<dim3(96, 8), 128>>>(h, y1, ps);
    att_s_fin<<<(96 * 625 + 255) / 256, blk>>>(ps, alphas, att0s, atts);
    ys2<<<NN * TT, blk>>>(x, atts, ah);
    gemm_h<<<dim3(2, MB), blk, GSM>>>(ah, wh + OFF_WOS, wl + OFF_WOS, bo_s, h, RTOT, 256, 768);
    ln2<<<NN*VV, blk>>>(h, x, g_os, b_os, y1, y1h, TT*256, 0, 0);
    gemm_h<<<dim3(2, MB), blk, GSM>>>(y1h, wh + OFF_FFS, wl + OFF_FFS, bff_s, h, RTOT, 256, 256);
    ln2<<<NN*VV, blk>>>(h, x, g_ffs, b_ffs, y2, y2h, TT*256, 1, 1);

    // Stage 2: temporal
    gemm_h<<<dim3(4, MB), blk, GSM>>>(y2h, wh + OFF_QKT, wl + OFF_QKT, bqk_t, bufB, RTOT, 512, 256);
    deint_t2<<<NN * TT, blk, DT_SMEM>>>(bufB, h, y1);
    att_t_part<<<dim3(128, 5), blk>>>(h, y1, pt);
    att_t_fin<<<(128 * 4096 + 255) / 256, blk>>>(pt, alphat_f, alphat_b, attf, attb);
    z2k<<<NN * VV, blk, (64*256 + 256) * 4>>>(y2, attf, attb, ah);
    gemm_h<<<dim3(2, MB), blk, GSM>>>(ah, wh + OFF_WOT, wl + OFF_WOT, bo_t, h, RTOT, 256, 1024);
    ln2<<<NN*TT, blk>>>(h, y2, g_ot, b_ot, y1, y1h, VV*256, 0, 0);
    gemm_h<<<dim3(2, MB), blk, GSM>>>(y1h, wh + OFF_FFT, wl + OFF_FFT, bff_t, h, RTOT, 256, 256);
    ln2<<<NN*TT, blk>>>(h, y2, g_fft, b_fft, z2b, z2h, VV*256, 0, 1);

    // Stage 3: conv + BN + gelu + transpose
    conv_h<<<dim3(2, MB), blk, GSM>>>(z2h, wh + OFF_CNV, wl + OFF_CNV, conv_b, h);
    final_kernel<<<RTOT, blk>>>(z2b, h, bn_g, bn_b, bn_m, bn_v, out);
}

// round 13
// speedup vs baseline: 3.5582x; 1.0458x over previous
#include <cuda_runtime.h>
#include <cuda_fp16.h>
#include <math.h>
#include <stdint.h>

#define NN 32
#define VV 25
#define TT 64
#define RTOT (NN*VV*TT)   /* 51200 */

// ------------------------- scratch (device globals) -------------------------
__device__ float g_bufB[(size_t)RTOT * 512];
__device__ float g_h   [(size_t)RTOT * 256];
__device__ float g_y1  [(size_t)RTOT * 256];
__device__ float g_y2  [(size_t)RTOT * 256];
__device__ float g_z2  [(size_t)RTOT * 256];
__device__ float g_atts[NN*VV*VV*3];
__device__ float g_attf[NN*TT*TT*2];   // transposed layout [n][q][t][s]
__device__ float g_attb[NN*TT*TT*2];
__device__ float g_ps  [96*625];
__device__ float g_pt  [128*64*64];
// fp16 activation buffers (16B-aligned for cp.async)
__device__ __align__(128) __half g_ah [(size_t)RTOT * 1024];
__device__ __align__(128) __half g_xh [(size_t)RTOT * 256];
__device__ __align__(128) __half g_y1h[(size_t)RTOT * 256];
__device__ __align__(128) __half g_y2h[(size_t)RTOT * 256];
__device__ __align__(128) __half g_z2h[(size_t)RTOT * 256];
#define WTOT 1277952
__device__ __align__(128) __half g_wh[WTOT];
__device__ __align__(128) __half g_wl[WTOT];
#define OFF_QKS 0         /* K=256  N=384  */
#define OFF_WOS 98304     /* K=768  N=256  */
#define OFF_FFS 294912    /* K=256  N=256  */
#define OFF_QKT 360448    /* K=256  N=512  */
#define OFF_WOT 491520    /* K=1024 N=256  */
#define OFF_FFT 753664    /* K=256  N=256  */
#define OFF_CNV 819200    /* K=1792 N=256  */

__device__ __forceinline__ float gelu_f(float x) {
    return 0.5f * x * (1.0f + erff(x * 0.7071067811865475f));
}
__device__ __forceinline__ uint32_t packh2(float a, float b) {
    __half2 h = __floats2half2_rn(a, b);
    return *(uint32_t*)&h;
}
__device__ __forceinline__ uint32_t smem_u32(const void* p) {
    uint32_t a;
    asm("{ .reg .u64 t; cvta.to.shared.u64 t, %1; cvt.u32.u64 %0, t; }" : "=r"(a) : "l"(p));
    return a;
}
__device__ __forceinline__ void ldm4(uint32_t &r0, uint32_t &r1, uint32_t &r2,
                                     uint32_t &r3, uint32_t a) {
    asm volatile("ldmatrix.sync.aligned.m8n8.x4.shared.b16 {%0,%1,%2,%3}, [%4];"
        : "=r"(r0), "=r"(r1), "=r"(r2), "=r"(r3) : "r"(a));
}
__device__ __forceinline__ void mma16816h(float* c, const uint32_t* a, const uint32_t* b) {
    asm volatile(
        "mma.sync.aligned.m16n8k16.row.col.f32.f16.f16.f32 "
        "{%0,%1,%2,%3}, {%4,%5,%6,%7}, {%8,%9}, {%0,%1,%2,%3};"
        : "+f"(c[0]), "+f"(c[1]), "+f"(c[2]), "+f"(c[3])
        : "r"(a[0]), "r"(a[1]), "r"(a[2]), "r"(a[3]), "r"(b[0]), "r"(b[1]));
}
__device__ __forceinline__ void cpa16(uint32_t dst, const void* src) {
    asm volatile("cp.async.cg.shared.global [%0], [%1], 16;" :: "r"(dst), "l"(src));
}
__device__ __forceinline__ void cpa16z(uint32_t dst, const void* src, int sz) {
    asm volatile("cp.async.cg.shared.global [%0], [%1], 16, %2;" :: "r"(dst), "l"(src), "r"(sz));
}
#define CPA_COMMIT() asm volatile("cp.async.commit_group;" ::: "memory")
#define CPA_WAIT1() asm volatile("cp.async.wait_group 1;" ::: "memory")
#define CPA_WAIT0() asm volatile("cp.async.wait_group 0;" ::: "memory")

// smem swizzle for 128B rows (64 fp16): 16B chunk ch of row r at (ch ^ (r&7))*16
#define SWZ8(row, ch) ((uint32_t)((row) * 128 + (((ch) ^ ((row) & 7)) << 4)))

// ==== fp16 HMMA GEMM: 128x128 tile, k-chunk 64, 2-stage, 2 CTA/SM ===========
// C[M,N] = A[M,K](fp16) @ (Bh+Bl)[K,N] + bias; B stored [N][K].
// stage 48KB: A(16K) Bh(16K) Bl(16K); 2 stages = 96KB. Prefetch distance = 1.
#define GSM (2*49152)
__global__ __launch_bounds__(256, 2) void gemm_h(
        const __half* __restrict__ A, const __half* __restrict__ Bh,
        const __half* __restrict__ Bl, const float* __restrict__ bias,
        float* __restrict__ C, int M, int N, int K) {
    extern __shared__ char sm[];
    const uint32_t sbase = smem_u32(sm);
    const int tid = threadIdx.x, lane = tid & 31, w = tid >> 5;
    const int wm = w & 3, wn = w >> 2;
    const int bm = blockIdx.y << 7, bn = blockIdx.x << 7;
    float acc[2][8][4];
#pragma unroll
    for (int i = 0; i < 2; i++)
#pragma unroll
        for (int j = 0; j < 8; j++)
#pragma unroll
            for (int q = 0; q < 4; q++) acc[i][j][q] = 0.f;
    const int nch = K >> 6;

    auto load_stage = [&](int c) {
        uint32_t st = sbase + (c & 1) * 49152;
        const int k0 = c << 6;
#pragma unroll
        for (int j = 0; j < 4; j++) {
            int f = j * 256 + tid;
            int row = f >> 3, ch = f & 7;
            uint32_t off = SWZ8(row, ch);
            cpa16(st + off,         A  + (size_t)(bm + row) * K + k0 + ch * 8);
            cpa16(st + 16384 + off, Bh + (size_t)(bn + row) * K + k0 + ch * 8);
            cpa16(st + 32768 + off, Bl + (size_t)(bn + row) * K + k0 + ch * 8);
        }
        CPA_COMMIT();
    };
    load_stage(0);
    for (int c = 0; c < nch; c++) {
        if (c + 1 < nch) { load_stage(c + 1); CPA_WAIT1(); }
        else CPA_WAIT0();
        __syncthreads();
        const uint32_t sA = sbase + (c & 1) * 49152;
        const uint32_t sBh = sA + 16384, sBl = sA + 32768;
#pragma unroll
        for (int kk = 0; kk < 4; kk++) {
            uint32_t af[2][4];
            const int arow = wm * 32 + (lane & 15);
            const int achunk = kk * 2 + (lane >> 4);
#pragma unroll
            for (int mi = 0; mi < 2; mi++) {
                int row = arow + mi * 16;
                ldm4(af[mi][0], af[mi][1], af[mi][2], af[mi][3], sA + SWZ8(row, achunk));
            }
            const int bchunk = kk * 2 + ((lane >> 3) & 1);
#pragma unroll
            for (int half = 0; half < 2; half++) {
                uint32_t bh[4][2], bl[4][2];
#pragma unroll
                for (int p = 0; p < 2; p++) {
                    int brow = wn * 64 + half * 32 + p * 16 + ((lane & 16) >> 1) + (lane & 7);
                    ldm4(bh[2*p][0], bh[2*p][1], bh[2*p+1][0], bh[2*p+1][1],
                         sBh + SWZ8(brow, bchunk));
                    ldm4(bl[2*p][0], bl[2*p][1], bl[2*p+1][0], bl[2*p+1][1],
                         sBl + SWZ8(brow, bchunk));
                }
#pragma unroll
                for (int mi = 0; mi < 2; mi++)
#pragma unroll
                    for (int nf = 0; nf < 4; nf++)
                        mma16816h(acc[mi][half * 4 + nf], af[mi], bh[nf]);
#pragma unroll
                for (int mi = 0; mi < 2; mi++)
#pragma unroll
                    for (int nf = 0; nf < 4; nf++)
                        mma16816h(acc[mi][half * 4 + nf], af[mi], bl[nf]);
            }
        }
        __syncthreads();
    }
    const int gid = lane >> 2, tig = lane & 3;
#pragma unroll
    for (int mi = 0; mi < 2; mi++)
#pragma unroll
        for (int nf = 0; nf < 8; nf++) {
            int col = bn + wn * 64 + nf * 8 + tig * 2;
            float b0v = bias[col], b1v = bias[col + 1];
            int r0 = bm + wm * 32 + mi * 16 + gid;
            *(float2*)(C + (size_t)r0 * N + col) =
                make_float2(acc[mi][nf][0] + b0v, acc[mi][nf][1] + b1v);
            *(float2*)(C + (size_t)(r0 + 8) * N + col) =
                make_float2(acc[mi][nf][2] + b0v, acc[mi][nf][3] + b1v);
        }
}

// ===== conv (implicit im2col) fp16 HMMA: K=1792, k-chunk 64, 2-stage ========
__global__ __launch_bounds__(256, 2) void conv_h(
        const __half* __restrict__ Z, const __half* __restrict__ Bh,
        const __half* __restrict__ Bl, const float* __restrict__ bias,
        float* __restrict__ C) {
    const int N = 256, K = 1792;
    extern __shared__ char sm[];
    const uint32_t sbase = smem_u32(sm);
    const int tid = threadIdx.x, lane = tid & 31, w = tid >> 5;
    const int wm = w & 3, wn = w >> 2;
    const int bm = blockIdx.y << 7, bn = blockIdx.x << 7;
    float acc[2][8][4];
#pragma unroll
    for (int i = 0; i < 2; i++)
#pragma unroll
        for (int j = 0; j < 8; j++)
#pragma unroll
            for (int q = 0; q < 4; q++) acc[i][j][q] = 0.f;
    const int nch = K >> 6;   // 28

    auto load_stage = [&](int c) {
        uint32_t st = sbase + (c & 1) * 49152;
        const int k0 = c << 6;
        const int dt = (k0 >> 8) - 3;
        const int iio = k0 & 255;
#pragma unroll
        for (int j = 0; j < 4; j++) {
            int f = j * 256 + tid;
            int row = f >> 3, ch = f & 7;
            uint32_t off = SWZ8(row, ch);
            int grow = bm + row;
            int t = (grow / VV) % TT;
            int tt = t + dt;
            int ok = (tt >= 0 && tt < TT);
            size_t srcoff = ok ? ((size_t)grow + (size_t)dt * VV) * 256 + iio + ch * 8 : 0;
            cpa16z(st + off, Z + srcoff, ok ? 16 : 0);
            cpa16(st + 16384 + off, Bh + (size_t)(bn + row) * K + k0 + ch * 8);
            cpa16(st + 32768 + off, Bl + (size_t)(bn + row) * K + k0 + ch * 8);
        }
        CPA_COMMIT();
    };
    load_stage(0);
    for (int c = 0; c < nch; c++) {
        if (c + 1 < nch) { load_stage(c + 1); CPA_WAIT1(); }
        else CPA_WAIT0();
        __syncthreads();
        const uint32_t sA = sbase + (c & 1) * 49152;
        const uint32_t sBh = sA + 16384, sBl = sA + 32768;
#pragma unroll
        for (int kk = 0; kk < 4; kk++) {
            uint32_t af[2][4];
            const int arow = wm * 32 + (lane & 15);
            const int achunk = kk * 2 + (lane >> 4);
#pragma unroll
            for (int mi = 0; mi < 2; mi++) {
                int row = arow + mi * 16;
                ldm4(af[mi][0], af[mi][1], af[mi][2], af[mi][3], sA + SWZ8(row, achunk));
            }
            const int bchunk = kk * 2 + ((lane >> 3) & 1);
#pragma unroll
            for (int half = 0; half < 2; half++) {
                uint32_t bh[4][2], bl[4][2];
#pragma unroll
                for (int p = 0; p < 2; p++) {
                    int brow = wn * 64 + half * 32 + p * 16 + ((lane & 16) >> 1) + (lane & 7);
                    ldm4(bh[2*p][0], bh[2*p][1], bh[2*p+1][0], bh[2*p+1][1],
                         sBh + SWZ8(brow, bchunk));
                    ldm4(bl[2*p][0], bl[2*p][1], bl[2*p+1][0], bl[2*p+1][1],
                         sBl + SWZ8(brow, bchunk));
                }
#pragma unroll
                for (int mi = 0; mi < 2; mi++)
#pragma unroll
                    for (int nf = 0; nf < 4; nf++)
                        mma16816h(acc[mi][half * 4 + nf], af[mi], bh[nf]);
#pragma unroll
                for (int mi = 0; mi < 2; mi++)
#pragma unroll
                    for (int nf = 0; nf < 4; nf++)
                        mma16816h(acc[mi][half * 4 + nf], af[mi], bl[nf]);
            }
        }
        __syncthreads();
    }
    const int gid = lane >> 2, tig = lane & 3;
#pragma unroll
    for (int mi = 0; mi < 2; mi++)
#pragma unroll
        for (int nf = 0; nf < 8; nf++) {
            int col = bn + wn * 64 + nf * 8 + tig * 2;
            float b0v = bias[col], b1v = bias[col + 1];
            int r0 = bm + wm * 32 + mi * 16 + gid;
            *(float2*)(C + (size_t)r0 * N + col) =
                make_float2(acc[mi][nf][0] + b0v, acc[mi][nf][1] + b1v);
            *(float2*)(C + (size_t)(r0 + 8) * N + col) =
                make_float2(acc[mi][nf][2] + b0v, acc[mi][nf][3] + b1v);
        }
}

// ---------------- prep kernels (x convert; weight fp16 hi/lo splits) --------
#define XITEMS 3276800
__global__ void prep_x(const float* __restrict__ x, __half* __restrict__ xh) {
    size_t idx = (size_t)blockIdx.x * 256 + threadIdx.x;
    if (idx >= XITEMS) return;
    size_t i = idx * 4;
    float4 v = *(const float4*)(x + i);
    *(uint2*)(xh + i) = make_uint2(packh2(v.x, v.y), packh2(v.z, v.w));
}
__global__ void prep_w(
        const float* __restrict__ Wqks, const float* __restrict__ Wos,
        const float* __restrict__ Wffs, const float* __restrict__ Wqkt,
        const float* __restrict__ Wot,  const float* __restrict__ Wfft,
        const float* __restrict__ Wcnv,
        __half* __restrict__ wh, __half* __restrict__ wl,
        int jbase, int jcount) {
    int li = blockIdx.x * 256 + threadIdx.x;
    if (li >= jcount) return;
    long j = (long)jbase + li;
    const float* W; int K, N, off; int isconv = 0;
    if (j < 98304)                    { W = Wqks; K = 256;  N = 384; off = OFF_QKS; }
    else if ((j -= 98304)  < 196608)  { W = Wos;  K = 768;  N = 256; off = OFF_WOS; }
    else if ((j -= 196608) < 65536)   { W = Wffs; K = 256;  N = 256; off = OFF_FFS; }
    else if ((j -= 65536)  < 131072)  { W = Wqkt; K = 256;  N = 512; off = OFF_QKT; }
    else if ((j -= 131072) < 262144)  { W = Wot;  K = 1024; N = 256; off = OFF_WOT; }
    else if ((j -= 262144) < 65536)   { W = Wfft; K = 256;  N = 256; off = OFF_FFT; }
    else if ((j -= 65536)  < 458752)  { W = Wcnv; K = 1792; N = 256; off = OFF_CNV; isconv = 1; }
    else return;
    float v = W[j];
    __half h = __float2half(v);
    size_t dst;
    if (isconv) {
        int o = (int)(j / 1792), r = (int)(j % 1792);
        int ii = r / 7, kw = r % 7;
        dst = (size_t)off + (size_t)o * 1792 + kw * 256 + ii;
    } else {
        int k = (int)(j / N), n = (int)(j % N);
        dst = (size_t)off + (size_t)n * K + k;
    }
    wh[dst] = h;
    wl[dst] = __float2half(v - __half2float(h));
}

// ------ deint_s: smem-staged, coalesced writes. block per (n,u,t-half) ------
#define DS_SMEM (6 * 2049 * 4)
__global__ __launch_bounds__(256) void deint_s2(const float* __restrict__ qk,
                                                float* __restrict__ qT,
                                                float* __restrict__ kT) {
    extern __shared__ float sms[];
    int b = blockIdx.x;
    int th = b & 1;
    int u = (b >> 1) % VV;
    int n = b / (VV * 2);
    int t0 = th << 5;
    const float* src = qk + ((size_t)(n * VV + u) * TT + t0) * 384;
    for (int i = threadIdx.x; i < 32 * 384; i += 256) {
        int tt = i / 384, col = i % 384;
        int ci = col / 6, r = col % 6;
        sms[r * 2049 + tt * 64 + ci] = src[i];
    }
    __syncthreads();
#pragma unroll
    for (int p = 0; p < 6; p++) {
        int s = (p < 3) ? p : p - 3;
        float* dst = ((p < 3) ? qT : kT) +
                     (((size_t)(n * 3 + s) * VV + u) << 12) + (size_t)t0 * 64;
        for (int i = threadIdx.x; i < 2048; i += 256)
            dst[i] = sms[p * 2049 + i];
    }
}

// ------ deint_t: smem-staged, coalesced writes. block per (n,t) --------------
#define DT_SMEM (8 * 1665 * 4)
__global__ __launch_bounds__(256) void deint_t2(const float* __restrict__ qkt,
                                                float* __restrict__ qd,
                                                float* __restrict__ kd) {
    extern __shared__ float smt[];
    int b = blockIdx.x;
    int t = b % TT, n = b / TT;
    const float* src = qkt + ((size_t)(n * TT + t) * VV) * 512;
    for (int i = threadIdx.x; i < 25 * 512; i += 256) {
        int v = i >> 9, col = i & 511;
        int ci = col >> 3, j = col & 7;
        smt[j * 1665 + v * 64 + ci] = src[i];
    }
    __syncthreads();
#pragma unroll
    for (int p = 0; p < 8; p++) {
        int m = p & 3;
        float* dst = ((p < 4) ? qd : kd) + ((size_t)(n * 4 + m) * TT + t) * 1600;
        for (int i = threadIdx.x; i < 1600; i += 256)
            dst[i] = smt[p * 1665 + i];
    }
}

// spatial attention split-K partials
__global__ __launch_bounds__(128) void att_s_part(
        const float* __restrict__ qT, const float* __restrict__ kT,
        float* __restrict__ ps) {
    int ns = blockIdx.x;
    int kc0 = blockIdx.y << 9;
    __shared__ float qs[25][132], ks[25][132];
    const float* qb = qT + ((size_t)ns * VV << 12);
    const float* kb = kT + ((size_t)ns * VV << 12);
    int t = threadIdx.x;
    int u0 = (t / 25) * 5, v = t % 25;
    float acc[5] = {0.f, 0.f, 0.f, 0.f, 0.f};
    for (int kc = kc0; kc < kc0 + 512; kc += 128) {
        for (int i = t; i < 25 * 128; i += 128) {
            int uu = i >> 7, e = i & 127;
            qs[uu][e] = qb[((size_t)uu << 12) + kc + e];
            ks[uu][e] = kb[((size_t)uu << 12) + kc + e];
        }
        __syncthreads();
        if (t < 125) {
#pragma unroll 4
            for (int e = 0; e < 128; e++) {
                float kv = ks[v][e];
                acc[0] = fmaf(qs[u0 + 0][e], kv, acc[0]);
                acc[1] = fmaf(qs[u0 + 1][e], kv, acc[1]);
                acc[2] = fmaf(qs[u0 + 2][e], kv, acc[2]);
                acc[3] = fmaf(qs[u0 + 3][e], kv, acc[3]);
                acc[4] = fmaf(qs[u0 + 4][e], kv, acc[4]);
            }
        }
        __syncthreads();
    }
    if (t < 125) {
#pragma unroll
        for (int i = 0; i < 5; i++)
            atomicAdd(&ps[(size_t)ns * 625 + (u0 + i) * 25 + v], acc[i]);
    }
}

__global__ void att_s_fin(const float* __restrict__ ps, const float* __restrict__ alphas,
                          const float* __restrict__ att0, float* __restrict__ att) {
    int idx = blockIdx.x * 256 + threadIdx.x;
    if (idx >= 96 * 625) return;
    int ns = idx / 625, r = idx % 625;
    int n = ns / 3, s = ns % 3, u = r / 25, v = r % 25;
    att[((size_t)(n * VV + u) * VV + v) * 3 + s] =
        tanhf(ps[idx] * (1.f / 4096.f)) * alphas[s] + att0[((size_t)u * VV + v) * 3 + s];
}

// y_s: block per (n,t); fp16 output
__global__ __launch_bounds__(256) void ys2(const float* __restrict__ x,
                                           const float* __restrict__ att,
                                           __half* __restrict__ yh) {
    __shared__ float xs[25][256];
    __shared__ float as_[25 * 25 * 3];
    int b = blockIdx.x;
    int n = b >> 6, t = b & 63;
    int tid = threadIdx.x;
    for (int i = tid; i < 25 * 256; i += 256) {
        int u = i >> 8, c = i & 255;
        xs[u][c] = x[((size_t)(n * VV + u) * TT + t) * 256 + c];
    }
    for (int i = tid; i < 1875; i += 256) as_[i] = att[(size_t)n * 1875 + i];
    __syncthreads();
    int c = tid;
#pragma unroll 1
    for (int v = 0; v < VV; v++) {
        float a0 = 0.f, a1 = 0.f, a2 = 0.f;
#pragma unroll
        for (int u = 0; u < VV; u++) {
            float xv = xs[u][c];
            a0 = fmaf(xv, as_[(u * VV + v) * 3 + 0], a0);
            a1 = fmaf(xv, as_[(u * VV + v) * 3 + 1], a1);
            a2 = fmaf(xv, as_[(u * VV + v) * 3 + 2], a2);
        }
        size_t base = ((size_t)(n * VV + v) * TT + t) * 768 + c * 3;
        yh[base]     = __float2half(a0);
        yh[base + 1] = __float2half(a1);
        yh[base + 2] = __float2half(a2);
    }
}

// LN + residual + gelu; writes fp16 (+ optional fp32)
__global__ void ln2(const float* __restrict__ h, const float* __restrict__ res,
                    const float* __restrict__ g, const float* __restrict__ b,
                    float* __restrict__ outf, __half* __restrict__ oh,
                    int G, int mode, int wf) {
    int grp = blockIdx.x;
    const float* hp = h + (size_t)grp * G;
    const float* rp = res + (size_t)grp * G;
    float s = 0.f, sq = 0.f;
    for (int i = threadIdx.x; i < G; i += blockDim.x) {
        float v = hp[i]; s += v; sq = fmaf(v, v, sq);
    }
    for (int o = 16; o; o >>= 1) {
        s += __shfl_down_sync(0xffffffffu, s, o);
        sq += __shfl_down_sync(0xffffffffu, sq, o);
    }
    __shared__ float ss[8], sqs[8];
    __shared__ float mean_s, inv_s;
    int w = threadIdx.x >> 5;
    if ((threadIdx.x & 31) == 0) { ss[w] = s; sqs[w] = sq; }
    __syncthreads();
    if (threadIdx.x == 0) {
        float S = 0.f, Q = 0.f;
        for (int i = 0; i < 8; i++) { S += ss[i]; Q += sqs[i]; }
        float mean = S / G;
        float var = Q / G - mean * mean;
        mean_s = mean; inv_s = rsqrtf(var + 1e-5f);
    }
    __syncthreads();
    float mean = mean_s, inv = inv_s;
    int n = 0, v = 0;
    if (mode == 1) { n = grp / VV; v = grp % VV; }
    for (int i = threadIdx.x; i < G; i += blockDim.x) {
        float val = gelu_f(rp[i] + fmaf((hp[i] - mean) * inv, g[i], b[i]));
        size_t dst;
        if (mode == 0) dst = (size_t)grp * G + i;
        else {
            int t = i >> 8, c = i & 255;
            dst = ((size_t)(n * TT + t) * VV + v) * 256 + c;
        }
        if (wf) outf[dst] = val;
        oh[dst] = __float2half(val);
    }
}

// temporal attention split-K partials
__global__ __launch_bounds__(256) void att_t_part(
        const float* __restrict__ qd, const float* __restrict__ kd,
        float* __restrict__ pt) {
    int nm = blockIdx.x;
    int kb = blockIdx.y * 320;
    __shared__ float Qs[64][68], Ks[64][68];
    const float* qb = qd + (size_t)nm * TT * 1600;
    const float* kb_ = kd + (size_t)nm * TT * 1600;
    const int tid = threadIdx.x;
    const int tx = tid & 15, ty = tid >> 4;
    const int lr = tid >> 2, lc = (tid & 3) << 4;
    float acc[4][4] = {};
    for (int kc = kb; kc < kb + 320; kc += 64) {
#pragma unroll
        for (int j = 0; j < 4; j++) {
            float4 q4 = *(const float4*)(qb + (size_t)lr * 1600 + kc + lc + j * 4);
            float4 k4 = *(const float4*)(kb_ + (size_t)lr * 1600 + kc + lc + j * 4);
            Qs[lc + j*4 + 0][lr] = q4.x; Qs[lc + j*4 + 1][lr] = q4.y;
            Qs[lc + j*4 + 2][lr] = q4.z; Qs[lc + j*4 + 3][lr] = q4.w;
            Ks[lc + j*4 + 0][lr] = k4.x; Ks[lc + j*4 + 1][lr] = k4.y;
            Ks[lc + j*4 + 2][lr] = k4.z; Ks[lc + j*4 + 3][lr] = k4.w;
        }
        __syncthreads();
#pragma unroll 8
        for (int kk = 0; kk < 64; kk++) {
            float4 aq = *(const float4*)(&Qs[kk][ty << 2]);
            float4 bk = *(const float4*)(&Ks[kk][tx << 2]);
            float a[4] = {aq.x, aq.y, aq.z, aq.w};
            float b[4] = {bk.x, bk.y, bk.z, bk.w};
#pragma unroll
            for (int i = 0; i < 4; i++)
#pragma unroll
                for (int j = 0; j < 4; j++) acc[i][j] = fmaf(a[i], b[j], acc[i][j]);
        }
        __syncthreads();
    }
#pragma unroll
    for (int i = 0; i < 4; i++)
#pragma unroll
        for (int j = 0; j < 4; j++) {
            int t_ = (ty << 2) + i, q_ = (tx << 2) + j;
            atomicAdd(&pt[(size_t)nm * 4096 + t_ * 64 + q_], acc[i][j]);
        }
}

__global__ void att_t_fin(const float* __restrict__ pt, const float* __restrict__ alf,
                          const float* __restrict__ alb, float* __restrict__ attf,
                          float* __restrict__ attb) {
    int idx = blockIdx.x * 256 + threadIdx.x;
    if (idx >= 128 * 4096) return;
    int nm = idx >> 12, r = idx & 4095;
    int t = r >> 6, q = r & 63;
    int n = nm >> 2, m = nm & 3, s = m & 1, dir = m >> 1;
    float val = tanhf(pt[idx] * (1.f / 1600.f)) * (dir ? alb[s] : alf[s]);
    size_t o = ((size_t)(n * TT + q) * TT + t) * 2 + s;
    if (dir == 0) attf[o] = (q <= t) ? val : 0.f;
    else          attb[o] = (q >= t) ? val : 0.f;
}

// z apply: fp16 output
__global__ __launch_bounds__(256) void z2k(const float* __restrict__ y2t,
                                           const float* __restrict__ attf,
                                           const float* __restrict__ attb,
                                           __half* __restrict__ zh) {
    extern __shared__ float zs[];
    float* ys = zs;
    float* as_ = zs + 64 * 256;
    int b = blockIdx.x;
    int n = b / VV, v = b % VV;
    int tid = threadIdx.x;
    for (int i = tid; i < 64 * 256; i += 256) {
        int t = i >> 8, c = i & 255;
        ys[t * 256 + c] = y2t[((size_t)(n * TT + t) * VV + v) * 256 + c];
    }
    __syncthreads();
    int c = tid;
    for (int q = 0; q < TT; q++) {
        if (tid < 128) as_[tid] = attf[(size_t)n * 8192 + q * 128 + tid];
        else           as_[tid] = attb[(size_t)n * 8192 + q * 128 + (tid - 128)];
        __syncthreads();
        float f0 = 0.f, f1 = 0.f, b0 = 0.f, b1 = 0.f;
#pragma unroll 8
        for (int t = 0; t < TT; t++) {
            float yv = ys[t * 256 + c];
            f0 = fmaf(yv, as_[t * 2], f0);       f1 = fmaf(yv, as_[t * 2 + 1], f1);
            b0 = fmaf(yv, as_[128 + t * 2], b0); b1 = fmaf(yv, as_[128 + t * 2 + 1], b1);
        }
        size_t base = ((size_t)(n * TT + q) * VV + v) * 1024;
        *(uint32_t*)(zh + base + c * 2) = packh2(f0, f1);
        *(uint32_t*)(zh + base + 512 + c * 2) = packh2(b0, b1);
        __syncthreads();
    }
}

__global__ void final_kernel(const float* __restrict__ z2, const float* __restrict__ cv,
                             const float* __restrict__ bn_g, const float* __restrict__ bn_b,
                             const float* __restrict__ bn_m, const float* __restrict__ bn_v,
                             float* __restrict__ out) {
    size_t i = (size_t)blockIdx.x * 256 + threadIdx.x;
    int o = (int)(i & 255);
    size_t r = i >> 8;
    int v = (int)(r % VV);
    size_t r2 = r / VV;
    int t = (int)(r2 % TT);
    int n = (int)(r2 / TT);
    float c1 = fmaf((cv[i] - bn_m[o]) * rsqrtf(bn_v[o] + 1e-5f), bn_g[o], bn_b[o]);
    out[((size_t)(n * VV + v) * TT + t) * 256 + o] = gelu_f(z2[i] + c1);
}

// ------------------------------- launcher -----------------------------------
extern "C" void kernel_launch(void* const* d_in, const int* in_sizes, int n_in,
                              void* d_out, int out_size) {
    const float* x       = (const float*)d_in[0];
    const float* Wqk_s   = (const float*)d_in[1];
    const float* bqk_s   = (const float*)d_in[2];
    const float* alphas  = (const float*)d_in[3];
    const float* att0s   = (const float*)d_in[4];
    const float* Wo_s    = (const float*)d_in[5];
    const float* bo_s    = (const float*)d_in[6];
    const float* g_os    = (const float*)d_in[7];
    const float* b_os    = (const float*)d_in[8];
    const float* Wff_s   = (const float*)d_in[9];
    const float* bff_s   = (const float*)d_in[10];
    const float* g_ffs   = (const float*)d_in[11];
    const float* b_ffs   = (const float*)d_in[12];
    const float* Wqk_t   = (const float*)d_in[13];
    const float* bqk_t   = (const float*)d_in[14];
    const float* alphat_f= (const float*)d_in[15];
    const float* alphat_b= (const float*)d_in[16];
    const float* Wo_t    = (const float*)d_in[17];
    const float* bo_t    = (const float*)d_in[18];
    const float* g_ot    = (const float*)d_in[19];
    const float* b_ot    = (const float*)d_in[20];
    const float* Wff_t   = (const float*)d_in[21];
    const float* bff_t   = (const float*)d_in[22];
    const float* g_fft   = (const float*)d_in[23];
    const float* b_fft   = (const float*)d_in[24];
    const float* conv_w  = (const float*)d_in[25];
    const float* conv_b  = (const float*)d_in[26];
    const float* bn_g    = (const float*)d_in[27];
    const float* bn_b    = (const float*)d_in[28];
    const float* bn_m    = (const float*)d_in[29];
    const float* bn_v    = (const float*)d_in[30];
    float* out = (float*)d_out;

    void *pB, *pH, *pY1, *pY2, *pZ2, *pAS, *pAF, *pAB, *pWH, *pWL, *pPS, *pPT;
    void *pAH, *pXH, *pY1H, *pY2H, *pZ2H;
    cudaGetSymbolAddress(&pB,  g_bufB);
    cudaGetSymbolAddress(&pH,  g_h);
    cudaGetSymbolAddress(&pY1, g_y1);
    cudaGetSymbolAddress(&pY2, g_y2);
    cudaGetSymbolAddress(&pZ2, g_z2);
    cudaGetSymbolAddress(&pAS, g_atts);
    cudaGetSymbolAddress(&pAF, g_attf);
    cudaGetSymbolAddress(&pAB, g_attb);
    cudaGetSymbolAddress(&pPS, g_ps);
    cudaGetSymbolAddress(&pPT, g_pt);
    cudaGetSymbolAddress(&pWH, g_wh);
    cudaGetSymbolAddress(&pWL, g_wl);
    cudaGetSymbolAddress(&pAH, g_ah);
    cudaGetSymbolAddress(&pXH, g_xh);
    cudaGetSymbolAddress(&pY1H, g_y1h);
    cudaGetSymbolAddress(&pY2H, g_y2h);
    cudaGetSymbolAddress(&pZ2H, g_z2h);
    float* bufB = (float*)pB;
    float* h    = (float*)pH;  float* y1   = (float*)pY1;
    float* y2   = (float*)pY2; float* z2b  = (float*)pZ2;
    float* atts = (float*)pAS; float* attf = (float*)pAF;
    float* attb = (float*)pAB;
    float* ps   = (float*)pPS; float* pt   = (float*)pPT;
    __half* wh  = (__half*)pWH;
    __half* wl  = (__half*)pWL;
    __half* ah  = (__half*)pAH;
    __half* xh  = (__half*)pXH;
    __half* y1h = (__half*)pY1H;
    __half* y2h = (__half*)pY2H;
    __half* z2h = (__half*)pZ2H;

    cudaFuncSetAttribute(gemm_h, cudaFuncAttributeMaxDynamicSharedMemorySize, GSM);
    cudaFuncSetAttribute(conv_h, cudaFuncAttributeMaxDynamicSharedMemorySize, GSM);
    cudaFuncSetAttribute(z2k, cudaFuncAttributeMaxDynamicSharedMemorySize, (64*256 + 256) * 4);
    cudaFuncSetAttribute(deint_s2, cudaFuncAttributeMaxDynamicSharedMemorySize, DS_SMEM);
    cudaFuncSetAttribute(deint_t2, cudaFuncAttributeMaxDynamicSharedMemorySize, DT_SMEM);

    dim3 blk(256);
    const int MB = RTOT / 128;   // 400
    const int WHALF = WTOT / 2;

    prep_x<<<(XITEMS + 255) / 256, blk>>>(x, xh);
    prep_w<<<(WHALF + 255) / 256, blk>>>(Wqk_s, Wo_s, Wff_s, Wqk_t, Wo_t, Wff_t,
                                         conv_w, wh, wl, 0, WHALF);
    prep_w<<<(WHALF + 255) / 256, blk>>>(Wqk_s, Wo_s, Wff_s, Wqk_t, Wo_t, Wff_t,
                                         conv_w, wh, wl, WHALF, WTOT - WHALF);
    cudaMemsetAsync(ps, 0, 96 * 625 * sizeof(float));
    cudaMemsetAsync(pt, 0, 128 * 4096 * sizeof(float));

    // Stage 1: spatial
    gemm_h<<<dim3(3, MB), blk, GSM>>>(xh, wh + OFF_QKS, wl + OFF_QKS, bqk_s, bufB, RTOT, 384, 256);
    deint_s2<<<NN * VV * 2, blk, DS_SMEM>>>(bufB, h, y1);
    att_s_part<<<dim3(96, 8), 128>>>(h, y1, ps);
    att_s_fin<<<(96 * 625 + 255) / 256, blk>>>(ps, alphas, att0s, atts);
    ys2<<<NN * TT, blk>>>(x, atts, ah);
    gemm_h<<<dim3(2, MB), blk, GSM>>>(ah, wh + OFF_WOS, wl + OFF_WOS, bo_s, h, RTOT, 256, 768);
    ln2<<<NN*VV, blk>>>(h, x, g_os, b_os, y1, y1h, TT*256, 0, 0);
    gemm_h<<<dim3(2, MB), blk, GSM>>>(y1h, wh + OFF_FFS, wl + OFF_FFS, bff_s, h, RTOT, 256, 256);
    ln2<<<NN*VV, blk>>>(h, x, g_ffs, b_ffs, y2, y2h, TT*256, 1, 1);

    // Stage 2: temporal
    gemm_h<<<dim3(4, MB), blk, GSM>>>(y2h, wh + OFF_QKT, wl + OFF_QKT, bqk_t, bufB, RTOT, 512, 256);
    deint_t2<<<NN * TT, blk, DT_SMEM>>>(bufB, h, y1);
    att_t_part<<<dim3(128, 5), blk>>>(h, y1, pt);
    att_t_fin<<<(128 * 4096 + 255) / 256, blk>>>(pt, alphat_f, alphat_b, attf, attb);
    z2k<<<NN * VV, blk, (64*256 + 256) * 4>>>(y2, attf, attb, ah);
    gemm_h<<<dim3(2, MB), blk, GSM>>>(ah, wh + OFF_WOT, wl + OFF_WOT, bo_t, h, RTOT, 256, 1024);
    ln2<<<NN*TT, blk>>>(h, y2, g_ot, b_ot, y1, y1h, VV*256, 0, 0);
    gemm_h<<<dim3(2, MB), blk, GSM>>>(y1h, wh + OFF_FFT, wl + OFF_FFT, bff_t, h, RTOT, 256, 256);
    ln2<<<NN*TT, blk>>>(h, y2, g_fft, b_fft, z2b, z2h, VV*256, 0, 1);

    // Stage 3: conv + BN + gelu + transpose
    conv_h<<<dim3(2, MB), blk, GSM>>>(z2h, wh + OFF_CNV, wl + OFF_CNV, conv_b, h);
    final_kernel<<<RTOT, blk>>>(z2b, h, bn_g, bn_b, bn_m, bn_v, out);
}